// round 5
// baseline (speedup 1.0000x reference)
#include <cuda_runtime.h>
#include <cuda_bf16.h>
#include <math.h>

#define NMAX 100000
#define EMAX 800000
#define ETMAX (NMAX + EMAX)
#define GMAX 128

// ---------------- device scratch ----------------
__device__ float g_H[NMAX * 256];
__device__ float g_OUT[NMAX * 256];
__device__ float g_H1[NMAX * 64];
__device__ float g_H2[NMAX * 64];
__device__ float g_AS[NMAX * 4];
__device__ float g_AD[NMAX * 4];
__device__ int   g_deg[NMAX];
__device__ int   g_rowptr[NMAX + 1];
__device__ int   g_cur[NMAX];
__device__ int   g_adj[ETMAX];
__device__ int   g_bsum[256];
__device__ float g_SUMP[GMAX * 64];
__device__ int   g_MAXP[GMAX * 64];
__device__ int   g_CNT[GMAX];
__device__ float g_X1[GMAX * 128];
__device__ float g_X2[GMAX * 128];

// ---------------- helpers ----------------
__device__ __forceinline__ int fmap(float f) {
    int i = __float_as_int(f);
    return i >= 0 ? i : (i ^ 0x7FFFFFFF);
}
__device__ __forceinline__ float funmap(int i) {
    return __int_as_float(i >= 0 ? i : (i ^ 0x7FFFFFFF));
}
__device__ __forceinline__ float selu_f(float x) {
    const float a = 1.6732632423543772f, s = 1.0507009873554805f;
    return x > 0.f ? s * x : s * a * (expf(x) - 1.f);
}
__device__ __forceinline__ float to_tf32(float x) {
    unsigned u;
    asm("cvt.rna.tf32.f32 %0, %1;" : "=r"(u) : "f"(x));
    return __uint_as_float(u);
}
__device__ __forceinline__ void mma_tf32(float& c0, float& c1, float& c2, float& c3,
                                         unsigned a0, unsigned a1, unsigned a2, unsigned a3,
                                         unsigned b0, unsigned b1) {
    asm volatile(
        "mma.sync.aligned.m16n8k8.row.col.f32.tf32.tf32.f32 "
        "{%0,%1,%2,%3}, {%4,%5,%6,%7}, {%8,%9}, {%0,%1,%2,%3};"
        : "+f"(c0), "+f"(c1), "+f"(c2), "+f"(c3)
        : "r"(a0), "r"(a1), "r"(a2), "r"(a3), "r"(b0), "r"(b1));
}
__device__ __forceinline__ void cp_async16(void* smem_dst, const void* gsrc, int src_bytes) {
    unsigned s = (unsigned)__cvta_generic_to_shared(smem_dst);
    asm volatile("cp.async.cg.shared.global [%0], [%1], 16, %2;"
                 :: "r"(s), "l"(gsrc), "r"(src_bytes));
}

// =================== CSR build ===================
__global__ void deg_init_kernel(int* __restrict__ deg, int* __restrict__ cur, int N) {
    int i = blockIdx.x * blockDim.x + threadIdx.x;
    if (i < N) { deg[i] = 1; cur[i] = 0; }
}
__global__ void zero_att_kernel(float* __restrict__ AS, float* __restrict__ AD, int N4) {
    int i = blockIdx.x * blockDim.x + threadIdx.x;
    if (i < N4) { AS[i] = 0.f; AD[i] = 0.f; }
}
__global__ void deg_count_kernel(const int* __restrict__ ei, int* __restrict__ deg, int E) {
    int e = blockIdx.x * blockDim.x + threadIdx.x;
    if (e < E) atomicAdd(&deg[ei[E + e]], 1);
}
__global__ void scan1_kernel(const int* __restrict__ deg, int* __restrict__ rowptr,
                             int* __restrict__ bsum, int N) {
    __shared__ int sh[256];
    int tid = threadIdx.x;
    int base = blockIdx.x * 2048 + tid * 8;
    int v[8], pre[8];
    int sum = 0;
    #pragma unroll
    for (int j = 0; j < 8; j++) {
        v[j] = (base + j < N) ? deg[base + j] : 0;
        pre[j] = sum;
        sum += v[j];
    }
    sh[tid] = sum;
    __syncthreads();
    for (int off = 1; off < 256; off <<= 1) {
        int t = (tid >= off) ? sh[tid - off] : 0;
        __syncthreads();
        sh[tid] += t;
        __syncthreads();
    }
    int texcl = sh[tid] - sum;
    #pragma unroll
    for (int j = 0; j < 8; j++)
        if (base + j < N) rowptr[base + j] = texcl + pre[j];
    if (tid == 255) bsum[blockIdx.x] = sh[255];
}
__global__ void scan23_kernel(int* __restrict__ rowptr, const int* __restrict__ bsum,
                              int N, int ET) {
    __shared__ int s_add;
    int tid = threadIdx.x;
    if (tid < 32) {
        int s = 0;
        for (int j = tid; j < blockIdx.x; j += 32) s += bsum[j];
        #pragma unroll
        for (int off = 16; off; off >>= 1) s += __shfl_down_sync(0xFFFFFFFFu, s, off);
        if (tid == 0) s_add = s;
    }
    __syncthreads();
    int add = s_add;
    int base = blockIdx.x * 2048 + tid * 8;
    #pragma unroll
    for (int j = 0; j < 8; j++)
        if (base + j < N) rowptr[base + j] += add;
    if (blockIdx.x == 0 && tid == 0) rowptr[N] = ET;
}
__global__ void fill_kernel(const int* __restrict__ ei, const int* __restrict__ rowptr,
                            int* __restrict__ cur, int* __restrict__ adj, int E, int ET) {
    int idx = blockIdx.x * blockDim.x + threadIdx.x;
    if (idx >= ET) return;
    int src, dst;
    if (idx < E) { src = ei[idx]; dst = ei[E + idx]; }
    else         { src = dst = idx - E; }
    adj[rowptr[dst] + atomicAdd(&cur[dst], 1)] = src;
}

// =================== pipelined tf32 GEMM (permuted-K A layout) ===================
// C[MxN] = A[MxK] @ B[KxN].  BM=128, BK=16, 256 threads, double-buffered.
// A smem layout: Asm[m][k'] with k' = (k%4)*4 + k/4 -> per-thread frag = float4.
// EPI: 0 = plain, 1 = bias+selu, 2 = plain store + fused attention dots into AS/AD
template <int BN, int WARPS_M, int WARPS_N, int EPI>
__global__ void __launch_bounds__(256)
tf32_gemm_kernel(const float* __restrict__ A, const float* __restrict__ B,
                 const float* __restrict__ bias, float* __restrict__ C,
                 const float* __restrict__ a_src, const float* __restrict__ a_dst,
                 float* __restrict__ AS, float* __restrict__ AD,
                 int M, int N, int K) {
    const int WM = 128 / WARPS_M, WN = BN / WARPS_N;
    const int MT = WM / 16, NT = WN / 8;
    const int ASTR = 20;                    // 16 + 4 pad floats (80B rows, 16B-aligned)
    __shared__ float Asm[2][128][ASTR];     // [buf][m][k'] tf32-rounded
    __shared__ float Bs[2][16][BN + 8];     // [buf][k][n] raw fp32 (RZ-truncated by MMA)

    int tid = threadIdx.x;
    int warp = tid >> 5, lane = tid & 31;
    int lr = lane >> 2, lc = lane & 3;
    int warp_m = warp / WARPS_N, warp_n = warp % WARPS_N;
    int wm0 = warp_m * WM, wn0 = warp_n * WN;
    int m0 = blockIdx.y * 128, n0 = blockIdx.x * BN;

    float c[MT][NT][4];
    #pragma unroll
    for (int i = 0; i < MT; i++)
        #pragma unroll
        for (int j = 0; j < NT; j++)
            #pragma unroll
            for (int q = 0; q < 4; q++) c[i][j][q] = 0.f;

    float4 areg[2];

    auto ldA = [&](int k0) {
        #pragma unroll
        for (int q = 0; q < 2; q++) {
            int f = tid + q * 256;
            int r = f >> 2, cc = (f & 3) * 4;
            int gm = m0 + r, gk = k0 + cc;
            float4 v = {0.f, 0.f, 0.f, 0.f};
            if (gm < M && gk < K) v = *(const float4*)&A[(size_t)gm * K + gk];  // K%4==0
            areg[q] = v;
        }
    };
    auto stA = [&](int buf) {
        #pragma unroll
        for (int q = 0; q < 2; q++) {
            int f = tid + q * 256;
            int r = f >> 2, kb = f & 3;     // kb = (k/4) within tile
            Asm[buf][r][kb + 0]  = to_tf32(areg[q].x);   // k%4=0 -> k'=kb
            Asm[buf][r][kb + 4]  = to_tf32(areg[q].y);   // k%4=1 -> k'=4+kb
            Asm[buf][r][kb + 8]  = to_tf32(areg[q].z);
            Asm[buf][r][kb + 12] = to_tf32(areg[q].w);
        }
    };
    auto cpB = [&](int k0, int buf) {
        const int NV4 = BN / 4;
        #pragma unroll
        for (int f = tid; f < 16 * NV4; f += 256) {
            int r = f / NV4, cc = (f % NV4) * 4;
            int gk = k0 + r;
            int bytes = (gk < K) ? 16 : 0;
            int gkc = (gk < K) ? gk : (K - 1);
            cp_async16(&Bs[buf][r][cc], &B[(size_t)gkc * N + n0 + cc], bytes);
        }
        asm volatile("cp.async.commit_group;");
    };

    int nk = (K + 15) / 16;
    ldA(0);
    cpB(0, 0);
    for (int t = 0; t < nk; t++) {
        int buf = t & 1;
        stA(buf);
        asm volatile("cp.async.wait_group 0;");
        __syncthreads();
        if (t + 1 < nk) { ldA((t + 1) * 16); cpB((t + 1) * 16, buf ^ 1); }

        // A fragments for the whole 16-K tile: 2 x LDS.128 per mt
        float4 fa[MT], fb[MT];
        #pragma unroll
        for (int mt = 0; mt < MT; mt++) {
            const float* pm = &Asm[buf][wm0 + mt * 16 + lr][4 * lc];
            fa[mt] = *(const float4*)pm;             // k = lc, 4+lc, 8+lc, 12+lc
            fb[mt] = *(const float4*)(pm + 8 * ASTR);
        }
        // kk = 0: B rows lc, lc+4
        {
            unsigned bf[NT][2];
            #pragma unroll
            for (int nt = 0; nt < NT; nt++) {
                int n = wn0 + nt * 8 + lr;
                bf[nt][0] = __float_as_uint(Bs[buf][lc][n]);
                bf[nt][1] = __float_as_uint(Bs[buf][lc + 4][n]);
            }
            #pragma unroll
            for (int mt = 0; mt < MT; mt++)
                #pragma unroll
                for (int nt = 0; nt < NT; nt++)
                    mma_tf32(c[mt][nt][0], c[mt][nt][1], c[mt][nt][2], c[mt][nt][3],
                             __float_as_uint(fa[mt].x), __float_as_uint(fb[mt].x),
                             __float_as_uint(fa[mt].y), __float_as_uint(fb[mt].y),
                             bf[nt][0], bf[nt][1]);
        }
        // kk = 8: B rows lc+8, lc+12
        {
            unsigned bf[NT][2];
            #pragma unroll
            for (int nt = 0; nt < NT; nt++) {
                int n = wn0 + nt * 8 + lr;
                bf[nt][0] = __float_as_uint(Bs[buf][lc + 8][n]);
                bf[nt][1] = __float_as_uint(Bs[buf][lc + 12][n]);
            }
            #pragma unroll
            for (int mt = 0; mt < MT; mt++)
                #pragma unroll
                for (int nt = 0; nt < NT; nt++)
                    mma_tf32(c[mt][nt][0], c[mt][nt][1], c[mt][nt][2], c[mt][nt][3],
                             __float_as_uint(fa[mt].z), __float_as_uint(fb[mt].z),
                             __float_as_uint(fa[mt].w), __float_as_uint(fb[mt].w),
                             bf[nt][0], bf[nt][1]);
        }
        __syncthreads();
    }

    // ---- epilogue ----
    float asv[NT][2], adv[NT][2];
    if (EPI == 2) {
        #pragma unroll
        for (int nt = 0; nt < NT; nt++) {
            int gc = n0 + wn0 + nt * 8 + lc * 2;
            asv[nt][0] = a_src[gc]; asv[nt][1] = a_src[gc + 1];
            adv[nt][0] = a_dst[gc]; adv[nt][1] = a_dst[gc + 1];
        }
    }
    #pragma unroll
    for (int mt = 0; mt < MT; mt++) {
        int r0 = m0 + wm0 + mt * 16 + lr;
        int r1 = r0 + 8;
        float s0 = 0.f, s1 = 0.f, d0 = 0.f, d1 = 0.f;
        #pragma unroll
        for (int nt = 0; nt < NT; nt++) {
            int gc = n0 + wn0 + nt * 8 + lc * 2;
            float v0 = c[mt][nt][0], v1 = c[mt][nt][1];
            float v2 = c[mt][nt][2], v3 = c[mt][nt][3];
            if (EPI == 1) {
                float b0 = bias[gc], b1 = bias[gc + 1];
                v0 = selu_f(v0 + b0); v1 = selu_f(v1 + b1);
                v2 = selu_f(v2 + b0); v3 = selu_f(v3 + b1);
            }
            if (EPI == 2) {
                s0 += v0 * asv[nt][0] + v1 * asv[nt][1];
                s1 += v2 * asv[nt][0] + v3 * asv[nt][1];
                d0 += v0 * adv[nt][0] + v1 * adv[nt][1];
                d1 += v2 * adv[nt][0] + v3 * adv[nt][1];
            }
            if (r0 < M) *(float2*)&C[(size_t)r0 * N + gc] = make_float2(v0, v1);
            if (r1 < M) *(float2*)&C[(size_t)r1 * N + gc] = make_float2(v2, v3);
        }
        if (EPI == 2) {
            s0 += __shfl_xor_sync(0xFFFFFFFFu, s0, 1);
            s0 += __shfl_xor_sync(0xFFFFFFFFu, s0, 2);
            s1 += __shfl_xor_sync(0xFFFFFFFFu, s1, 1);
            s1 += __shfl_xor_sync(0xFFFFFFFFu, s1, 2);
            d0 += __shfl_xor_sync(0xFFFFFFFFu, d0, 1);
            d0 += __shfl_xor_sync(0xFFFFFFFFu, d0, 2);
            d1 += __shfl_xor_sync(0xFFFFFFFFu, d1, 1);
            d1 += __shfl_xor_sync(0xFFFFFFFFu, d1, 2);
            if (lc == 0) {
                int h = (n0 + wn0) >> 6;   // WN=32 tile lies within one 64-col head
                if (r0 < M) { atomicAdd(&AS[r0 * 4 + h], s0); atomicAdd(&AD[r0 * 4 + h], d0); }
                if (r1 < M) { atomicAdd(&AS[r1 * 4 + h], s1); atomicAdd(&AD[r1 * 4 + h], d1); }
            }
        }
    }
}

// =================== GAT gather: warp per dst, online softmax, prefetched ===================
__global__ void gat_gather_kernel(const int* __restrict__ rowptr, const int* __restrict__ adj,
                                  const float* __restrict__ H, const float* __restrict__ AS,
                                  const float* __restrict__ AD, const float* __restrict__ gb,
                                  float* __restrict__ OUT, int N) {
    int gw = (blockIdx.x * blockDim.x + threadIdx.x) >> 5;
    int lane = threadIdx.x & 31;
    if (gw >= N) return;
    int dst = gw;
    int h = lane >> 3;
    float adh = AD[dst * 4 + h];
    int beg = rowptr[dst], end = rowptr[dst + 1];
    float acc[8] = {};
    float m = -INFINITY, s = 0.f;
    int src = adj[beg];
    for (int i = beg; i < end; i++) {
        int nsrc = (i + 1 < end) ? adj[i + 1] : 0;      // prefetch next index
        float e = AS[src * 4 + h] + adh;
        const float4* hp = (const float4*)(H + (size_t)src * 256) + lane * 2;
        float4 va = hp[0], vb = hp[1];
        e = e > 0.f ? e : 0.2f * e;
        if (e <= m) {
            float w = expf(e - m);
            s += w;
            acc[0] += w * va.x; acc[1] += w * va.y;
            acc[2] += w * va.z; acc[3] += w * va.w;
            acc[4] += w * vb.x; acc[5] += w * vb.y;
            acc[6] += w * vb.z; acc[7] += w * vb.w;
        } else {
            float sc = expf(m - e);   // first iter: exp(-inf)=0
            s = s * sc + 1.f;
            acc[0] = acc[0] * sc + va.x; acc[1] = acc[1] * sc + va.y;
            acc[2] = acc[2] * sc + va.z; acc[3] = acc[3] * sc + va.w;
            acc[4] = acc[4] * sc + vb.x; acc[5] = acc[5] * sc + vb.y;
            acc[6] = acc[6] * sc + vb.z; acc[7] = acc[7] * sc + vb.w;
            m = e;
        }
        src = nsrc;
    }
    float inv = 1.f / (s + 1e-16f);
    float* o = OUT + (size_t)dst * 256 + lane * 8;
    const float* gbp = gb + lane * 8;
    float4 r0 = {acc[0] * inv + gbp[0], acc[1] * inv + gbp[1],
                 acc[2] * inv + gbp[2], acc[3] * inv + gbp[3]};
    float4 r1 = {acc[4] * inv + gbp[4], acc[5] * inv + gbp[5],
                 acc[6] * inv + gbp[6], acc[7] * inv + gbp[7]};
    *(float4*)(o + 0) = r0;
    *(float4*)(o + 4) = r1;
}

// =================== pooling ===================
__global__ void pool_zero_kernel(float* __restrict__ SUMP, int* __restrict__ MAXP,
                                 int* __restrict__ CNT) {
    int i = blockIdx.x * blockDim.x + threadIdx.x;
    if (i < GMAX * 64) { SUMP[i] = 0.f; MAXP[i] = fmap(-INFINITY); }
    if (i < GMAX) CNT[i] = 0;
}
__global__ void pool_acc_kernel(const float* __restrict__ Hx, const int* __restrict__ batch,
                                float* __restrict__ SUMP, int* __restrict__ MAXP,
                                int* __restrict__ CNT, int N) {
    int c = threadIdx.x & 63;
    int rsub = threadIdx.x >> 6;
    int r = blockIdx.x * 128 + rsub;
    int rend = blockIdx.x * 128 + 128;
    if (rend > N) rend = N;
    float sum = 0.f, mx = -INFINITY;
    int cnt = 0, curg = -1;
    for (; r < rend; r += 4) {
        int g = batch[r];
        float v = Hx[(size_t)r * 64 + c];
        if (g != curg) {
            if (curg >= 0) {
                atomicAdd(&SUMP[curg * 64 + c], sum);
                atomicMax(&MAXP[curg * 64 + c], fmap(mx));
                if (c == 0) atomicAdd(&CNT[curg], cnt);
            }
            curg = g; sum = 0.f; mx = -INFINITY; cnt = 0;
        }
        sum += v;
        mx = fmaxf(mx, v);
        cnt++;
    }
    if (curg >= 0) {
        atomicAdd(&SUMP[curg * 64 + c], sum);
        atomicMax(&MAXP[curg * 64 + c], fmap(mx));
        if (c == 0) atomicAdd(&CNT[curg], cnt);
    }
}
__global__ void pool_fin_kernel(const float* __restrict__ SUMP, const int* __restrict__ MAXP,
                                const int* __restrict__ CNT, float* __restrict__ X) {
    int i = blockIdx.x * blockDim.x + threadIdx.x;
    if (i >= GMAX * 64) return;
    int g = i >> 6, c = i & 63;
    float cnt = (float)CNT[g];
    if (cnt < 1.f) cnt = 1.f;
    X[g * 128 + c] = SUMP[i] / cnt;
    X[g * 128 + 64 + c] = funmap(MAXP[i]);
}

// =================== final MLP head ===================
__global__ void mlp_kernel(const float* __restrict__ X1, const float* __restrict__ X2,
                           const float* __restrict__ sum_w, const float* __restrict__ sum_b,
                           const float* __restrict__ sh1_w, const float* __restrict__ sh1_b,
                           const float* __restrict__ sh2_w, const float* __restrict__ sh2_b,
                           const float* __restrict__ sh3_w, const float* __restrict__ sh3_b,
                           const float* __restrict__ reg_w, const float* __restrict__ reg_b,
                           float* __restrict__ out) {
    __shared__ float zin[256], z1[128], z2[64], z3[64];
    int g = blockIdx.x, t = threadIdx.x;
    zin[t] = X1[g * 128 + t];
    zin[128 + t] = X2[g * 128 + t];
    __syncthreads();
    {
        float acc = sum_b[t];
        for (int k = 0; k < 256; k++) acc += zin[k] * sum_w[k * 128 + t];
        z1[t] = acc;
    }
    __syncthreads();
    if (t < 64) {
        float acc = sh1_b[t];
        for (int k = 0; k < 128; k++) acc += z1[k] * sh1_w[k * 64 + t];
        z2[t] = selu_f(acc);
    }
    __syncthreads();
    if (t < 64) {
        float acc = sh2_b[t];
        for (int k = 0; k < 64; k++) acc += z2[k] * sh2_w[k * 64 + t];
        z3[t] = selu_f(acc);
    }
    __syncthreads();
    if (t < 64) {
        float acc = sh3_b[t];
        for (int k = 0; k < 64; k++) acc += z3[k] * sh3_w[k * 64 + t];
        z2[t] = selu_f(acc);
    }
    __syncthreads();
    if (t < 32) {
        float acc = reg_b[t];
        for (int k = 0; k < 64; k++) acc += z2[k] * reg_w[k * 32 + t];
        out[g * 32 + t] = acc;
    }
}

// =================== host orchestration ===================
static void run_pool(const float* Hx, const int* batch, int N,
                     float* SUMP, int* MAXP, int* CNT, float* X) {
    pool_zero_kernel<<<(GMAX * 64 + 255) / 256, 256>>>(SUMP, MAXP, CNT);
    pool_acc_kernel<<<(N + 127) / 128, 256>>>(Hx, batch, SUMP, MAXP, CNT, N);
    pool_fin_kernel<<<(GMAX * 64 + 255) / 256, 256>>>(SUMP, MAXP, CNT, X);
}

extern "C" void kernel_launch(void* const* d_in, const int* in_sizes, int n_in,
                              void* d_out, int out_size) {
    const float* x       = (const float*)d_in[0];
    const int*   ei      = (const int*)d_in[1];
    const int*   batch   = (const int*)d_in[2];
    const float* gat1_w  = (const float*)d_in[3];
    const float* gat1_as = (const float*)d_in[4];
    const float* gat1_ad = (const float*)d_in[5];
    const float* gat1_b  = (const float*)d_in[6];
    const float* lin1_w  = (const float*)d_in[7];
    const float* lin1_b  = (const float*)d_in[8];
    const float* gat2_w  = (const float*)d_in[9];
    const float* gat2_as = (const float*)d_in[10];
    const float* gat2_ad = (const float*)d_in[11];
    const float* gat2_b  = (const float*)d_in[12];
    const float* lin2_w  = (const float*)d_in[13];
    const float* lin2_b  = (const float*)d_in[14];
    const float* sum_w   = (const float*)d_in[15];
    const float* sum_b   = (const float*)d_in[16];
    const float* sh1_w   = (const float*)d_in[17];
    const float* sh1_b   = (const float*)d_in[18];
    const float* sh2_w   = (const float*)d_in[19];
    const float* sh2_b   = (const float*)d_in[20];
    const float* sh3_w   = (const float*)d_in[21];
    const float* sh3_b   = (const float*)d_in[22];
    const float* reg_w   = (const float*)d_in[23];
    const float* reg_b   = (const float*)d_in[24];

    int N  = in_sizes[2];
    int E  = in_sizes[1] / 2;
    int K1 = in_sizes[0] / N;
    int ET = E + N;

    float *H, *OUT, *H1, *H2, *AS, *AD, *SUMP, *X1, *X2;
    int *deg, *rowptr, *cur, *adj, *bsum, *MAXP, *CNT;
    cudaGetSymbolAddress((void**)&H, g_H);
    cudaGetSymbolAddress((void**)&OUT, g_OUT);
    cudaGetSymbolAddress((void**)&H1, g_H1);
    cudaGetSymbolAddress((void**)&H2, g_H2);
    cudaGetSymbolAddress((void**)&AS, g_AS);
    cudaGetSymbolAddress((void**)&AD, g_AD);
    cudaGetSymbolAddress((void**)&deg, g_deg);
    cudaGetSymbolAddress((void**)&rowptr, g_rowptr);
    cudaGetSymbolAddress((void**)&cur, g_cur);
    cudaGetSymbolAddress((void**)&adj, g_adj);
    cudaGetSymbolAddress((void**)&bsum, g_bsum);
    cudaGetSymbolAddress((void**)&SUMP, g_SUMP);
    cudaGetSymbolAddress((void**)&MAXP, g_MAXP);
    cudaGetSymbolAddress((void**)&CNT, g_CNT);
    cudaGetSymbolAddress((void**)&X1, g_X1);
    cudaGetSymbolAddress((void**)&X2, g_X2);

    int nScanBlocks = (N + 2047) / 2048;
    dim3 gH(2, (N + 127) / 128);    // H GEMMs (N=256)
    dim3 gL(1, (N + 127) / 128);    // lin GEMMs (N=64)

    // launches 0..2 (indep prep); launch 3 = GEMM1 (ncu profiles 0-idx 3)
    deg_init_kernel<<<(N + 255) / 256, 256>>>(deg, cur, N);
    zero_att_kernel<<<(N * 4 + 255) / 256, 256>>>(AS, AD, N * 4);
    deg_count_kernel<<<(E + 255) / 256, 256>>>(ei, deg, E);

    // ---- GEMM1 + fused attention dots ----
    tf32_gemm_kernel<128, 2, 4, 2><<<gH, 256>>>(x, gat1_w, nullptr, H,
                                                gat1_as, gat1_ad, AS, AD, N, 256, K1);

    // rest of CSR build
    scan1_kernel<<<nScanBlocks, 256>>>(deg, rowptr, bsum, N);
    scan23_kernel<<<nScanBlocks, 256>>>(rowptr, bsum, N, ET);
    fill_kernel<<<(ET + 255) / 256, 256>>>(ei, rowptr, cur, adj, E, ET);

    // ---- Layer 1 aggregate + lin1 ----
    gat_gather_kernel<<<(N * 32 + 255) / 256, 256>>>(rowptr, adj, H, AS, AD, gat1_b, OUT, N);
    tf32_gemm_kernel<64, 4, 2, 1><<<gL, 256>>>(OUT, lin1_w, lin1_b, H1,
                                               nullptr, nullptr, nullptr, nullptr, N, 64, 256);
    run_pool(H1, batch, N, SUMP, MAXP, CNT, X1);

    // ---- Layer 2 ----
    zero_att_kernel<<<(N * 4 + 255) / 256, 256>>>(AS, AD, N * 4);
    tf32_gemm_kernel<128, 2, 4, 2><<<gH, 256>>>(H1, gat2_w, nullptr, H,
                                                gat2_as, gat2_ad, AS, AD, N, 256, 64);
    gat_gather_kernel<<<(N * 32 + 255) / 256, 256>>>(rowptr, adj, H, AS, AD, gat2_b, OUT, N);
    tf32_gemm_kernel<64, 4, 2, 1><<<gL, 256>>>(OUT, lin2_w, lin2_b, H2,
                                               nullptr, nullptr, nullptr, nullptr, N, 64, 256);
    run_pool(H2, batch, N, SUMP, MAXP, CNT, X2);

    // ---- Head MLP ----
    mlp_kernel<<<GMAX, 128>>>(X1, X2, sum_w, sum_b, sh1_w, sh1_b, sh2_w, sh2_b,
                              sh3_w, sh3_b, reg_w, reg_b, (float*)d_out);
}

// round 6
// speedup vs baseline: 1.0287x; 1.0287x over previous
#include <cuda_runtime.h>
#include <cuda_bf16.h>
#include <math.h>

#define NMAX 100000
#define EMAX 800000
#define ETMAX (NMAX + EMAX)
#define GMAX 128

// ---------------- device scratch ----------------
__device__ float g_H[NMAX * 256];
__device__ float g_OUT[NMAX * 256];
__device__ float g_H1[NMAX * 64];
__device__ float g_H2[NMAX * 64];
__device__ float g_AS[NMAX * 4];
__device__ float g_AD[NMAX * 4];
__device__ float g_AS2[NMAX * 4];
__device__ float g_AD2[NMAX * 4];
__device__ int   g_deg[NMAX];
__device__ int   g_rowptr[NMAX + 1];
__device__ int   g_cur[NMAX];
__device__ int   g_adj[ETMAX];
__device__ int   g_bsum[256];
__device__ float g_SUMP1[GMAX * 64];
__device__ int   g_MAXP1[GMAX * 64];
__device__ int   g_CNT1[GMAX];
__device__ float g_SUMP2[GMAX * 64];
__device__ int   g_MAXP2[GMAX * 64];
__device__ int   g_CNT2[GMAX];
__device__ float g_X1[GMAX * 128];
__device__ float g_X2[GMAX * 128];

// ---------------- helpers ----------------
__device__ __forceinline__ int fmap(float f) {
    int i = __float_as_int(f);
    return i >= 0 ? i : (i ^ 0x7FFFFFFF);
}
__device__ __forceinline__ float funmap(int i) {
    return __int_as_float(i >= 0 ? i : (i ^ 0x7FFFFFFF));
}
__device__ __forceinline__ float selu_f(float x) {
    const float a = 1.6732632423543772f, s = 1.0507009873554805f;
    return x > 0.f ? s * x : s * a * (expf(x) - 1.f);
}
__device__ __forceinline__ float to_tf32(float x) {
    unsigned u;
    asm("cvt.rna.tf32.f32 %0, %1;" : "=r"(u) : "f"(x));
    return __uint_as_float(u);
}
__device__ __forceinline__ unsigned to_tf32u(float x) {
    unsigned u;
    asm("cvt.rna.tf32.f32 %0, %1;" : "=r"(u) : "f"(x));
    return u;
}
__device__ __forceinline__ void mma_tf32(float& c0, float& c1, float& c2, float& c3,
                                         unsigned a0, unsigned a1, unsigned a2, unsigned a3,
                                         unsigned b0, unsigned b1) {
    asm volatile(
        "mma.sync.aligned.m16n8k8.row.col.f32.tf32.tf32.f32 "
        "{%0,%1,%2,%3}, {%4,%5,%6,%7}, {%8,%9}, {%0,%1,%2,%3};"
        : "+f"(c0), "+f"(c1), "+f"(c2), "+f"(c3)
        : "r"(a0), "r"(a1), "r"(a2), "r"(a3), "r"(b0), "r"(b1));
}
__device__ __forceinline__ void cp_async16(void* smem_dst, const void* gsrc, int src_bytes) {
    unsigned s = (unsigned)__cvta_generic_to_shared(smem_dst);
    asm volatile("cp.async.cg.shared.global [%0], [%1], 16, %2;"
                 :: "r"(s), "l"(gsrc), "r"(src_bytes));
}

// =================== one-shot init: deg/cur, att bufs, pool bufs ===================
__global__ void init_all_kernel(int* __restrict__ deg, int* __restrict__ cur,
                                float* __restrict__ AS, float* __restrict__ AD,
                                float* __restrict__ AS2, float* __restrict__ AD2,
                                float* __restrict__ SUMP1, int* __restrict__ MAXP1,
                                int* __restrict__ CNT1,
                                float* __restrict__ SUMP2, int* __restrict__ MAXP2,
                                int* __restrict__ CNT2, int N) {
    int i = blockIdx.x * blockDim.x + threadIdx.x;
    if (i < N) { deg[i] = 1; cur[i] = 0; }
    if (i < N * 4) { AS[i] = 0.f; AD[i] = 0.f; AS2[i] = 0.f; AD2[i] = 0.f; }
    if (i < GMAX * 64) {
        SUMP1[i] = 0.f; MAXP1[i] = fmap(-INFINITY);
        SUMP2[i] = 0.f; MAXP2[i] = fmap(-INFINITY);
    }
    if (i < GMAX) { CNT1[i] = 0; CNT2[i] = 0; }
}

// =================== CSR scan/fill ===================
__global__ void scan1_kernel(const int* __restrict__ deg, int* __restrict__ rowptr,
                             int* __restrict__ bsum, int N) {
    __shared__ int sh[256];
    int tid = threadIdx.x;
    int base = blockIdx.x * 2048 + tid * 8;
    int v[8], pre[8];
    int sum = 0;
    #pragma unroll
    for (int j = 0; j < 8; j++) {
        v[j] = (base + j < N) ? deg[base + j] : 0;
        pre[j] = sum;
        sum += v[j];
    }
    sh[tid] = sum;
    __syncthreads();
    for (int off = 1; off < 256; off <<= 1) {
        int t = (tid >= off) ? sh[tid - off] : 0;
        __syncthreads();
        sh[tid] += t;
        __syncthreads();
    }
    int texcl = sh[tid] - sum;
    #pragma unroll
    for (int j = 0; j < 8; j++)
        if (base + j < N) rowptr[base + j] = texcl + pre[j];
    if (tid == 255) bsum[blockIdx.x] = sh[255];
}
__global__ void scan23_kernel(int* __restrict__ rowptr, const int* __restrict__ bsum,
                              int N, int ET) {
    __shared__ int s_add;
    int tid = threadIdx.x;
    if (tid < 32) {
        int s = 0;
        for (int j = tid; j < blockIdx.x; j += 32) s += bsum[j];
        #pragma unroll
        for (int off = 16; off; off >>= 1) s += __shfl_down_sync(0xFFFFFFFFu, s, off);
        if (tid == 0) s_add = s;
    }
    __syncthreads();
    int add = s_add;
    int base = blockIdx.x * 2048 + tid * 8;
    #pragma unroll
    for (int j = 0; j < 8; j++)
        if (base + j < N) rowptr[base + j] += add;
    if (blockIdx.x == 0 && tid == 0) rowptr[N] = ET;
}
__global__ void fill_kernel(const int* __restrict__ ei, const int* __restrict__ rowptr,
                            int* __restrict__ cur, int* __restrict__ adj, int E, int ET) {
    int idx = blockIdx.x * blockDim.x + threadIdx.x;
    if (idx >= ET) return;
    int src, dst;
    if (idx < E) { src = ei[idx]; dst = ei[E + idx]; }
    else         { src = dst = idx - E; }
    adj[rowptr[dst] + atomicAdd(&cur[dst], 1)] = src;
}

// =================== pipelined tf32 GEMM (R4-proven core) + fused side work ===================
// C[MxN] = A[MxK] @ B[KxN].  BM=128, BK=16, 256 threads, double-buffered.
// EPI: 0 = plain, 1 = bias+selu, 2 = plain store + fused attention dots into AS/AD
// SIDE: 0 = none; 1 = blocks with blockIdx.x==gridDim.x-1 do deg_count over edges;
//       2 = those blocks do pool_acc (segmented sum/max over sorted batch).
template <int BN, int WARPS_M, int WARPS_N, int EPI, int SIDE>
__global__ void __launch_bounds__(256)
tf32_gemm_kernel(const float* __restrict__ A, const float* __restrict__ B,
                 const float* __restrict__ bias, float* __restrict__ C,
                 const float* __restrict__ a_src, const float* __restrict__ a_dst,
                 float* __restrict__ AS, float* __restrict__ AD,
                 const void* sp0, const void* sp1, void* sp2, void* sp3, void* sp4,
                 int M, int N, int K, int sE) {
    if (SIDE != 0 && blockIdx.x == gridDim.x - 1) {
        if (SIDE == 1) {
            // deg_count: count in-degrees over a chunk of edges
            const int* ei = (const int*)sp0;
            int* deg = (int*)sp2;
            int NY = gridDim.y;
            int chunk = (sE + NY - 1) / NY;
            int e0 = blockIdx.y * chunk;
            int e1 = e0 + chunk;
            if (e1 > sE) e1 = sE;
            for (int e = e0 + threadIdx.x; e < e1; e += 256)
                atomicAdd(&deg[ei[sE + e]], 1);
        } else {
            // pool_acc: run-based segmented mean/max accumulation
            const float* Hx = (const float*)sp0;
            const int* batch = (const int*)sp1;
            float* SUMP = (float*)sp2;
            int* MAXP = (int*)sp3;
            int* CNT = (int*)sp4;
            int c = threadIdx.x & 63;
            int r = blockIdx.y * 128 + (threadIdx.x >> 6);
            int rend = blockIdx.y * 128 + 128;
            if (rend > M) rend = M;
            float sum = 0.f, mx = -INFINITY;
            int cnt = 0, curg = -1;
            for (; r < rend; r += 4) {
                int g = batch[r];
                float v = Hx[(size_t)r * 64 + c];
                if (g != curg) {
                    if (curg >= 0) {
                        atomicAdd(&SUMP[curg * 64 + c], sum);
                        atomicMax(&MAXP[curg * 64 + c], fmap(mx));
                        if (c == 0) atomicAdd(&CNT[curg], cnt);
                    }
                    curg = g; sum = 0.f; mx = -INFINITY; cnt = 0;
                }
                sum += v;
                mx = fmaxf(mx, v);
                cnt++;
            }
            if (curg >= 0) {
                atomicAdd(&SUMP[curg * 64 + c], sum);
                atomicMax(&MAXP[curg * 64 + c], fmap(mx));
                if (c == 0) atomicAdd(&CNT[curg], cnt);
            }
        }
        return;
    }

    const int WM = 128 / WARPS_M, WN = BN / WARPS_N;
    const int MT = WM / 16, NT = WN / 8;
    __shared__ float As[2][16][136];       // [buf][k][m] tf32-rounded
    __shared__ float Bs[2][16][BN + 8];    // [buf][k][n] raw fp32, cvt at frag load

    int tid = threadIdx.x;
    int warp = tid >> 5, lane = tid & 31;
    int lr = lane >> 2, lc = lane & 3;
    int warp_m = warp / WARPS_N, warp_n = warp % WARPS_N;
    int wm0 = warp_m * WM, wn0 = warp_n * WN;
    int m0 = blockIdx.y * 128, n0 = blockIdx.x * BN;

    float c[MT][NT][4];
    #pragma unroll
    for (int i = 0; i < MT; i++)
        #pragma unroll
        for (int j = 0; j < NT; j++)
            #pragma unroll
            for (int q = 0; q < 4; q++) c[i][j][q] = 0.f;

    float4 areg[2];

    auto ldA = [&](int k0) {
        #pragma unroll
        for (int q = 0; q < 2; q++) {
            int f = tid + q * 256;
            int r = f >> 2, cc = (f & 3) * 4;
            int gm = m0 + r, gk = k0 + cc;
            float4 v = {0.f, 0.f, 0.f, 0.f};
            if (gm < M && gk < K) v = *(const float4*)&A[(size_t)gm * K + gk];  // K%4==0
            areg[q] = v;
        }
    };
    auto stA = [&](int buf) {
        #pragma unroll
        for (int q = 0; q < 2; q++) {
            int f = tid + q * 256;
            int r = f >> 2, cc = (f & 3) * 4;
            As[buf][cc + 0][r] = to_tf32(areg[q].x);
            As[buf][cc + 1][r] = to_tf32(areg[q].y);
            As[buf][cc + 2][r] = to_tf32(areg[q].z);
            As[buf][cc + 3][r] = to_tf32(areg[q].w);
        }
    };
    auto cpB = [&](int k0, int buf) {
        const int NV4 = BN / 4;
        #pragma unroll
        for (int f = tid; f < 16 * NV4; f += 256) {
            int r = f / NV4, cc = (f % NV4) * 4;
            int gk = k0 + r;
            int bytes = (gk < K) ? 16 : 0;
            int gkc = (gk < K) ? gk : (K - 1);
            cp_async16(&Bs[buf][r][cc], &B[(size_t)gkc * N + n0 + cc], bytes);
        }
        asm volatile("cp.async.commit_group;");
    };

    int nk = (K + 15) / 16;
    ldA(0);
    cpB(0, 0);
    for (int t = 0; t < nk; t++) {
        int buf = t & 1;
        stA(buf);
        asm volatile("cp.async.wait_group 0;");
        __syncthreads();
        if (t + 1 < nk) { ldA((t + 1) * 16); cpB((t + 1) * 16, buf ^ 1); }
        #pragma unroll
        for (int kk = 0; kk < 16; kk += 8) {
            unsigned af[MT][4];
            #pragma unroll
            for (int mt = 0; mt < MT; mt++) {
                int m = wm0 + mt * 16 + lr;
                af[mt][0] = __float_as_uint(As[buf][kk + lc][m]);
                af[mt][1] = __float_as_uint(As[buf][kk + lc][m + 8]);
                af[mt][2] = __float_as_uint(As[buf][kk + lc + 4][m]);
                af[mt][3] = __float_as_uint(As[buf][kk + lc + 4][m + 8]);
            }
            unsigned bf[NT][2];
            #pragma unroll
            for (int nt = 0; nt < NT; nt++) {
                int n = wn0 + nt * 8 + lr;
                bf[nt][0] = to_tf32u(Bs[buf][kk + lc][n]);
                bf[nt][1] = to_tf32u(Bs[buf][kk + lc + 4][n]);
            }
            #pragma unroll
            for (int mt = 0; mt < MT; mt++)
                #pragma unroll
                for (int nt = 0; nt < NT; nt++)
                    mma_tf32(c[mt][nt][0], c[mt][nt][1], c[mt][nt][2], c[mt][nt][3],
                             af[mt][0], af[mt][1], af[mt][2], af[mt][3],
                             bf[nt][0], bf[nt][1]);
        }
        __syncthreads();
    }

    // ---- epilogue ----
    float asv[NT][2], adv[NT][2];
    if (EPI == 2) {
        #pragma unroll
        for (int nt = 0; nt < NT; nt++) {
            int gc = n0 + wn0 + nt * 8 + lc * 2;
            asv[nt][0] = a_src[gc]; asv[nt][1] = a_src[gc + 1];
            adv[nt][0] = a_dst[gc]; adv[nt][1] = a_dst[gc + 1];
        }
    }
    #pragma unroll
    for (int mt = 0; mt < MT; mt++) {
        int r0 = m0 + wm0 + mt * 16 + lr;
        int r1 = r0 + 8;
        float s0 = 0.f, s1 = 0.f, d0 = 0.f, d1 = 0.f;
        #pragma unroll
        for (int nt = 0; nt < NT; nt++) {
            int gc = n0 + wn0 + nt * 8 + lc * 2;
            float v0 = c[mt][nt][0], v1 = c[mt][nt][1];
            float v2 = c[mt][nt][2], v3 = c[mt][nt][3];
            if (EPI == 1) {
                float b0 = bias[gc], b1 = bias[gc + 1];
                v0 = selu_f(v0 + b0); v1 = selu_f(v1 + b1);
                v2 = selu_f(v2 + b0); v3 = selu_f(v3 + b1);
            }
            if (EPI == 2) {
                s0 += v0 * asv[nt][0] + v1 * asv[nt][1];
                s1 += v2 * asv[nt][0] + v3 * asv[nt][1];
                d0 += v0 * adv[nt][0] + v1 * adv[nt][1];
                d1 += v2 * adv[nt][0] + v3 * adv[nt][1];
            }
            if (r0 < M) *(float2*)&C[(size_t)r0 * N + gc] = make_float2(v0, v1);
            if (r1 < M) *(float2*)&C[(size_t)r1 * N + gc] = make_float2(v2, v3);
        }
        if (EPI == 2) {
            s0 += __shfl_xor_sync(0xFFFFFFFFu, s0, 1);
            s0 += __shfl_xor_sync(0xFFFFFFFFu, s0, 2);
            s1 += __shfl_xor_sync(0xFFFFFFFFu, s1, 1);
            s1 += __shfl_xor_sync(0xFFFFFFFFu, s1, 2);
            d0 += __shfl_xor_sync(0xFFFFFFFFu, d0, 1);
            d0 += __shfl_xor_sync(0xFFFFFFFFu, d0, 2);
            d1 += __shfl_xor_sync(0xFFFFFFFFu, d1, 1);
            d1 += __shfl_xor_sync(0xFFFFFFFFu, d1, 2);
            if (lc == 0) {
                int h = (n0 + wn0) >> 6;   // WN=32 tile lies within one 64-col head
                if (r0 < M) { atomicAdd(&AS[r0 * 4 + h], s0); atomicAdd(&AD[r0 * 4 + h], d0); }
                if (r1 < M) { atomicAdd(&AS[r1 * 4 + h], s1); atomicAdd(&AD[r1 * 4 + h], d1); }
            }
        }
    }
}

// =================== GAT gather: warp per dst, online softmax, 2-edge unroll ===================
__device__ __forceinline__ void ons_update(float e, float4 va, float4 vb,
                                           float& m, float& s, float* acc) {
    if (e <= m) {
        float w = expf(e - m);
        s += w;
        acc[0] += w * va.x; acc[1] += w * va.y;
        acc[2] += w * va.z; acc[3] += w * va.w;
        acc[4] += w * vb.x; acc[5] += w * vb.y;
        acc[6] += w * vb.z; acc[7] += w * vb.w;
    } else {
        float sc = expf(m - e);   // first iter: exp(-inf)=0
        s = s * sc + 1.f;
        acc[0] = acc[0] * sc + va.x; acc[1] = acc[1] * sc + va.y;
        acc[2] = acc[2] * sc + va.z; acc[3] = acc[3] * sc + va.w;
        acc[4] = acc[4] * sc + vb.x; acc[5] = acc[5] * sc + vb.y;
        acc[6] = acc[6] * sc + vb.z; acc[7] = acc[7] * sc + vb.w;
        m = e;
    }
}

__global__ void gat_gather_kernel(const int* __restrict__ rowptr, const int* __restrict__ adj,
                                  const float* __restrict__ H, const float* __restrict__ AS,
                                  const float* __restrict__ AD, const float* __restrict__ gb,
                                  float* __restrict__ OUT, int N) {
    int gw = (blockIdx.x * blockDim.x + threadIdx.x) >> 5;
    int lane = threadIdx.x & 31;
    if (gw >= N) return;
    int dst = gw;
    int h = lane >> 3;
    float adh = AD[dst * 4 + h];
    int beg = rowptr[dst], end = rowptr[dst + 1];
    float acc[8] = {};
    float m = -INFINITY, s = 0.f;
    int i = beg;
    for (; i + 2 <= end; i += 2) {
        int s0 = adj[i], s1 = adj[i + 1];
        float e0 = AS[s0 * 4 + h] + adh;
        float e1 = AS[s1 * 4 + h] + adh;
        const float4* hp0 = (const float4*)(H + (size_t)s0 * 256) + lane * 2;
        const float4* hp1 = (const float4*)(H + (size_t)s1 * 256) + lane * 2;
        float4 va0 = hp0[0], vb0 = hp0[1];
        float4 va1 = hp1[0], vb1 = hp1[1];
        e0 = e0 > 0.f ? e0 : 0.2f * e0;
        e1 = e1 > 0.f ? e1 : 0.2f * e1;
        ons_update(e0, va0, vb0, m, s, acc);
        ons_update(e1, va1, vb1, m, s, acc);
    }
    if (i < end) {
        int s0 = adj[i];
        float e0 = AS[s0 * 4 + h] + adh;
        const float4* hp0 = (const float4*)(H + (size_t)s0 * 256) + lane * 2;
        float4 va0 = hp0[0], vb0 = hp0[1];
        e0 = e0 > 0.f ? e0 : 0.2f * e0;
        ons_update(e0, va0, vb0, m, s, acc);
    }
    float inv = 1.f / (s + 1e-16f);
    float* o = OUT + (size_t)dst * 256 + lane * 8;
    const float* gbp = gb + lane * 8;
    float4 r0 = {acc[0] * inv + gbp[0], acc[1] * inv + gbp[1],
                 acc[2] * inv + gbp[2], acc[3] * inv + gbp[3]};
    float4 r1 = {acc[4] * inv + gbp[4], acc[5] * inv + gbp[5],
                 acc[6] * inv + gbp[6], acc[7] * inv + gbp[7]};
    *(float4*)(o + 0) = r0;
    *(float4*)(o + 4) = r1;
}

// =================== standalone pool pieces ===================
__global__ void pool_acc_kernel(const float* __restrict__ Hx, const int* __restrict__ batch,
                                float* __restrict__ SUMP, int* __restrict__ MAXP,
                                int* __restrict__ CNT, int N) {
    int c = threadIdx.x & 63;
    int r = blockIdx.x * 128 + (threadIdx.x >> 6);
    int rend = blockIdx.x * 128 + 128;
    if (rend > N) rend = N;
    float sum = 0.f, mx = -INFINITY;
    int cnt = 0, curg = -1;
    for (; r < rend; r += 4) {
        int g = batch[r];
        float v = Hx[(size_t)r * 64 + c];
        if (g != curg) {
            if (curg >= 0) {
                atomicAdd(&SUMP[curg * 64 + c], sum);
                atomicMax(&MAXP[curg * 64 + c], fmap(mx));
                if (c == 0) atomicAdd(&CNT[curg], cnt);
            }
            curg = g; sum = 0.f; mx = -INFINITY; cnt = 0;
        }
        sum += v;
        mx = fmaxf(mx, v);
        cnt++;
    }
    if (curg >= 0) {
        atomicAdd(&SUMP[curg * 64 + c], sum);
        atomicMax(&MAXP[curg * 64 + c], fmap(mx));
        if (c == 0) atomicAdd(&CNT[curg], cnt);
    }
}
__global__ void pool_fin_kernel(const float* __restrict__ SUMP, const int* __restrict__ MAXP,
                                const int* __restrict__ CNT, float* __restrict__ X) {
    int i = blockIdx.x * blockDim.x + threadIdx.x;
    if (i >= GMAX * 64) return;
    int g = i >> 6, c = i & 63;
    float cnt = (float)CNT[g];
    if (cnt < 1.f) cnt = 1.f;
    X[g * 128 + c] = SUMP[i] / cnt;
    X[g * 128 + 64 + c] = funmap(MAXP[i]);
}

// =================== final MLP head ===================
__global__ void mlp_kernel(const float* __restrict__ X1, const float* __restrict__ X2,
                           const float* __restrict__ sum_w, const float* __restrict__ sum_b,
                           const float* __restrict__ sh1_w, const float* __restrict__ sh1_b,
                           const float* __restrict__ sh2_w, const float* __restrict__ sh2_b,
                           const float* __restrict__ sh3_w, const float* __restrict__ sh3_b,
                           const float* __restrict__ reg_w, const float* __restrict__ reg_b,
                           float* __restrict__ out) {
    __shared__ float zin[256], z1[128], z2[64], z3[64];
    int g = blockIdx.x, t = threadIdx.x;
    zin[t] = X1[g * 128 + t];
    zin[128 + t] = X2[g * 128 + t];
    __syncthreads();
    {
        float acc = sum_b[t];
        for (int k = 0; k < 256; k++) acc += zin[k] * sum_w[k * 128 + t];
        z1[t] = acc;
    }
    __syncthreads();
    if (t < 64) {
        float acc = sh1_b[t];
        for (int k = 0; k < 128; k++) acc += z1[k] * sh1_w[k * 64 + t];
        z2[t] = selu_f(acc);
    }
    __syncthreads();
    if (t < 64) {
        float acc = sh2_b[t];
        for (int k = 0; k < 64; k++) acc += z2[k] * sh2_w[k * 64 + t];
        z3[t] = selu_f(acc);
    }
    __syncthreads();
    if (t < 64) {
        float acc = sh3_b[t];
        for (int k = 0; k < 64; k++) acc += z3[k] * sh3_w[k * 64 + t];
        z2[t] = selu_f(acc);
    }
    __syncthreads();
    if (t < 32) {
        float acc = reg_b[t];
        for (int k = 0; k < 64; k++) acc += z2[k] * reg_w[k * 32 + t];
        out[g * 32 + t] = acc;
    }
}

// =================== host orchestration ===================
extern "C" void kernel_launch(void* const* d_in, const int* in_sizes, int n_in,
                              void* d_out, int out_size) {
    const float* x       = (const float*)d_in[0];
    const int*   ei      = (const int*)d_in[1];
    const int*   batch   = (const int*)d_in[2];
    const float* gat1_w  = (const float*)d_in[3];
    const float* gat1_as = (const float*)d_in[4];
    const float* gat1_ad = (const float*)d_in[5];
    const float* gat1_b  = (const float*)d_in[6];
    const float* lin1_w  = (const float*)d_in[7];
    const float* lin1_b  = (const float*)d_in[8];
    const float* gat2_w  = (const float*)d_in[9];
    const float* gat2_as = (const float*)d_in[10];
    const float* gat2_ad = (const float*)d_in[11];
    const float* gat2_b  = (const float*)d_in[12];
    const float* lin2_w  = (const float*)d_in[13];
    const float* lin2_b  = (const float*)d_in[14];
    const float* sum_w   = (const float*)d_in[15];
    const float* sum_b   = (const float*)d_in[16];
    const float* sh1_w   = (const float*)d_in[17];
    const float* sh1_b   = (const float*)d_in[18];
    const float* sh2_w   = (const float*)d_in[19];
    const float* sh2_b   = (const float*)d_in[20];
    const float* sh3_w   = (const float*)d_in[21];
    const float* sh3_b   = (const float*)d_in[22];
    const float* reg_w   = (const float*)d_in[23];
    const float* reg_b   = (const float*)d_in[24];

    int N  = in_sizes[2];
    int E  = in_sizes[1] / 2;
    int K1 = in_sizes[0] / N;
    int ET = E + N;

    float *H, *OUT, *H1, *H2, *AS, *AD, *AS2, *AD2, *SUMP1, *SUMP2, *X1, *X2;
    int *deg, *rowptr, *cur, *adj, *bsum, *MAXP1, *CNT1, *MAXP2, *CNT2;
    cudaGetSymbolAddress((void**)&H, g_H);
    cudaGetSymbolAddress((void**)&OUT, g_OUT);
    cudaGetSymbolAddress((void**)&H1, g_H1);
    cudaGetSymbolAddress((void**)&H2, g_H2);
    cudaGetSymbolAddress((void**)&AS, g_AS);
    cudaGetSymbolAddress((void**)&AD, g_AD);
    cudaGetSymbolAddress((void**)&AS2, g_AS2);
    cudaGetSymbolAddress((void**)&AD2, g_AD2);
    cudaGetSymbolAddress((void**)&deg, g_deg);
    cudaGetSymbolAddress((void**)&rowptr, g_rowptr);
    cudaGetSymbolAddress((void**)&cur, g_cur);
    cudaGetSymbolAddress((void**)&adj, g_adj);
    cudaGetSymbolAddress((void**)&bsum, g_bsum);
    cudaGetSymbolAddress((void**)&SUMP1, g_SUMP1);
    cudaGetSymbolAddress((void**)&MAXP1, g_MAXP1);
    cudaGetSymbolAddress((void**)&CNT1, g_CNT1);
    cudaGetSymbolAddress((void**)&SUMP2, g_SUMP2);
    cudaGetSymbolAddress((void**)&MAXP2, g_MAXP2);
    cudaGetSymbolAddress((void**)&CNT2, g_CNT2);
    cudaGetSymbolAddress((void**)&X1, g_X1);
    cudaGetSymbolAddress((void**)&X2, g_X2);

    int nScanBlocks = (N + 2047) / 2048;
    int nyH = (N + 127) / 128;
    dim3 gH1(3, nyH);    // 2 GEMM slices + 1 side slice (deg_count)
    dim3 gH2(3, nyH);    // 2 GEMM slices + 1 side slice (pool_acc layer1)
    dim3 gL(1, nyH);     // lin GEMMs (BN=64)

    // 0: consolidated init
    init_all_kernel<<<(N * 4 + 255) / 256, 256>>>(deg, cur, AS, AD, AS2, AD2,
                                                  SUMP1, MAXP1, CNT1, SUMP2, MAXP2, CNT2, N);

    // 1: GEMM1 (+att dots into AS/AD) with fused deg_count side slice
    tf32_gemm_kernel<128, 2, 4, 2, 1><<<gH1, 256>>>(
        x, gat1_w, nullptr, H, gat1_as, gat1_ad, AS, AD,
        ei, nullptr, deg, nullptr, nullptr, N, 256, K1, E);

    // 2-4: CSR scan + fill
    scan1_kernel<<<nScanBlocks, 256>>>(deg, rowptr, bsum, N);
    scan23_kernel<<<nScanBlocks, 256>>>(rowptr, bsum, N, ET);
    fill_kernel<<<(ET + 255) / 256, 256>>>(ei, rowptr, cur, adj, E, ET);

    // 5: layer-1 aggregate
    gat_gather_kernel<<<(N * 32 + 255) / 256, 256>>>(rowptr, adj, H, AS, AD, gat1_b, OUT, N);
    // 6: lin1 + selu
    tf32_gemm_kernel<64, 4, 2, 1, 0><<<gL, 256>>>(
        OUT, lin1_w, lin1_b, H1, nullptr, nullptr, nullptr, nullptr,
        nullptr, nullptr, nullptr, nullptr, nullptr, N, 64, 256, 0);

    // 7: GEMM2 (+att dots into AS2/AD2) with fused pool_acc(layer1) side slice
    tf32_gemm_kernel<128, 2, 4, 2, 2><<<gH2, 256>>>(
        H1, gat2_w, nullptr, H, gat2_as, gat2_ad, AS2, AD2,
        H1, batch, SUMP1, MAXP1, CNT1, N, 256, 64, 0);
    // 8: finish pool1 -> X1
    pool_fin_kernel<<<(GMAX * 64 + 255) / 256, 256>>>(SUMP1, MAXP1, CNT1, X1);

    // 9: layer-2 aggregate
    gat_gather_kernel<<<(N * 32 + 255) / 256, 256>>>(rowptr, adj, H, AS2, AD2, gat2_b, OUT, N);
    // 10: lin2 + selu
    tf32_gemm_kernel<64, 4, 2, 1, 0><<<gL, 256>>>(
        OUT, lin2_w, lin2_b, H2, nullptr, nullptr, nullptr, nullptr,
        nullptr, nullptr, nullptr, nullptr, nullptr, N, 64, 256, 0);

    // 11-12: pool2 -> X2
    pool_acc_kernel<<<nyH, 256>>>(H2, batch, SUMP2, MAXP2, CNT2, N);
    pool_fin_kernel<<<(GMAX * 64 + 255) / 256, 256>>>(SUMP2, MAXP2, CNT2, X2);

    // 13: head MLP
    mlp_kernel<<<GMAX, 128>>>(X1, X2, sum_w, sum_b, sh1_w, sh1_b, sh2_w, sh2_b,
                              sh3_w, sh3_b, reg_w, reg_b, (float*)d_out);
}

// round 7
// speedup vs baseline: 1.0823x; 1.0520x over previous
#include <cuda_runtime.h>
#include <cuda_fp16.h>
#include <math.h>

#define NMAX 100000
#define EMAX 800000
#define ETMAX (NMAX + EMAX)
#define GMAX 128

// ---------------- device scratch ----------------
__device__ __half g_H[NMAX * 256];     // GAT hidden h, fp16 (read by gather)
__device__ float g_OUT[NMAX * 256];
__device__ float g_H1[NMAX * 64];
__device__ float g_H2[NMAX * 64];
__device__ float g_AS[NMAX * 4];
__device__ float g_AD[NMAX * 4];
__device__ float g_AS2[NMAX * 4];
__device__ float g_AD2[NMAX * 4];
__device__ int   g_deg[NMAX];
__device__ int   g_rowptr[NMAX + 1];
__device__ int   g_cur[NMAX];
__device__ int   g_adj[ETMAX];
__device__ int   g_bsum[256];
__device__ float g_SUMP1[GMAX * 64];
__device__ int   g_MAXP1[GMAX * 64];
__device__ int   g_CNT1[GMAX];
__device__ float g_SUMP2[GMAX * 64];
__device__ int   g_MAXP2[GMAX * 64];
__device__ int   g_CNT2[GMAX];
__device__ float g_X1[GMAX * 128];
__device__ float g_X2[GMAX * 128];

// ---------------- helpers ----------------
__device__ __forceinline__ int fmap(float f) {
    int i = __float_as_int(f);
    return i >= 0 ? i : (i ^ 0x7FFFFFFF);
}
__device__ __forceinline__ float funmap(int i) {
    return __int_as_float(i >= 0 ? i : (i ^ 0x7FFFFFFF));
}
__device__ __forceinline__ float selu_f(float x) {
    const float a = 1.6732632423543772f, s = 1.0507009873554805f;
    return x > 0.f ? s * x : s * a * (expf(x) - 1.f);
}
__device__ __forceinline__ float to_tf32(float x) {
    unsigned u;
    asm("cvt.rna.tf32.f32 %0, %1;" : "=r"(u) : "f"(x));
    return __uint_as_float(u);
}
__device__ __forceinline__ unsigned to_tf32u(float x) {
    unsigned u;
    asm("cvt.rna.tf32.f32 %0, %1;" : "=r"(u) : "f"(x));
    return u;
}
__device__ __forceinline__ void mma_tf32(float& c0, float& c1, float& c2, float& c3,
                                         unsigned a0, unsigned a1, unsigned a2, unsigned a3,
                                         unsigned b0, unsigned b1) {
    asm volatile(
        "mma.sync.aligned.m16n8k8.row.col.f32.tf32.tf32.f32 "
        "{%0,%1,%2,%3}, {%4,%5,%6,%7}, {%8,%9}, {%0,%1,%2,%3};"
        : "+f"(c0), "+f"(c1), "+f"(c2), "+f"(c3)
        : "r"(a0), "r"(a1), "r"(a2), "r"(a3), "r"(b0), "r"(b1));
}
__device__ __forceinline__ void cp_async16(void* smem_dst, const void* gsrc, int src_bytes) {
    unsigned s = (unsigned)__cvta_generic_to_shared(smem_dst);
    asm volatile("cp.async.cg.shared.global [%0], [%1], 16, %2;"
                 :: "r"(s), "l"(gsrc), "r"(src_bytes));
}

// =================== one-shot init ===================
__global__ void init_all_kernel(int* __restrict__ deg, int* __restrict__ cur,
                                float* __restrict__ AS, float* __restrict__ AD,
                                float* __restrict__ AS2, float* __restrict__ AD2,
                                float* __restrict__ SUMP1, int* __restrict__ MAXP1,
                                int* __restrict__ CNT1,
                                float* __restrict__ SUMP2, int* __restrict__ MAXP2,
                                int* __restrict__ CNT2, int N) {
    int i = blockIdx.x * blockDim.x + threadIdx.x;
    if (i < N) { deg[i] = 1; cur[i] = 0; }
    if (i < N * 4) { AS[i] = 0.f; AD[i] = 0.f; AS2[i] = 0.f; AD2[i] = 0.f; }
    if (i < GMAX * 64) {
        SUMP1[i] = 0.f; MAXP1[i] = fmap(-INFINITY);
        SUMP2[i] = 0.f; MAXP2[i] = fmap(-INFINITY);
    }
    if (i < GMAX) { CNT1[i] = 0; CNT2[i] = 0; }
}

// =================== CSR build ===================
__global__ void deg_count_kernel(const int* __restrict__ ei, int* __restrict__ deg, int E) {
    int e = blockIdx.x * blockDim.x + threadIdx.x;
    if (e < E) atomicAdd(&deg[ei[E + e]], 1);
}
__global__ void scan1_kernel(const int* __restrict__ deg, int* __restrict__ rowptr,
                             int* __restrict__ bsum, int N) {
    __shared__ int sh[256];
    int tid = threadIdx.x;
    int base = blockIdx.x * 2048 + tid * 8;
    int v[8], pre[8];
    int sum = 0;
    #pragma unroll
    for (int j = 0; j < 8; j++) {
        v[j] = (base + j < N) ? deg[base + j] : 0;
        pre[j] = sum;
        sum += v[j];
    }
    sh[tid] = sum;
    __syncthreads();
    for (int off = 1; off < 256; off <<= 1) {
        int t = (tid >= off) ? sh[tid - off] : 0;
        __syncthreads();
        sh[tid] += t;
        __syncthreads();
    }
    int texcl = sh[tid] - sum;
    #pragma unroll
    for (int j = 0; j < 8; j++)
        if (base + j < N) rowptr[base + j] = texcl + pre[j];
    if (tid == 255) bsum[blockIdx.x] = sh[255];
}
__global__ void scan23_kernel(int* __restrict__ rowptr, const int* __restrict__ bsum,
                              int N, int ET) {
    __shared__ int s_add;
    int tid = threadIdx.x;
    if (tid < 32) {
        int s = 0;
        for (int j = tid; j < blockIdx.x; j += 32) s += bsum[j];
        #pragma unroll
        for (int off = 16; off; off >>= 1) s += __shfl_down_sync(0xFFFFFFFFu, s, off);
        if (tid == 0) s_add = s;
    }
    __syncthreads();
    int add = s_add;
    int base = blockIdx.x * 2048 + tid * 8;
    #pragma unroll
    for (int j = 0; j < 8; j++)
        if (base + j < N) rowptr[base + j] += add;
    if (blockIdx.x == 0 && tid == 0) rowptr[N] = ET;
}
__global__ void fill_kernel(const int* __restrict__ ei, const int* __restrict__ rowptr,
                            int* __restrict__ cur, int* __restrict__ adj, int E, int ET) {
    int idx = blockIdx.x * blockDim.x + threadIdx.x;
    if (idx >= ET) return;
    int src, dst;
    if (idx < E) { src = ei[idx]; dst = ei[E + idx]; }
    else         { src = dst = idx - E; }
    adj[rowptr[dst] + atomicAdd(&cur[dst], 1)] = src;
}

// =================== pipelined tf32 GEMM (R4-proven core) ===================
// EPI: 0 = plain fp32 store, 1 = bias+selu fp32 store,
//      2 = fp16 store + fused attention dots into AS/AD (fp32-accurate)
// SIDE: 0 = none; 2 = last-grid.x blocks do pool_acc
template <int BN, int WARPS_M, int WARPS_N, int EPI, int SIDE>
__global__ void __launch_bounds__(256)
tf32_gemm_kernel(const float* __restrict__ A, const float* __restrict__ B,
                 const float* __restrict__ bias, void* __restrict__ Cv,
                 const float* __restrict__ a_src, const float* __restrict__ a_dst,
                 float* __restrict__ AS, float* __restrict__ AD,
                 const void* sp0, const void* sp1, void* sp2, void* sp3, void* sp4,
                 int M, int N, int K, int sE) {
    if (SIDE == 2 && blockIdx.x == gridDim.x - 1) {
        // pool_acc: run-based segmented mean/max accumulation
        const float* Hx = (const float*)sp0;
        const int* batch = (const int*)sp1;
        float* SUMP = (float*)sp2;
        int* MAXP = (int*)sp3;
        int* CNT = (int*)sp4;
        int c = threadIdx.x & 63;
        int r = blockIdx.y * 128 + (threadIdx.x >> 6);
        int rend = blockIdx.y * 128 + 128;
        if (rend > M) rend = M;
        float sum = 0.f, mx = -INFINITY;
        int cnt = 0, curg = -1;
        for (; r < rend; r += 4) {
            int g = batch[r];
            float v = Hx[(size_t)r * 64 + c];
            if (g != curg) {
                if (curg >= 0) {
                    atomicAdd(&SUMP[curg * 64 + c], sum);
                    atomicMax(&MAXP[curg * 64 + c], fmap(mx));
                    if (c == 0) atomicAdd(&CNT[curg], cnt);
                }
                curg = g; sum = 0.f; mx = -INFINITY; cnt = 0;
            }
            sum += v;
            mx = fmaxf(mx, v);
            cnt++;
        }
        if (curg >= 0) {
            atomicAdd(&SUMP[curg * 64 + c], sum);
            atomicMax(&MAXP[curg * 64 + c], fmap(mx));
            if (c == 0) atomicAdd(&CNT[curg], cnt);
        }
        return;
    }

    const int WM = 128 / WARPS_M, WN = BN / WARPS_N;
    const int MT = WM / 16, NT = WN / 8;
    __shared__ float As[2][16][136];       // [buf][k][m] tf32-rounded
    __shared__ float Bs[2][16][BN + 8];    // [buf][k][n] raw fp32, cvt at frag load

    int tid = threadIdx.x;
    int warp = tid >> 5, lane = tid & 31;
    int lr = lane >> 2, lc = lane & 3;
    int warp_m = warp / WARPS_N, warp_n = warp % WARPS_N;
    int wm0 = warp_m * WM, wn0 = warp_n * WN;
    int m0 = blockIdx.y * 128, n0 = blockIdx.x * BN;

    float c[MT][NT][4];
    #pragma unroll
    for (int i = 0; i < MT; i++)
        #pragma unroll
        for (int j = 0; j < NT; j++)
            #pragma unroll
            for (int q = 0; q < 4; q++) c[i][j][q] = 0.f;

    float4 areg[2];

    auto ldA = [&](int k0) {
        #pragma unroll
        for (int q = 0; q < 2; q++) {
            int f = tid + q * 256;
            int r = f >> 2, cc = (f & 3) * 4;
            int gm = m0 + r, gk = k0 + cc;
            float4 v = {0.f, 0.f, 0.f, 0.f};
            if (gm < M && gk < K) v = *(const float4*)&A[(size_t)gm * K + gk];  // K%4==0
            areg[q] = v;
        }
    };
    auto stA = [&](int buf) {
        #pragma unroll
        for (int q = 0; q < 2; q++) {
            int f = tid + q * 256;
            int r = f >> 2, cc = (f & 3) * 4;
            As[buf][cc + 0][r] = to_tf32(areg[q].x);
            As[buf][cc + 1][r] = to_tf32(areg[q].y);
            As[buf][cc + 2][r] = to_tf32(areg[q].z);
            As[buf][cc + 3][r] = to_tf32(areg[q].w);
        }
    };
    auto cpB = [&](int k0, int buf) {
        const int NV4 = BN / 4;
        #pragma unroll
        for (int f = tid; f < 16 * NV4; f += 256) {
            int r = f / NV4, cc = (f % NV4) * 4;
            int gk = k0 + r;
            int bytes = (gk < K) ? 16 : 0;
            int gkc = (gk < K) ? gk : (K - 1);
            cp_async16(&Bs[buf][r][cc], &B[(size_t)gkc * N + n0 + cc], bytes);
        }
        asm volatile("cp.async.commit_group;");
    };

    int nk = (K + 15) / 16;
    ldA(0);
    cpB(0, 0);
    for (int t = 0; t < nk; t++) {
        int buf = t & 1;
        stA(buf);
        asm volatile("cp.async.wait_group 0;");
        __syncthreads();
        if (t + 1 < nk) { ldA((t + 1) * 16); cpB((t + 1) * 16, buf ^ 1); }
        #pragma unroll
        for (int kk = 0; kk < 16; kk += 8) {
            unsigned af[MT][4];
            #pragma unroll
            for (int mt = 0; mt < MT; mt++) {
                int m = wm0 + mt * 16 + lr;
                af[mt][0] = __float_as_uint(As[buf][kk + lc][m]);
                af[mt][1] = __float_as_uint(As[buf][kk + lc][m + 8]);
                af[mt][2] = __float_as_uint(As[buf][kk + lc + 4][m]);
                af[mt][3] = __float_as_uint(As[buf][kk + lc + 4][m + 8]);
            }
            unsigned bf[NT][2];
            #pragma unroll
            for (int nt = 0; nt < NT; nt++) {
                int n = wn0 + nt * 8 + lr;
                bf[nt][0] = to_tf32u(Bs[buf][kk + lc][n]);
                bf[nt][1] = to_tf32u(Bs[buf][kk + lc + 4][n]);
            }
            #pragma unroll
            for (int mt = 0; mt < MT; mt++)
                #pragma unroll
                for (int nt = 0; nt < NT; nt++)
                    mma_tf32(c[mt][nt][0], c[mt][nt][1], c[mt][nt][2], c[mt][nt][3],
                             af[mt][0], af[mt][1], af[mt][2], af[mt][3],
                             bf[nt][0], bf[nt][1]);
        }
        __syncthreads();
    }

    // ---- epilogue ----
    float asv[NT][2], adv[NT][2];
    if (EPI == 2) {
        #pragma unroll
        for (int nt = 0; nt < NT; nt++) {
            int gc = n0 + wn0 + nt * 8 + lc * 2;
            asv[nt][0] = a_src[gc]; asv[nt][1] = a_src[gc + 1];
            adv[nt][0] = a_dst[gc]; adv[nt][1] = a_dst[gc + 1];
        }
    }
    float* Cf = (float*)Cv;
    __half* Ch = (__half*)Cv;
    #pragma unroll
    for (int mt = 0; mt < MT; mt++) {
        int r0 = m0 + wm0 + mt * 16 + lr;
        int r1 = r0 + 8;
        float s0 = 0.f, s1 = 0.f, d0 = 0.f, d1 = 0.f;
        #pragma unroll
        for (int nt = 0; nt < NT; nt++) {
            int gc = n0 + wn0 + nt * 8 + lc * 2;
            float v0 = c[mt][nt][0], v1 = c[mt][nt][1];
            float v2 = c[mt][nt][2], v3 = c[mt][nt][3];
            if (EPI == 1) {
                float b0 = bias[gc], b1 = bias[gc + 1];
                v0 = selu_f(v0 + b0); v1 = selu_f(v1 + b1);
                v2 = selu_f(v2 + b0); v3 = selu_f(v3 + b1);
            }
            if (EPI == 2) {
                s0 += v0 * asv[nt][0] + v1 * asv[nt][1];
                s1 += v2 * asv[nt][0] + v3 * asv[nt][1];
                d0 += v0 * adv[nt][0] + v1 * adv[nt][1];
                d1 += v2 * adv[nt][0] + v3 * adv[nt][1];
                if (r0 < M) *(__half2*)&Ch[(size_t)r0 * N + gc] = __floats2half2_rn(v0, v1);
                if (r1 < M) *(__half2*)&Ch[(size_t)r1 * N + gc] = __floats2half2_rn(v2, v3);
            } else {
                if (r0 < M) *(float2*)&Cf[(size_t)r0 * N + gc] = make_float2(v0, v1);
                if (r1 < M) *(float2*)&Cf[(size_t)r1 * N + gc] = make_float2(v2, v3);
            }
        }
        if (EPI == 2) {
            s0 += __shfl_xor_sync(0xFFFFFFFFu, s0, 1);
            s0 += __shfl_xor_sync(0xFFFFFFFFu, s0, 2);
            s1 += __shfl_xor_sync(0xFFFFFFFFu, s1, 1);
            s1 += __shfl_xor_sync(0xFFFFFFFFu, s1, 2);
            d0 += __shfl_xor_sync(0xFFFFFFFFu, d0, 1);
            d0 += __shfl_xor_sync(0xFFFFFFFFu, d0, 2);
            d1 += __shfl_xor_sync(0xFFFFFFFFu, d1, 1);
            d1 += __shfl_xor_sync(0xFFFFFFFFu, d1, 2);
            if (lc == 0) {
                int h = (n0 + wn0) >> 6;   // WN=32 tile lies within one 64-col head
                if (r0 < M) { atomicAdd(&AS[r0 * 4 + h], s0); atomicAdd(&AD[r0 * 4 + h], d0); }
                if (r1 < M) { atomicAdd(&AS[r1 * 4 + h], s1); atomicAdd(&AD[r1 * 4 + h], d1); }
            }
        }
    }
}

// =================== GAT gather: warp per dst, fp16 H, online softmax ===================
__device__ __forceinline__ void ons_update(float e, const float* v,
                                           float& m, float& s, float* acc) {
    if (e <= m) {
        float w = expf(e - m);
        s += w;
        #pragma unroll
        for (int q = 0; q < 8; q++) acc[q] += w * v[q];
    } else {
        float sc = expf(m - e);   // first iter: exp(-inf)=0
        s = s * sc + 1.f;
        #pragma unroll
        for (int q = 0; q < 8; q++) acc[q] = acc[q] * sc + v[q];
        m = e;
    }
}
__device__ __forceinline__ void unpack8(uint4 u, float* v) {
    __half2* hh = (__half2*)&u;
    #pragma unroll
    for (int q = 0; q < 4; q++) {
        float2 f = __half22float2(hh[q]);
        v[q * 2] = f.x; v[q * 2 + 1] = f.y;
    }
}

__global__ void gat_gather_kernel(const int* __restrict__ rowptr, const int* __restrict__ adj,
                                  const __half* __restrict__ H, const float* __restrict__ AS,
                                  const float* __restrict__ AD, const float* __restrict__ gb,
                                  float* __restrict__ OUT, int N) {
    int gw = (blockIdx.x * blockDim.x + threadIdx.x) >> 5;
    int lane = threadIdx.x & 31;
    if (gw >= N) return;
    int dst = gw;
    int h = lane >> 3;
    float adh = AD[dst * 4 + h];
    int beg = rowptr[dst], end = rowptr[dst + 1];
    float acc[8] = {};
    float m = -INFINITY, s = 0.f;
    int i = beg;
    for (; i + 2 <= end; i += 2) {
        int s0 = adj[i], s1 = adj[i + 1];
        float e0 = AS[s0 * 4 + h] + adh;
        float e1 = AS[s1 * 4 + h] + adh;
        uint4 u0 = *((const uint4*)(H + (size_t)s0 * 256) + lane);
        uint4 u1 = *((const uint4*)(H + (size_t)s1 * 256) + lane);
        float v0[8], v1[8];
        unpack8(u0, v0);
        unpack8(u1, v1);
        e0 = e0 > 0.f ? e0 : 0.2f * e0;
        e1 = e1 > 0.f ? e1 : 0.2f * e1;
        ons_update(e0, v0, m, s, acc);
        ons_update(e1, v1, m, s, acc);
    }
    if (i < end) {
        int s0 = adj[i];
        float e0 = AS[s0 * 4 + h] + adh;
        uint4 u0 = *((const uint4*)(H + (size_t)s0 * 256) + lane);
        float v0[8];
        unpack8(u0, v0);
        e0 = e0 > 0.f ? e0 : 0.2f * e0;
        ons_update(e0, v0, m, s, acc);
    }
    float inv = 1.f / (s + 1e-16f);
    float* o = OUT + (size_t)dst * 256 + lane * 8;
    const float* gbp = gb + lane * 8;
    float4 r0 = {acc[0] * inv + gbp[0], acc[1] * inv + gbp[1],
                 acc[2] * inv + gbp[2], acc[3] * inv + gbp[3]};
    float4 r1 = {acc[4] * inv + gbp[4], acc[5] * inv + gbp[5],
                 acc[6] * inv + gbp[6], acc[7] * inv + gbp[7]};
    *(float4*)(o + 0) = r0;
    *(float4*)(o + 4) = r1;
}

// =================== standalone pool pieces ===================
__global__ void pool_acc_kernel(const float* __restrict__ Hx, const int* __restrict__ batch,
                                float* __restrict__ SUMP, int* __restrict__ MAXP,
                                int* __restrict__ CNT, int N) {
    int c = threadIdx.x & 63;
    int r = blockIdx.x * 128 + (threadIdx.x >> 6);
    int rend = blockIdx.x * 128 + 128;
    if (rend > N) rend = N;
    float sum = 0.f, mx = -INFINITY;
    int cnt = 0, curg = -1;
    for (; r < rend; r += 4) {
        int g = batch[r];
        float v = Hx[(size_t)r * 64 + c];
        if (g != curg) {
            if (curg >= 0) {
                atomicAdd(&SUMP[curg * 64 + c], sum);
                atomicMax(&MAXP[curg * 64 + c], fmap(mx));
                if (c == 0) atomicAdd(&CNT[curg], cnt);
            }
            curg = g; sum = 0.f; mx = -INFINITY; cnt = 0;
        }
        sum += v;
        mx = fmaxf(mx, v);
        cnt++;
    }
    if (curg >= 0) {
        atomicAdd(&SUMP[curg * 64 + c], sum);
        atomicMax(&MAXP[curg * 64 + c], fmap(mx));
        if (c == 0) atomicAdd(&CNT[curg], cnt);
    }
}
__global__ void pool_fin_kernel(const float* __restrict__ SUMP, const int* __restrict__ MAXP,
                                const int* __restrict__ CNT, float* __restrict__ X) {
    int i = blockIdx.x * blockDim.x + threadIdx.x;
    if (i >= GMAX * 64) return;
    int g = i >> 6, c = i & 63;
    float cnt = (float)CNT[g];
    if (cnt < 1.f) cnt = 1.f;
    X[g * 128 + c] = SUMP[i] / cnt;
    X[g * 128 + 64 + c] = funmap(MAXP[i]);
}

// =================== final MLP head ===================
__global__ void mlp_kernel(const float* __restrict__ X1, const float* __restrict__ X2,
                           const float* __restrict__ sum_w, const float* __restrict__ sum_b,
                           const float* __restrict__ sh1_w, const float* __restrict__ sh1_b,
                           const float* __restrict__ sh2_w, const float* __restrict__ sh2_b,
                           const float* __restrict__ sh3_w, const float* __restrict__ sh3_b,
                           const float* __restrict__ reg_w, const float* __restrict__ reg_b,
                           float* __restrict__ out) {
    __shared__ float zin[256], z1[128], z2[64], z3[64];
    int g = blockIdx.x, t = threadIdx.x;
    zin[t] = X1[g * 128 + t];
    zin[128 + t] = X2[g * 128 + t];
    __syncthreads();
    {
        float acc = sum_b[t];
        for (int k = 0; k < 256; k++) acc += zin[k] * sum_w[k * 128 + t];
        z1[t] = acc;
    }
    __syncthreads();
    if (t < 64) {
        float acc = sh1_b[t];
        for (int k = 0; k < 128; k++) acc += z1[k] * sh1_w[k * 64 + t];
        z2[t] = selu_f(acc);
    }
    __syncthreads();
    if (t < 64) {
        float acc = sh2_b[t];
        for (int k = 0; k < 64; k++) acc += z2[k] * sh2_w[k * 64 + t];
        z3[t] = selu_f(acc);
    }
    __syncthreads();
    if (t < 64) {
        float acc = sh3_b[t];
        for (int k = 0; k < 64; k++) acc += z3[k] * sh3_w[k * 64 + t];
        z2[t] = selu_f(acc);
    }
    __syncthreads();
    if (t < 32) {
        float acc = reg_b[t];
        for (int k = 0; k < 64; k++) acc += z2[k] * reg_w[k * 32 + t];
        out[g * 32 + t] = acc;
    }
}

// =================== host orchestration ===================
extern "C" void kernel_launch(void* const* d_in, const int* in_sizes, int n_in,
                              void* d_out, int out_size) {
    const float* x       = (const float*)d_in[0];
    const int*   ei      = (const int*)d_in[1];
    const int*   batch   = (const int*)d_in[2];
    const float* gat1_w  = (const float*)d_in[3];
    const float* gat1_as = (const float*)d_in[4];
    const float* gat1_ad = (const float*)d_in[5];
    const float* gat1_b  = (const float*)d_in[6];
    const float* lin1_w  = (const float*)d_in[7];
    const float* lin1_b  = (const float*)d_in[8];
    const float* gat2_w  = (const float*)d_in[9];
    const float* gat2_as = (const float*)d_in[10];
    const float* gat2_ad = (const float*)d_in[11];
    const float* gat2_b  = (const float*)d_in[12];
    const float* lin2_w  = (const float*)d_in[13];
    const float* lin2_b  = (const float*)d_in[14];
    const float* sum_w   = (const float*)d_in[15];
    const float* sum_b   = (const float*)d_in[16];
    const float* sh1_w   = (const float*)d_in[17];
    const float* sh1_b   = (const float*)d_in[18];
    const float* sh2_w   = (const float*)d_in[19];
    const float* sh2_b   = (const float*)d_in[20];
    const float* sh3_w   = (const float*)d_in[21];
    const float* sh3_b   = (const float*)d_in[22];
    const float* reg_w   = (const float*)d_in[23];
    const float* reg_b   = (const float*)d_in[24];

    int N  = in_sizes[2];
    int E  = in_sizes[1] / 2;
    int K1 = in_sizes[0] / N;
    int ET = E + N;

    __half* H;
    float *OUT, *H1, *H2, *AS, *AD, *AS2, *AD2, *SUMP1, *SUMP2, *X1, *X2;
    int *deg, *rowptr, *cur, *adj, *bsum, *MAXP1, *CNT1, *MAXP2, *CNT2;
    cudaGetSymbolAddress((void**)&H, g_H);
    cudaGetSymbolAddress((void**)&OUT, g_OUT);
    cudaGetSymbolAddress((void**)&H1, g_H1);
    cudaGetSymbolAddress((void**)&H2, g_H2);
    cudaGetSymbolAddress((void**)&AS, g_AS);
    cudaGetSymbolAddress((void**)&AD, g_AD);
    cudaGetSymbolAddress((void**)&AS2, g_AS2);
    cudaGetSymbolAddress((void**)&AD2, g_AD2);
    cudaGetSymbolAddress((void**)&deg, g_deg);
    cudaGetSymbolAddress((void**)&rowptr, g_rowptr);
    cudaGetSymbolAddress((void**)&cur, g_cur);
    cudaGetSymbolAddress((void**)&adj, g_adj);
    cudaGetSymbolAddress((void**)&bsum, g_bsum);
    cudaGetSymbolAddress((void**)&SUMP1, g_SUMP1);
    cudaGetSymbolAddress((void**)&MAXP1, g_MAXP1);
    cudaGetSymbolAddress((void**)&CNT1, g_CNT1);
    cudaGetSymbolAddress((void**)&SUMP2, g_SUMP2);
    cudaGetSymbolAddress((void**)&MAXP2, g_MAXP2);
    cudaGetSymbolAddress((void**)&CNT2, g_CNT2);
    cudaGetSymbolAddress((void**)&X1, g_X1);
    cudaGetSymbolAddress((void**)&X2, g_X2);

    int nScanBlocks = (N + 2047) / 2048;
    int nyH = (N + 127) / 128;
    dim3 gH(2, nyH);       // big GEMMs (BN=128, N=256)
    dim3 gH2(3, nyH);      // GEMM2 + fused pool_acc side slice
    dim3 gL(1, nyH);       // lin GEMMs (BN=64)

    // 0-2: prep; 3 = GEMM1 (ncu profiles launch idx 3)
    init_all_kernel<<<(N * 4 + 255) / 256, 256>>>(deg, cur, AS, AD, AS2, AD2,
                                                  SUMP1, MAXP1, CNT1, SUMP2, MAXP2, CNT2, N);
    deg_count_kernel<<<(E + 255) / 256, 256>>>(ei, deg, E);
    scan1_kernel<<<nScanBlocks, 256>>>(deg, rowptr, bsum, N);

    // 3: GEMM1 -> H (fp16) + attention dots
    tf32_gemm_kernel<128, 2, 4, 2, 0><<<gH, 256>>>(
        x, gat1_w, nullptr, H, gat1_as, gat1_ad, AS, AD,
        nullptr, nullptr, nullptr, nullptr, nullptr, N, 256, K1, 0);

    // 4-5: finish CSR
    scan23_kernel<<<nScanBlocks, 256>>>(rowptr, bsum, N, ET);
    fill_kernel<<<(ET + 255) / 256, 256>>>(ei, rowptr, cur, adj, E, ET);

    // 6: layer-1 aggregate (fp16 H reads)
    gat_gather_kernel<<<(N * 32 + 255) / 256, 256>>>(rowptr, adj, H, AS, AD, gat1_b, OUT, N);
    // 7: lin1 + selu
    tf32_gemm_kernel<64, 4, 2, 1, 0><<<gL, 256>>>(
        OUT, lin1_w, lin1_b, H1, nullptr, nullptr, nullptr, nullptr,
        nullptr, nullptr, nullptr, nullptr, nullptr, N, 64, 256, 0);

    // 8: GEMM2 -> H (fp16) + att dots, with fused pool_acc(H1) side slice
    tf32_gemm_kernel<128, 2, 4, 2, 2><<<gH2, 256>>>(
        H1, gat2_w, nullptr, H, gat2_as, gat2_ad, AS2, AD2,
        H1, batch, SUMP1, MAXP1, CNT1, N, 256, 64, 0);
    // 9: finish pool1 -> X1
    pool_fin_kernel<<<(GMAX * 64 + 255) / 256, 256>>>(SUMP1, MAXP1, CNT1, X1);

    // 10: layer-2 aggregate
    gat_gather_kernel<<<(N * 32 + 255) / 256, 256>>>(rowptr, adj, H, AS2, AD2, gat2_b, OUT, N);
    // 11: lin2 + selu
    tf32_gemm_kernel<64, 4, 2, 1, 0><<<gL, 256>>>(
        OUT, lin2_w, lin2_b, H2, nullptr, nullptr, nullptr, nullptr,
        nullptr, nullptr, nullptr, nullptr, nullptr, N, 64, 256, 0);

    // 12-13: pool2 -> X2
    pool_acc_kernel<<<nyH, 256>>>(H2, batch, SUMP2, MAXP2, CNT2, N);
    pool_fin_kernel<<<(GMAX * 64 + 255) / 256, 256>>>(SUMP2, MAXP2, CNT2, X2);

    // 14: head MLP
    mlp_kernel<<<GMAX, 128>>>(X1, X2, sum_w, sum_b, sh1_w, sh1_b, sh2_w, sh2_b,
                              sh3_w, sh3_b, reg_w, reg_b, (float*)d_out);
}

// round 8
// speedup vs baseline: 1.1611x; 1.0728x over previous
#include <cuda_runtime.h>
#include <cuda_fp16.h>
#include <math.h>

#define NMAX 100000
#define EMAX 800000
#define ETMAX (NMAX + EMAX)
#define GMAX 128

// ---------------- device scratch ----------------
__device__ __half g_H[NMAX * 256];     // GAT hidden h, fp16 (read by gather)
__device__ float g_OUT[NMAX * 256];
__device__ float g_H1[NMAX * 64];
__device__ float g_H2[NMAX * 64];
__device__ float g_AS[NMAX * 4];
__device__ float g_AD[NMAX * 4];
__device__ float g_AS2[NMAX * 4];
__device__ float g_AD2[NMAX * 4];
__device__ int   g_deg[NMAX];
__device__ int   g_rowptr[NMAX + 1];
__device__ int   g_cur[NMAX];
__device__ int   g_adj[ETMAX];
__device__ int   g_bsum[256];
__device__ float g_SUMP1[GMAX * 64];
__device__ int   g_MAXP1[GMAX * 64];
__device__ int   g_CNT1[GMAX];
__device__ float g_SUMP2[GMAX * 64];
__device__ int   g_MAXP2[GMAX * 64];
__device__ int   g_CNT2[GMAX];
__device__ float g_X1[GMAX * 128];
__device__ float g_X2[GMAX * 128];

// ---------------- helpers ----------------
__device__ __forceinline__ int fmap(float f) {
    int i = __float_as_int(f);
    return i >= 0 ? i : (i ^ 0x7FFFFFFF);
}
__device__ __forceinline__ float funmap(int i) {
    return __int_as_float(i >= 0 ? i : (i ^ 0x7FFFFFFF));
}
__device__ __forceinline__ float selu_f(float x) {
    const float a = 1.6732632423543772f, s = 1.0507009873554805f;
    return x > 0.f ? s * x : s * a * (expf(x) - 1.f);
}
// fp16 MMA m16n8k16, fp32 accumulate
__device__ __forceinline__ void mma_f16(float& c0, float& c1, float& c2, float& c3,
                                        unsigned a0, unsigned a1, unsigned a2, unsigned a3,
                                        unsigned b0, unsigned b1) {
    asm volatile(
        "mma.sync.aligned.m16n8k16.row.col.f32.f16.f16.f32 "
        "{%0,%1,%2,%3}, {%4,%5,%6,%7}, {%8,%9}, {%0,%1,%2,%3};"
        : "+f"(c0), "+f"(c1), "+f"(c2), "+f"(c3)
        : "r"(a0), "r"(a1), "r"(a2), "r"(a3), "r"(b0), "r"(b1));
}

// =================== one-shot init ===================
__global__ void init_all_kernel(int* __restrict__ deg, int* __restrict__ cur,
                                float* __restrict__ AS, float* __restrict__ AD,
                                float* __restrict__ AS2, float* __restrict__ AD2,
                                float* __restrict__ SUMP1, int* __restrict__ MAXP1,
                                int* __restrict__ CNT1,
                                float* __restrict__ SUMP2, int* __restrict__ MAXP2,
                                int* __restrict__ CNT2, int N) {
    int i = blockIdx.x * blockDim.x + threadIdx.x;
    if (i < N) { deg[i] = 1; cur[i] = 0; }
    if (i < N * 4) { AS[i] = 0.f; AD[i] = 0.f; AS2[i] = 0.f; AD2[i] = 0.f; }
    if (i < GMAX * 64) {
        SUMP1[i] = 0.f; MAXP1[i] = fmap(-INFINITY);
        SUMP2[i] = 0.f; MAXP2[i] = fmap(-INFINITY);
    }
    if (i < GMAX) { CNT1[i] = 0; CNT2[i] = 0; }
}

// =================== CSR build ===================
__global__ void deg_count_kernel(const int* __restrict__ ei, int* __restrict__ deg, int E) {
    int e = blockIdx.x * blockDim.x + threadIdx.x;
    if (e < E) atomicAdd(&deg[ei[E + e]], 1);
}
__global__ void scan1_kernel(const int* __restrict__ deg, int* __restrict__ rowptr,
                             int* __restrict__ bsum, int N) {
    __shared__ int sh[256];
    int tid = threadIdx.x;
    int base = blockIdx.x * 2048 + tid * 8;
    int v[8], pre[8];
    int sum = 0;
    #pragma unroll
    for (int j = 0; j < 8; j++) {
        v[j] = (base + j < N) ? deg[base + j] : 0;
        pre[j] = sum;
        sum += v[j];
    }
    sh[tid] = sum;
    __syncthreads();
    for (int off = 1; off < 256; off <<= 1) {
        int t = (tid >= off) ? sh[tid - off] : 0;
        __syncthreads();
        sh[tid] += t;
        __syncthreads();
    }
    int texcl = sh[tid] - sum;
    #pragma unroll
    for (int j = 0; j < 8; j++)
        if (base + j < N) rowptr[base + j] = texcl + pre[j];
    if (tid == 255) bsum[blockIdx.x] = sh[255];
}
__global__ void scan23_kernel(int* __restrict__ rowptr, const int* __restrict__ bsum,
                              int N, int ET) {
    __shared__ int s_add;
    int tid = threadIdx.x;
    if (tid < 32) {
        int s = 0;
        for (int j = tid; j < blockIdx.x; j += 32) s += bsum[j];
        #pragma unroll
        for (int off = 16; off; off >>= 1) s += __shfl_down_sync(0xFFFFFFFFu, s, off);
        if (tid == 0) s_add = s;
    }
    __syncthreads();
    int add = s_add;
    int base = blockIdx.x * 2048 + tid * 8;
    #pragma unroll
    for (int j = 0; j < 8; j++)
        if (base + j < N) rowptr[base + j] += add;
    if (blockIdx.x == 0 && tid == 0) rowptr[N] = ET;
}
__global__ void fill_kernel(const int* __restrict__ ei, const int* __restrict__ rowptr,
                            int* __restrict__ cur, int* __restrict__ adj, int E, int ET) {
    int idx = blockIdx.x * blockDim.x + threadIdx.x;
    if (idx >= ET) return;
    int src, dst;
    if (idx < E) { src = ei[idx]; dst = ei[E + idx]; }
    else         { src = dst = idx - E; }
    adj[rowptr[dst] + atomicAdd(&cur[dst], 1)] = src;
}

// =================== fp16 m16n8k16 GEMM, fp32 accum, double-buffered ===================
// C[MxN] = A[MxK] @ B[KxN].  BM=128, BK=16, 256 threads.
// A smem: [128][24] half (row-major, padded). B smem: [8][BN+8] half2 (k-paired).
// EPI: 0 = plain fp32, 1 = bias+selu fp32, 2 = fp16 store + fused attention dots
// SIDE: 0 = none; 2 = last-grid.x blocks do pool_acc
template <int BN, int WARPS_M, int WARPS_N, int EPI, int SIDE>
__global__ void __launch_bounds__(256)
f16_gemm_kernel(const float* __restrict__ A, const float* __restrict__ B,
                const float* __restrict__ bias, void* __restrict__ Cv,
                const float* __restrict__ a_src, const float* __restrict__ a_dst,
                float* __restrict__ AS, float* __restrict__ AD,
                const void* sp0, const void* sp1, void* sp2, void* sp3, void* sp4,
                int M, int N, int K, int sE) {
    if (SIDE == 2 && blockIdx.x == gridDim.x - 1) {
        const float* Hx = (const float*)sp0;
        const int* batch = (const int*)sp1;
        float* SUMP = (float*)sp2;
        int* MAXP = (int*)sp3;
        int* CNT = (int*)sp4;
        int c = threadIdx.x & 63;
        int r = blockIdx.y * 128 + (threadIdx.x >> 6);
        int rend = blockIdx.y * 128 + 128;
        if (rend > M) rend = M;
        float sum = 0.f, mx = -INFINITY;
        int cnt = 0, curg = -1;
        for (; r < rend; r += 4) {
            int g = batch[r];
            float v = Hx[(size_t)r * 64 + c];
            if (g != curg) {
                if (curg >= 0) {
                    atomicAdd(&SUMP[curg * 64 + c], sum);
                    atomicMax(&MAXP[curg * 64 + c], fmap(mx));
                    if (c == 0) atomicAdd(&CNT[curg], cnt);
                }
                curg = g; sum = 0.f; mx = -INFINITY; cnt = 0;
            }
            sum += v;
            mx = fmaxf(mx, v);
            cnt++;
        }
        if (curg >= 0) {
            atomicAdd(&SUMP[curg * 64 + c], sum);
            atomicMax(&MAXP[curg * 64 + c], fmap(mx));
            if (c == 0) atomicAdd(&CNT[curg], cnt);
        }
        return;
    }

    const int WM = 128 / WARPS_M, WN = BN / WARPS_N;
    const int MT = WM / 16, NT = WN / 8;
    const int ASTR = 24;                        // halves per A row (16 + 8 pad)
    __shared__ __half  Asm[2][128][ASTR];       // [buf][m][k] fp16
    __shared__ __half2 Bs2[2][8][BN + 8];       // [buf][k/2][n] = {B[2k2][n], B[2k2+1][n]}

    int tid = threadIdx.x;
    int warp = tid >> 5, lane = tid & 31;
    int lr = lane >> 2, lc = lane & 3;
    int warp_m = warp / WARPS_N, warp_n = warp % WARPS_N;
    int wm0 = warp_m * WM, wn0 = warp_n * WN;
    int m0 = blockIdx.y * 128, n0 = blockIdx.x * BN;

    float c[MT][NT][4];
    #pragma unroll
    for (int i = 0; i < MT; i++)
        #pragma unroll
        for (int j = 0; j < NT; j++)
            #pragma unroll
            for (int q = 0; q < 4; q++) c[i][j][q] = 0.f;

    float4 areg[2];
    float4 bga, bgb;
    const int BTASK = 8 * (BN / 4);   // 256 for BN=128, 128 for BN=64
    int bk2 = tid / (BN / 4);
    int bnc = (tid % (BN / 4)) * 4;

    auto ldA = [&](int k0) {
        #pragma unroll
        for (int q = 0; q < 2; q++) {
            int f = tid + q * 256;
            int r = f >> 2, cc = (f & 3) * 4;
            int gm = m0 + r, gk = k0 + cc;
            float4 v = {0.f, 0.f, 0.f, 0.f};
            if (gm < M && gk < K) v = *(const float4*)&A[(size_t)gm * K + gk];  // K%4==0
            areg[q] = v;
        }
    };
    auto stA = [&](int buf) {
        #pragma unroll
        for (int q = 0; q < 2; q++) {
            int f = tid + q * 256;
            int r = f >> 2, cc = (f & 3) * 4;
            __half2 h0 = __floats2half2_rn(areg[q].x, areg[q].y);
            __half2 h1 = __floats2half2_rn(areg[q].z, areg[q].w);
            *(__half2*)&Asm[buf][r][cc]     = h0;
            *(__half2*)&Asm[buf][r][cc + 2] = h1;
        }
    };
    auto ldB = [&](int k0) {
        if (tid < BTASK) {
            int gk0 = k0 + 2 * bk2, gk1 = gk0 + 1;
            float4 z = {0.f, 0.f, 0.f, 0.f};
            bga = (gk0 < K) ? *(const float4*)&B[(size_t)gk0 * N + n0 + bnc] : z;
            bgb = (gk1 < K) ? *(const float4*)&B[(size_t)gk1 * N + n0 + bnc] : z;
        }
    };
    auto stB = [&](int buf) {
        if (tid < BTASK) {
            Bs2[buf][bk2][bnc + 0] = __floats2half2_rn(bga.x, bgb.x);
            Bs2[buf][bk2][bnc + 1] = __floats2half2_rn(bga.y, bgb.y);
            Bs2[buf][bk2][bnc + 2] = __floats2half2_rn(bga.z, bgb.z);
            Bs2[buf][bk2][bnc + 3] = __floats2half2_rn(bga.w, bgb.w);
        }
    };

    int nk = (K + 15) / 16;
    ldA(0);
    ldB(0);
    for (int t = 0; t < nk; t++) {
        int buf = t & 1;
        stA(buf);
        stB(buf);
        __syncthreads();
        if (t + 1 < nk) { ldA((t + 1) * 16); ldB((t + 1) * 16); }

        // fragments: A = m16k16, B = k16n8 per (mt,nt); one MMA covers full BK=16
        unsigned af[MT][4];
        #pragma unroll
        for (int mt = 0; mt < MT; mt++) {
            int row = wm0 + mt * 16 + lr;
            af[mt][0] = *(const unsigned*)&Asm[buf][row][2 * lc];
            af[mt][1] = *(const unsigned*)&Asm[buf][row + 8][2 * lc];
            af[mt][2] = *(const unsigned*)&Asm[buf][row][2 * lc + 8];
            af[mt][3] = *(const unsigned*)&Asm[buf][row + 8][2 * lc + 8];
        }
        unsigned bf[NT][2];
        #pragma unroll
        for (int nt = 0; nt < NT; nt++) {
            int n = wn0 + nt * 8 + lr;
            bf[nt][0] = *(const unsigned*)&Bs2[buf][lc][n];
            bf[nt][1] = *(const unsigned*)&Bs2[buf][lc + 4][n];
        }
        #pragma unroll
        for (int mt = 0; mt < MT; mt++)
            #pragma unroll
            for (int nt = 0; nt < NT; nt++)
                mma_f16(c[mt][nt][0], c[mt][nt][1], c[mt][nt][2], c[mt][nt][3],
                        af[mt][0], af[mt][1], af[mt][2], af[mt][3],
                        bf[nt][0], bf[nt][1]);
        __syncthreads();
    }

    // ---- epilogue ----
    float asv[NT][2], adv[NT][2];
    if (EPI == 2) {
        #pragma unroll
        for (int nt = 0; nt < NT; nt++) {
            int gc = n0 + wn0 + nt * 8 + lc * 2;
            asv[nt][0] = a_src[gc]; asv[nt][1] = a_src[gc + 1];
            adv[nt][0] = a_dst[gc]; adv[nt][1] = a_dst[gc + 1];
        }
    }
    float* Cf = (float*)Cv;
    __half* Ch = (__half*)Cv;
    #pragma unroll
    for (int mt = 0; mt < MT; mt++) {
        int r0 = m0 + wm0 + mt * 16 + lr;
        int r1 = r0 + 8;
        float s0 = 0.f, s1 = 0.f, d0 = 0.f, d1 = 0.f;
        #pragma unroll
        for (int nt = 0; nt < NT; nt++) {
            int gc = n0 + wn0 + nt * 8 + lc * 2;
            float v0 = c[mt][nt][0], v1 = c[mt][nt][1];
            float v2 = c[mt][nt][2], v3 = c[mt][nt][3];
            if (EPI == 1) {
                float b0 = bias[gc], b1 = bias[gc + 1];
                v0 = selu_f(v0 + b0); v1 = selu_f(v1 + b1);
                v2 = selu_f(v2 + b0); v3 = selu_f(v3 + b1);
            }
            if (EPI == 2) {
                s0 += v0 * asv[nt][0] + v1 * asv[nt][1];
                s1 += v2 * asv[nt][0] + v3 * asv[nt][1];
                d0 += v0 * adv[nt][0] + v1 * adv[nt][1];
                d1 += v2 * adv[nt][0] + v3 * adv[nt][1];
                if (r0 < M) *(__half2*)&Ch[(size_t)r0 * N + gc] = __floats2half2_rn(v0, v1);
                if (r1 < M) *(__half2*)&Ch[(size_t)r1 * N + gc] = __floats2half2_rn(v2, v3);
            } else {
                if (r0 < M) *(float2*)&Cf[(size_t)r0 * N + gc] = make_float2(v0, v1);
                if (r1 < M) *(float2*)&Cf[(size_t)r1 * N + gc] = make_float2(v2, v3);
            }
        }
        if (EPI == 2) {
            s0 += __shfl_xor_sync(0xFFFFFFFFu, s0, 1);
            s0 += __shfl_xor_sync(0xFFFFFFFFu, s0, 2);
            s1 += __shfl_xor_sync(0xFFFFFFFFu, s1, 1);
            s1 += __shfl_xor_sync(0xFFFFFFFFu, s1, 2);
            d0 += __shfl_xor_sync(0xFFFFFFFFu, d0, 1);
            d0 += __shfl_xor_sync(0xFFFFFFFFu, d0, 2);
            d1 += __shfl_xor_sync(0xFFFFFFFFu, d1, 1);
            d1 += __shfl_xor_sync(0xFFFFFFFFu, d1, 2);
            if (lc == 0) {
                int h = (n0 + wn0) >> 6;   // WN=32 tile lies within one 64-col head
                if (r0 < M) { atomicAdd(&AS[r0 * 4 + h], s0); atomicAdd(&AD[r0 * 4 + h], d0); }
                if (r1 < M) { atomicAdd(&AS[r1 * 4 + h], s1); atomicAdd(&AD[r1 * 4 + h], d1); }
            }
        }
    }
}

// =================== GAT gather: warp per dst, fp16 H, online softmax ===================
__device__ __forceinline__ void ons_update(float e, const float* v,
                                           float& m, float& s, float* acc) {
    if (e <= m) {
        float w = expf(e - m);
        s += w;
        #pragma unroll
        for (int q = 0; q < 8; q++) acc[q] += w * v[q];
    } else {
        float sc = expf(m - e);   // first iter: exp(-inf)=0
        s = s * sc + 1.f;
        #pragma unroll
        for (int q = 0; q < 8; q++) acc[q] = acc[q] * sc + v[q];
        m = e;
    }
}
__device__ __forceinline__ void unpack8(uint4 u, float* v) {
    __half2* hh = (__half2*)&u;
    #pragma unroll
    for (int q = 0; q < 4; q++) {
        float2 f = __half22float2(hh[q]);
        v[q * 2] = f.x; v[q * 2 + 1] = f.y;
    }
}

__global__ void gat_gather_kernel(const int* __restrict__ rowptr, const int* __restrict__ adj,
                                  const __half* __restrict__ H, const float* __restrict__ AS,
                                  const float* __restrict__ AD, const float* __restrict__ gb,
                                  float* __restrict__ OUT, int N) {
    int gw = (blockIdx.x * blockDim.x + threadIdx.x) >> 5;
    int lane = threadIdx.x & 31;
    if (gw >= N) return;
    int dst = gw;
    int h = lane >> 3;
    float adh = AD[dst * 4 + h];
    int beg = rowptr[dst], end = rowptr[dst + 1];
    float acc[8] = {};
    float m = -INFINITY, s = 0.f;
    int i = beg;
    for (; i + 2 <= end; i += 2) {
        int s0 = adj[i], s1 = adj[i + 1];
        float e0 = AS[s0 * 4 + h] + adh;
        float e1 = AS[s1 * 4 + h] + adh;
        uint4 u0 = *((const uint4*)(H + (size_t)s0 * 256) + lane);
        uint4 u1 = *((const uint4*)(H + (size_t)s1 * 256) + lane);
        float v0[8], v1[8];
        unpack8(u0, v0);
        unpack8(u1, v1);
        e0 = e0 > 0.f ? e0 : 0.2f * e0;
        e1 = e1 > 0.f ? e1 : 0.2f * e1;
        ons_update(e0, v0, m, s, acc);
        ons_update(e1, v1, m, s, acc);
    }
    if (i < end) {
        int s0 = adj[i];
        float e0 = AS[s0 * 4 + h] + adh;
        uint4 u0 = *((const uint4*)(H + (size_t)s0 * 256) + lane);
        float v0[8];
        unpack8(u0, v0);
        e0 = e0 > 0.f ? e0 : 0.2f * e0;
        ons_update(e0, v0, m, s, acc);
    }
    float inv = 1.f / (s + 1e-16f);
    float* o = OUT + (size_t)dst * 256 + lane * 8;
    const float* gbp = gb + lane * 8;
    float4 r0 = {acc[0] * inv + gbp[0], acc[1] * inv + gbp[1],
                 acc[2] * inv + gbp[2], acc[3] * inv + gbp[3]};
    float4 r1 = {acc[4] * inv + gbp[4], acc[5] * inv + gbp[5],
                 acc[6] * inv + gbp[6], acc[7] * inv + gbp[7]};
    *(float4*)(o + 0) = r0;
    *(float4*)(o + 4) = r1;
}

// =================== standalone pool pieces ===================
__global__ void pool_acc_kernel(const float* __restrict__ Hx, const int* __restrict__ batch,
                                float* __restrict__ SUMP, int* __restrict__ MAXP,
                                int* __restrict__ CNT, int N) {
    int c = threadIdx.x & 63;
    int r = blockIdx.x * 128 + (threadIdx.x >> 6);
    int rend = blockIdx.x * 128 + 128;
    if (rend > N) rend = N;
    float sum = 0.f, mx = -INFINITY;
    int cnt = 0, curg = -1;
    for (; r < rend; r += 4) {
        int g = batch[r];
        float v = Hx[(size_t)r * 64 + c];
        if (g != curg) {
            if (curg >= 0) {
                atomicAdd(&SUMP[curg * 64 + c], sum);
                atomicMax(&MAXP[curg * 64 + c], fmap(mx));
                if (c == 0) atomicAdd(&CNT[curg], cnt);
            }
            curg = g; sum = 0.f; mx = -INFINITY; cnt = 0;
        }
        sum += v;
        mx = fmaxf(mx, v);
        cnt++;
    }
    if (curg >= 0) {
        atomicAdd(&SUMP[curg * 64 + c], sum);
        atomicMax(&MAXP[curg * 64 + c], fmap(mx));
        if (c == 0) atomicAdd(&CNT[curg], cnt);
    }
}
__global__ void pool_fin_kernel(const float* __restrict__ SUMP, const int* __restrict__ MAXP,
                                const int* __restrict__ CNT, float* __restrict__ X) {
    int i = blockIdx.x * blockDim.x + threadIdx.x;
    if (i >= GMAX * 64) return;
    int g = i >> 6, c = i & 63;
    float cnt = (float)CNT[g];
    if (cnt < 1.f) cnt = 1.f;
    X[g * 128 + c] = SUMP[i] / cnt;
    X[g * 128 + 64 + c] = funmap(MAXP[i]);
}

// =================== final MLP head ===================
__global__ void mlp_kernel(const float* __restrict__ X1, const float* __restrict__ X2,
                           const float* __restrict__ sum_w, const float* __restrict__ sum_b,
                           const float* __restrict__ sh1_w, const float* __restrict__ sh1_b,
                           const float* __restrict__ sh2_w, const float* __restrict__ sh2_b,
                           const float* __restrict__ sh3_w, const float* __restrict__ sh3_b,
                           const float* __restrict__ reg_w, const float* __restrict__ reg_b,
                           float* __restrict__ out) {
    __shared__ float zin[256], z1[128], z2[64], z3[64];
    int g = blockIdx.x, t = threadIdx.x;
    zin[t] = X1[g * 128 + t];
    zin[128 + t] = X2[g * 128 + t];
    __syncthreads();
    {
        float acc = sum_b[t];
        for (int k = 0; k < 256; k++) acc += zin[k] * sum_w[k * 128 + t];
        z1[t] = acc;
    }
    __syncthreads();
    if (t < 64) {
        float acc = sh1_b[t];
        for (int k = 0; k < 128; k++) acc += z1[k] * sh1_w[k * 64 + t];
        z2[t] = selu_f(acc);
    }
    __syncthreads();
    if (t < 64) {
        float acc = sh2_b[t];
        for (int k = 0; k < 64; k++) acc += z2[k] * sh2_w[k * 64 + t];
        z3[t] = selu_f(acc);
    }
    __syncthreads();
    if (t < 64) {
        float acc = sh3_b[t];
        for (int k = 0; k < 64; k++) acc += z3[k] * sh3_w[k * 64 + t];
        z2[t] = selu_f(acc);
    }
    __syncthreads();
    if (t < 32) {
        float acc = reg_b[t];
        for (int k = 0; k < 64; k++) acc += z2[k] * reg_w[k * 32 + t];
        out[g * 32 + t] = acc;
    }
}

// =================== host orchestration ===================
extern "C" void kernel_launch(void* const* d_in, const int* in_sizes, int n_in,
                              void* d_out, int out_size) {
    const float* x       = (const float*)d_in[0];
    const int*   ei      = (const int*)d_in[1];
    const int*   batch   = (const int*)d_in[2];
    const float* gat1_w  = (const float*)d_in[3];
    const float* gat1_as = (const float*)d_in[4];
    const float* gat1_ad = (const float*)d_in[5];
    const float* gat1_b  = (const float*)d_in[6];
    const float* lin1_w  = (const float*)d_in[7];
    const float* lin1_b  = (const float*)d_in[8];
    const float* gat2_w  = (const float*)d_in[9];
    const float* gat2_as = (const float*)d_in[10];
    const float* gat2_ad = (const float*)d_in[11];
    const float* gat2_b  = (const float*)d_in[12];
    const float* lin2_w  = (const float*)d_in[13];
    const float* lin2_b  = (const float*)d_in[14];
    const float* sum_w   = (const float*)d_in[15];
    const float* sum_b   = (const float*)d_in[16];
    const float* sh1_w   = (const float*)d_in[17];
    const float* sh1_b   = (const float*)d_in[18];
    const float* sh2_w   = (const float*)d_in[19];
    const float* sh2_b   = (const float*)d_in[20];
    const float* sh3_w   = (const float*)d_in[21];
    const float* sh3_b   = (const float*)d_in[22];
    const float* reg_w   = (const float*)d_in[23];
    const float* reg_b   = (const float*)d_in[24];

    int N  = in_sizes[2];
    int E  = in_sizes[1] / 2;
    int K1 = in_sizes[0] / N;
    int ET = E + N;

    __half* H;
    float *OUT, *H1, *H2, *AS, *AD, *AS2, *AD2, *SUMP1, *SUMP2, *X1, *X2;
    int *deg, *rowptr, *cur, *adj, *bsum, *MAXP1, *CNT1, *MAXP2, *CNT2;
    cudaGetSymbolAddress((void**)&H, g_H);
    cudaGetSymbolAddress((void**)&OUT, g_OUT);
    cudaGetSymbolAddress((void**)&H1, g_H1);
    cudaGetSymbolAddress((void**)&H2, g_H2);
    cudaGetSymbolAddress((void**)&AS, g_AS);
    cudaGetSymbolAddress((void**)&AD, g_AD);
    cudaGetSymbolAddress((void**)&AS2, g_AS2);
    cudaGetSymbolAddress((void**)&AD2, g_AD2);
    cudaGetSymbolAddress((void**)&deg, g_deg);
    cudaGetSymbolAddress((void**)&rowptr, g_rowptr);
    cudaGetSymbolAddress((void**)&cur, g_cur);
    cudaGetSymbolAddress((void**)&adj, g_adj);
    cudaGetSymbolAddress((void**)&bsum, g_bsum);
    cudaGetSymbolAddress((void**)&SUMP1, g_SUMP1);
    cudaGetSymbolAddress((void**)&MAXP1, g_MAXP1);
    cudaGetSymbolAddress((void**)&CNT1, g_CNT1);
    cudaGetSymbolAddress((void**)&SUMP2, g_SUMP2);
    cudaGetSymbolAddress((void**)&MAXP2, g_MAXP2);
    cudaGetSymbolAddress((void**)&CNT2, g_CNT2);
    cudaGetSymbolAddress((void**)&X1, g_X1);
    cudaGetSymbolAddress((void**)&X2, g_X2);

    int nScanBlocks = (N + 2047) / 2048;
    int nyH = (N + 127) / 128;
    dim3 gH(2, nyH);       // big GEMMs (BN=128, N=256)
    dim3 gH2(3, nyH);      // GEMM2 + fused pool_acc side slice
    dim3 gL(1, nyH);       // lin GEMMs (BN=64)

    // 0-2: prep; 3 = GEMM1 (ncu profiles launch idx 3)
    init_all_kernel<<<(N * 4 + 255) / 256, 256>>>(deg, cur, AS, AD, AS2, AD2,
                                                  SUMP1, MAXP1, CNT1, SUMP2, MAXP2, CNT2, N);
    deg_count_kernel<<<(E + 255) / 256, 256>>>(ei, deg, E);
    scan1_kernel<<<nScanBlocks, 256>>>(deg, rowptr, bsum, N);

    // 3: GEMM1 -> H (fp16) + attention dots
    f16_gemm_kernel<128, 2, 4, 2, 0><<<gH, 256>>>(
        x, gat1_w, nullptr, H, gat1_as, gat1_ad, AS, AD,
        nullptr, nullptr, nullptr, nullptr, nullptr, N, 256, K1, 0);

    // 4-5: finish CSR
    scan23_kernel<<<nScanBlocks, 256>>>(rowptr, bsum, N, ET);
    fill_kernel<<<(ET + 255) / 256, 256>>>(ei, rowptr, cur, adj, E, ET);

    // 6: layer-1 aggregate (fp16 H reads)
    gat_gather_kernel<<<(N * 32 + 255) / 256, 256>>>(rowptr, adj, H, AS, AD, gat1_b, OUT, N);
    // 7: lin1 + selu
    f16_gemm_kernel<64, 4, 2, 1, 0><<<gL, 256>>>(
        OUT, lin1_w, lin1_b, H1, nullptr, nullptr, nullptr, nullptr,
        nullptr, nullptr, nullptr, nullptr, nullptr, N, 64, 256, 0);

    // 8: GEMM2 -> H (fp16) + att dots, with fused pool_acc(H1) side slice
    f16_gemm_kernel<128, 2, 4, 2, 2><<<gH2, 256>>>(
        H1, gat2_w, nullptr, H, gat2_as, gat2_ad, AS2, AD2,
        H1, batch, SUMP1, MAXP1, CNT1, N, 256, 64, 0);
    // 9: finish pool1 -> X1
    pool_fin_kernel<<<(GMAX * 64 + 255) / 256, 256>>>(SUMP1, MAXP1, CNT1, X1);

    // 10: layer-2 aggregate
    gat_gather_kernel<<<(N * 32 + 255) / 256, 256>>>(rowptr, adj, H, AS2, AD2, gat2_b, OUT, N);
    // 11: lin2 + selu
    f16_gemm_kernel<64, 4, 2, 1, 0><<<gL, 256>>>(
        OUT, lin2_w, lin2_b, H2, nullptr, nullptr, nullptr, nullptr,
        nullptr, nullptr, nullptr, nullptr, nullptr, N, 64, 256, 0);

    // 12-13: pool2 -> X2
    pool_acc_kernel<<<nyH, 256>>>(H2, batch, SUMP2, MAXP2, CNT2, N);
    pool_fin_kernel<<<(GMAX * 64 + 255) / 256, 256>>>(SUMP2, MAXP2, CNT2, X2);

    // 14: head MLP
    mlp_kernel<<<GMAX, 128>>>(X1, X2, sum_w, sum_b, sh1_w, sh1_b, sh2_w, sh2_b,
                              sh3_w, sh3_b, reg_w, reg_b, (float*)d_out);
}

// round 9
// speedup vs baseline: 1.2728x; 1.0962x over previous
#include <cuda_runtime.h>
#include <cuda_fp16.h>
#include <math.h>

#define NMAX 100000
#define EMAX 800000
#define ETMAX (NMAX + EMAX)
#define GMAX 128

// ---------------- device scratch ----------------
__device__ __half g_H[NMAX * 256];     // GAT hidden h, fp16
__device__ __half g_OUT[NMAX * 256];   // GAT aggregation output, fp16
__device__ float g_H1[NMAX * 64];
__device__ float g_H2[NMAX * 64];
__device__ float g_AS[NMAX * 4];
__device__ float g_AD[NMAX * 4];
__device__ float g_AS2[NMAX * 4];
__device__ float g_AD2[NMAX * 4];
__device__ int   g_deg[NMAX];
__device__ int   g_rowptr[NMAX + 1];
__device__ int   g_cur[NMAX];
__device__ int   g_adj[ETMAX];
__device__ int   g_bsum[256];
__device__ float g_SUMP1[GMAX * 64];
__device__ int   g_MAXP1[GMAX * 64];
__device__ int   g_CNT1[GMAX];
__device__ float g_SUMP2[GMAX * 64];
__device__ int   g_MAXP2[GMAX * 64];
__device__ int   g_CNT2[GMAX];
__device__ float g_X1[GMAX * 128];
__device__ float g_X2[GMAX * 128];

// ---------------- helpers ----------------
__device__ __forceinline__ int fmap(float f) {
    int i = __float_as_int(f);
    return i >= 0 ? i : (i ^ 0x7FFFFFFF);
}
__device__ __forceinline__ float funmap(int i) {
    return __int_as_float(i >= 0 ? i : (i ^ 0x7FFFFFFF));
}
__device__ __forceinline__ float selu_f(float x) {
    const float a = 1.6732632423543772f, s = 1.0507009873554805f;
    return x > 0.f ? s * x : s * a * (expf(x) - 1.f);
}
__device__ __forceinline__ void mma_f16(float& c0, float& c1, float& c2, float& c3,
                                        unsigned a0, unsigned a1, unsigned a2, unsigned a3,
                                        unsigned b0, unsigned b1) {
    asm volatile(
        "mma.sync.aligned.m16n8k16.row.col.f32.f16.f16.f32 "
        "{%0,%1,%2,%3}, {%4,%5,%6,%7}, {%8,%9}, {%0,%1,%2,%3};"
        : "+f"(c0), "+f"(c1), "+f"(c2), "+f"(c3)
        : "r"(a0), "r"(a1), "r"(a2), "r"(a3), "r"(b0), "r"(b1));
}

// =================== one-shot init ===================
__global__ void init_all_kernel(int* __restrict__ deg, int* __restrict__ cur,
                                float* __restrict__ AS, float* __restrict__ AD,
                                float* __restrict__ AS2, float* __restrict__ AD2,
                                float* __restrict__ SUMP1, int* __restrict__ MAXP1,
                                int* __restrict__ CNT1,
                                float* __restrict__ SUMP2, int* __restrict__ MAXP2,
                                int* __restrict__ CNT2, int N) {
    int i = blockIdx.x * blockDim.x + threadIdx.x;
    if (i < N) { deg[i] = 1; cur[i] = 0; }
    if (i < N * 4) { AS[i] = 0.f; AD[i] = 0.f; AS2[i] = 0.f; AD2[i] = 0.f; }
    if (i < GMAX * 64) {
        SUMP1[i] = 0.f; MAXP1[i] = fmap(-INFINITY);
        SUMP2[i] = 0.f; MAXP2[i] = fmap(-INFINITY);
    }
    if (i < GMAX) { CNT1[i] = 0; CNT2[i] = 0; }
}

// =================== CSR build ===================
__global__ void deg_count_kernel(const int* __restrict__ ei, int* __restrict__ deg, int E) {
    int e = blockIdx.x * blockDim.x + threadIdx.x;
    if (e < E) atomicAdd(&deg[ei[E + e]], 1);
}
__global__ void scan1_kernel(const int* __restrict__ deg, int* __restrict__ rowptr,
                             int* __restrict__ bsum, int N) {
    __shared__ int sh[256];
    int tid = threadIdx.x;
    int base = blockIdx.x * 2048 + tid * 8;
    int v[8], pre[8];
    int sum = 0;
    #pragma unroll
    for (int j = 0; j < 8; j++) {
        v[j] = (base + j < N) ? deg[base + j] : 0;
        pre[j] = sum;
        sum += v[j];
    }
    sh[tid] = sum;
    __syncthreads();
    for (int off = 1; off < 256; off <<= 1) {
        int t = (tid >= off) ? sh[tid - off] : 0;
        __syncthreads();
        sh[tid] += t;
        __syncthreads();
    }
    int texcl = sh[tid] - sum;
    #pragma unroll
    for (int j = 0; j < 8; j++)
        if (base + j < N) rowptr[base + j] = texcl + pre[j];
    if (tid == 255) bsum[blockIdx.x] = sh[255];
}
__global__ void scan23_kernel(int* __restrict__ rowptr, const int* __restrict__ bsum,
                              int N, int ET) {
    __shared__ int s_add;
    int tid = threadIdx.x;
    if (tid < 32) {
        int s = 0;
        for (int j = tid; j < blockIdx.x; j += 32) s += bsum[j];
        #pragma unroll
        for (int off = 16; off; off >>= 1) s += __shfl_down_sync(0xFFFFFFFFu, s, off);
        if (tid == 0) s_add = s;
    }
    __syncthreads();
    int add = s_add;
    int base = blockIdx.x * 2048 + tid * 8;
    #pragma unroll
    for (int j = 0; j < 8; j++)
        if (base + j < N) rowptr[base + j] += add;
    if (blockIdx.x == 0 && tid == 0) rowptr[N] = ET;
}
__global__ void fill_kernel(const int* __restrict__ ei, const int* __restrict__ rowptr,
                            int* __restrict__ cur, int* __restrict__ adj, int E, int ET) {
    int idx = blockIdx.x * blockDim.x + threadIdx.x;
    if (idx >= ET) return;
    int src, dst;
    if (idx < E) { src = ei[idx]; dst = ei[E + idx]; }
    else         { src = dst = idx - E; }
    adj[rowptr[dst] + atomicAdd(&cur[dst], 1)] = src;
}

// =================== fp16 m16n8k16 GEMM, fp32 accum, double-buffered ===================
// C[MxN] = A[MxK] @ B[KxN].  BM=128, BK=16, 256 threads, ONE sync per K-tile.
// AHALF: 0 = A fp32 (cvt on store), 1 = A already fp16 (direct restage)
// EPI: 0 = plain fp32, 1 = bias+selu fp32, 2 = fp16 store + fused attention dots
// SIDE: 0 = none; 2 = last-grid.x blocks do pool_acc
template <int BN, int WARPS_M, int WARPS_N, int EPI, int SIDE, int AHALF>
__global__ void __launch_bounds__(256)
f16_gemm_kernel(const void* __restrict__ Av, const float* __restrict__ B,
                const float* __restrict__ bias, void* __restrict__ Cv,
                const float* __restrict__ a_src, const float* __restrict__ a_dst,
                float* __restrict__ AS, float* __restrict__ AD,
                const void* sp0, const void* sp1, void* sp2, void* sp3, void* sp4,
                int M, int N, int K, int sE) {
    if (SIDE == 2 && blockIdx.x == gridDim.x - 1) {
        const float* Hx = (const float*)sp0;
        const int* batch = (const int*)sp1;
        float* SUMP = (float*)sp2;
        int* MAXP = (int*)sp3;
        int* CNT = (int*)sp4;
        int c = threadIdx.x & 63;
        int r = blockIdx.y * 128 + (threadIdx.x >> 6);
        int rend = blockIdx.y * 128 + 128;
        if (rend > M) rend = M;
        float sum = 0.f, mx = -INFINITY;
        int cnt = 0, curg = -1;
        for (; r < rend; r += 4) {
            int g = batch[r];
            float v = Hx[(size_t)r * 64 + c];
            if (g != curg) {
                if (curg >= 0) {
                    atomicAdd(&SUMP[curg * 64 + c], sum);
                    atomicMax(&MAXP[curg * 64 + c], fmap(mx));
                    if (c == 0) atomicAdd(&CNT[curg], cnt);
                }
                curg = g; sum = 0.f; mx = -INFINITY; cnt = 0;
            }
            sum += v;
            mx = fmaxf(mx, v);
            cnt++;
        }
        if (curg >= 0) {
            atomicAdd(&SUMP[curg * 64 + c], sum);
            atomicMax(&MAXP[curg * 64 + c], fmap(mx));
            if (c == 0) atomicAdd(&CNT[curg], cnt);
        }
        return;
    }

    const int WM = 128 / WARPS_M, WN = BN / WARPS_N;
    const int MT = WM / 16, NT = WN / 8;
    const int ASTR = 24;                        // halves per A row (16 + 8 pad)
    __shared__ __half  Asm[2][128][ASTR];       // [buf][m][k] fp16
    __shared__ __half2 Bs2[2][8][BN + 8];       // [buf][k/2][n]

    int tid = threadIdx.x;
    int warp = tid >> 5, lane = tid & 31;
    int lr = lane >> 2, lc = lane & 3;
    int warp_m = warp / WARPS_N, warp_n = warp % WARPS_N;
    int wm0 = warp_m * WM, wn0 = warp_n * WN;
    int m0 = blockIdx.y * 128, n0 = blockIdx.x * BN;

    float c[MT][NT][4];
    #pragma unroll
    for (int i = 0; i < MT; i++)
        #pragma unroll
        for (int j = 0; j < NT; j++)
            #pragma unroll
            for (int q = 0; q < 4; q++) c[i][j][q] = 0.f;

    const float* Af = (const float*)Av;
    const __half* Ah = (const __half*)Av;
    float4 areg[2];
    uint4 ahreg;
    float4 bga, bgb;
    const int BTASK = 8 * (BN / 4);
    int bk2 = tid / (BN / 4);
    int bnc = (tid % (BN / 4)) * 4;

    auto ldA = [&](int k0) {
        if (AHALF) {
            int gm = m0 + (tid >> 1), gk = k0 + (tid & 1) * 8;
            uint4 z = {0u, 0u, 0u, 0u};
            ahreg = (gm < M && gk < K) ? *(const uint4*)&Ah[(size_t)gm * K + gk] : z;
        } else {
            #pragma unroll
            for (int q = 0; q < 2; q++) {
                int f = tid + q * 256;
                int r = f >> 2, cc = (f & 3) * 4;
                int gm = m0 + r, gk = k0 + cc;
                float4 v = {0.f, 0.f, 0.f, 0.f};
                if (gm < M && gk < K) v = *(const float4*)&Af[(size_t)gm * K + gk];
                areg[q] = v;
            }
        }
    };
    auto stA = [&](int buf) {
        if (AHALF) {
            int r = tid >> 1, cc = (tid & 1) * 8;
            *(__half2*)&Asm[buf][r][cc + 0] = *(const __half2*)&ahreg.x;
            *(__half2*)&Asm[buf][r][cc + 2] = *(const __half2*)&ahreg.y;
            *(__half2*)&Asm[buf][r][cc + 4] = *(const __half2*)&ahreg.z;
            *(__half2*)&Asm[buf][r][cc + 6] = *(const __half2*)&ahreg.w;
        } else {
            #pragma unroll
            for (int q = 0; q < 2; q++) {
                int f = tid + q * 256;
                int r = f >> 2, cc = (f & 3) * 4;
                *(__half2*)&Asm[buf][r][cc]     = __floats2half2_rn(areg[q].x, areg[q].y);
                *(__half2*)&Asm[buf][r][cc + 2] = __floats2half2_rn(areg[q].z, areg[q].w);
            }
        }
    };
    auto ldB = [&](int k0) {
        if (tid < BTASK) {
            int gk0 = k0 + 2 * bk2, gk1 = gk0 + 1;
            float4 z = {0.f, 0.f, 0.f, 0.f};
            bga = (gk0 < K) ? *(const float4*)&B[(size_t)gk0 * N + n0 + bnc] : z;
            bgb = (gk1 < K) ? *(const float4*)&B[(size_t)gk1 * N + n0 + bnc] : z;
        }
    };
    auto stB = [&](int buf) {
        if (tid < BTASK) {
            Bs2[buf][bk2][bnc + 0] = __floats2half2_rn(bga.x, bgb.x);
            Bs2[buf][bk2][bnc + 1] = __floats2half2_rn(bga.y, bgb.y);
            Bs2[buf][bk2][bnc + 2] = __floats2half2_rn(bga.z, bgb.z);
            Bs2[buf][bk2][bnc + 3] = __floats2half2_rn(bga.w, bgb.w);
        }
    };

    int nk = (K + 15) / 16;
    ldA(0);
    ldB(0);
    for (int t = 0; t < nk; t++) {
        int buf = t & 1;
        stA(buf);
        stB(buf);
        __syncthreads();      // single barrier per tile (2-stage pipeline)
        if (t + 1 < nk) { ldA((t + 1) * 16); ldB((t + 1) * 16); }

        unsigned af[MT][4];
        #pragma unroll
        for (int mt = 0; mt < MT; mt++) {
            int row = wm0 + mt * 16 + lr;
            af[mt][0] = *(const unsigned*)&Asm[buf][row][2 * lc];
            af[mt][1] = *(const unsigned*)&Asm[buf][row + 8][2 * lc];
            af[mt][2] = *(const unsigned*)&Asm[buf][row][2 * lc + 8];
            af[mt][3] = *(const unsigned*)&Asm[buf][row + 8][2 * lc + 8];
        }
        unsigned bf[NT][2];
        #pragma unroll
        for (int nt = 0; nt < NT; nt++) {
            int n = wn0 + nt * 8 + lr;
            bf[nt][0] = *(const unsigned*)&Bs2[buf][lc][n];
            bf[nt][1] = *(const unsigned*)&Bs2[buf][lc + 4][n];
        }
        #pragma unroll
        for (int mt = 0; mt < MT; mt++)
            #pragma unroll
            for (int nt = 0; nt < NT; nt++)
                mma_f16(c[mt][nt][0], c[mt][nt][1], c[mt][nt][2], c[mt][nt][3],
                        af[mt][0], af[mt][1], af[mt][2], af[mt][3],
                        bf[nt][0], bf[nt][1]);
    }

    // ---- epilogue ----
    float asv[NT][2], adv[NT][2];
    if (EPI == 2) {
        #pragma unroll
        for (int nt = 0; nt < NT; nt++) {
            int gc = n0 + wn0 + nt * 8 + lc * 2;
            asv[nt][0] = a_src[gc]; asv[nt][1] = a_src[gc + 1];
            adv[nt][0] = a_dst[gc]; adv[nt][1] = a_dst[gc + 1];
        }
    }
    float* Cf = (float*)Cv;
    __half* Ch = (__half*)Cv;
    #pragma unroll
    for (int mt = 0; mt < MT; mt++) {
        int r0 = m0 + wm0 + mt * 16 + lr;
        int r1 = r0 + 8;
        float s0 = 0.f, s1 = 0.f, d0 = 0.f, d1 = 0.f;
        #pragma unroll
        for (int nt = 0; nt < NT; nt++) {
            int gc = n0 + wn0 + nt * 8 + lc * 2;
            float v0 = c[mt][nt][0], v1 = c[mt][nt][1];
            float v2 = c[mt][nt][2], v3 = c[mt][nt][3];
            if (EPI == 1) {
                float b0 = bias[gc], b1 = bias[gc + 1];
                v0 = selu_f(v0 + b0); v1 = selu_f(v1 + b1);
                v2 = selu_f(v2 + b0); v3 = selu_f(v3 + b1);
            }
            if (EPI == 2) {
                s0 += v0 * asv[nt][0] + v1 * asv[nt][1];
                s1 += v2 * asv[nt][0] + v3 * asv[nt][1];
                d0 += v0 * adv[nt][0] + v1 * adv[nt][1];
                d1 += v2 * adv[nt][0] + v3 * adv[nt][1];
                if (r0 < M) *(__half2*)&Ch[(size_t)r0 * N + gc] = __floats2half2_rn(v0, v1);
                if (r1 < M) *(__half2*)&Ch[(size_t)r1 * N + gc] = __floats2half2_rn(v2, v3);
            } else {
                if (r0 < M) *(float2*)&Cf[(size_t)r0 * N + gc] = make_float2(v0, v1);
                if (r1 < M) *(float2*)&Cf[(size_t)r1 * N + gc] = make_float2(v2, v3);
            }
        }
        if (EPI == 2) {
            s0 += __shfl_xor_sync(0xFFFFFFFFu, s0, 1);
            s0 += __shfl_xor_sync(0xFFFFFFFFu, s0, 2);
            s1 += __shfl_xor_sync(0xFFFFFFFFu, s1, 1);
            s1 += __shfl_xor_sync(0xFFFFFFFFu, s1, 2);
            d0 += __shfl_xor_sync(0xFFFFFFFFu, d0, 1);
            d0 += __shfl_xor_sync(0xFFFFFFFFu, d0, 2);
            d1 += __shfl_xor_sync(0xFFFFFFFFu, d1, 1);
            d1 += __shfl_xor_sync(0xFFFFFFFFu, d1, 2);
            if (lc == 0) {
                int h = (n0 + wn0) >> 6;
                if (r0 < M) { atomicAdd(&AS[r0 * 4 + h], s0); atomicAdd(&AD[r0 * 4 + h], d0); }
                if (r1 < M) { atomicAdd(&AS[r1 * 4 + h], s1); atomicAdd(&AD[r1 * 4 + h], d1); }
            }
        }
    }
}

// =================== GAT gather: warp per dst, fp16 H, fp16 OUT ===================
__device__ __forceinline__ void ons_update(float e, const float* v,
                                           float& m, float& s, float* acc) {
    if (e <= m) {
        float w = expf(e - m);
        s += w;
        #pragma unroll
        for (int q = 0; q < 8; q++) acc[q] += w * v[q];
    } else {
        float sc = expf(m - e);   // first iter: exp(-inf)=0
        s = s * sc + 1.f;
        #pragma unroll
        for (int q = 0; q < 8; q++) acc[q] = acc[q] * sc + v[q];
        m = e;
    }
}
__device__ __forceinline__ void unpack8(uint4 u, float* v) {
    __half2* hh = (__half2*)&u;
    #pragma unroll
    for (int q = 0; q < 4; q++) {
        float2 f = __half22float2(hh[q]);
        v[q * 2] = f.x; v[q * 2 + 1] = f.y;
    }
}

__global__ void gat_gather_kernel(const int* __restrict__ rowptr, const int* __restrict__ adj,
                                  const __half* __restrict__ H, const float* __restrict__ AS,
                                  const float* __restrict__ AD, const float* __restrict__ gb,
                                  __half* __restrict__ OUT, int N) {
    int gw = (blockIdx.x * blockDim.x + threadIdx.x) >> 5;
    int lane = threadIdx.x & 31;
    if (gw >= N) return;
    int dst = gw;
    int h = lane >> 3;
    float adh = AD[dst * 4 + h];
    int beg = rowptr[dst], end = rowptr[dst + 1];
    float acc[8] = {};
    float m = -INFINITY, s = 0.f;
    int i = beg;
    for (; i + 2 <= end; i += 2) {
        int s0 = adj[i], s1 = adj[i + 1];
        float e0 = AS[s0 * 4 + h] + adh;
        float e1 = AS[s1 * 4 + h] + adh;
        uint4 u0 = *((const uint4*)(H + (size_t)s0 * 256) + lane);
        uint4 u1 = *((const uint4*)(H + (size_t)s1 * 256) + lane);
        float v0[8], v1[8];
        unpack8(u0, v0);
        unpack8(u1, v1);
        e0 = e0 > 0.f ? e0 : 0.2f * e0;
        e1 = e1 > 0.f ? e1 : 0.2f * e1;
        ons_update(e0, v0, m, s, acc);
        ons_update(e1, v1, m, s, acc);
    }
    if (i < end) {
        int s0 = adj[i];
        float e0 = AS[s0 * 4 + h] + adh;
        uint4 u0 = *((const uint4*)(H + (size_t)s0 * 256) + lane);
        float v0[8];
        unpack8(u0, v0);
        e0 = e0 > 0.f ? e0 : 0.2f * e0;
        ons_update(e0, v0, m, s, acc);
    }
    float inv = 1.f / (s + 1e-16f);
    const float* gbp = gb + lane * 8;
    uint4 o;
    __half2* oh = (__half2*)&o;
    #pragma unroll
    for (int q = 0; q < 4; q++)
        oh[q] = __floats2half2_rn(acc[2 * q] * inv + gbp[2 * q],
                                  acc[2 * q + 1] * inv + gbp[2 * q + 1]);
    *((uint4*)(OUT + (size_t)dst * 256) + lane) = o;
}

// =================== standalone pool pieces ===================
__global__ void pool_acc_kernel(const float* __restrict__ Hx, const int* __restrict__ batch,
                                float* __restrict__ SUMP, int* __restrict__ MAXP,
                                int* __restrict__ CNT, int N) {
    int c = threadIdx.x & 63;
    int r = blockIdx.x * 128 + (threadIdx.x >> 6);
    int rend = blockIdx.x * 128 + 128;
    if (rend > N) rend = N;
    float sum = 0.f, mx = -INFINITY;
    int cnt = 0, curg = -1;
    for (; r < rend; r += 4) {
        int g = batch[r];
        float v = Hx[(size_t)r * 64 + c];
        if (g != curg) {
            if (curg >= 0) {
                atomicAdd(&SUMP[curg * 64 + c], sum);
                atomicMax(&MAXP[curg * 64 + c], fmap(mx));
                if (c == 0) atomicAdd(&CNT[curg], cnt);
            }
            curg = g; sum = 0.f; mx = -INFINITY; cnt = 0;
        }
        sum += v;
        mx = fmaxf(mx, v);
        cnt++;
    }
    if (curg >= 0) {
        atomicAdd(&SUMP[curg * 64 + c], sum);
        atomicMax(&MAXP[curg * 64 + c], fmap(mx));
        if (c == 0) atomicAdd(&CNT[curg], cnt);
    }
}
__global__ void pool_fin_kernel(const float* __restrict__ SUMP, const int* __restrict__ MAXP,
                                const int* __restrict__ CNT, float* __restrict__ X) {
    int i = blockIdx.x * blockDim.x + threadIdx.x;
    if (i >= GMAX * 64) return;
    int g = i >> 6, c = i & 63;
    float cnt = (float)CNT[g];
    if (cnt < 1.f) cnt = 1.f;
    X[g * 128 + c] = SUMP[i] / cnt;
    X[g * 128 + 64 + c] = funmap(MAXP[i]);
}

// =================== final MLP head ===================
__global__ void mlp_kernel(const float* __restrict__ X1, const float* __restrict__ X2,
                           const float* __restrict__ sum_w, const float* __restrict__ sum_b,
                           const float* __restrict__ sh1_w, const float* __restrict__ sh1_b,
                           const float* __restrict__ sh2_w, const float* __restrict__ sh2_b,
                           const float* __restrict__ sh3_w, const float* __restrict__ sh3_b,
                           const float* __restrict__ reg_w, const float* __restrict__ reg_b,
                           float* __restrict__ out) {
    __shared__ float zin[256], z1[128], z2[64], z3[64];
    int g = blockIdx.x, t = threadIdx.x;
    zin[t] = X1[g * 128 + t];
    zin[128 + t] = X2[g * 128 + t];
    __syncthreads();
    {
        float acc = sum_b[t];
        for (int k = 0; k < 256; k++) acc += zin[k] * sum_w[k * 128 + t];
        z1[t] = acc;
    }
    __syncthreads();
    if (t < 64) {
        float acc = sh1_b[t];
        for (int k = 0; k < 128; k++) acc += z1[k] * sh1_w[k * 64 + t];
        z2[t] = selu_f(acc);
    }
    __syncthreads();
    if (t < 64) {
        float acc = sh2_b[t];
        for (int k = 0; k < 64; k++) acc += z2[k] * sh2_w[k * 64 + t];
        z3[t] = selu_f(acc);
    }
    __syncthreads();
    if (t < 64) {
        float acc = sh3_b[t];
        for (int k = 0; k < 64; k++) acc += z3[k] * sh3_w[k * 64 + t];
        z2[t] = selu_f(acc);
    }
    __syncthreads();
    if (t < 32) {
        float acc = reg_b[t];
        for (int k = 0; k < 64; k++) acc += z2[k] * reg_w[k * 32 + t];
        out[g * 32 + t] = acc;
    }
}

// =================== host orchestration ===================
extern "C" void kernel_launch(void* const* d_in, const int* in_sizes, int n_in,
                              void* d_out, int out_size) {
    const float* x       = (const float*)d_in[0];
    const int*   ei      = (const int*)d_in[1];
    const int*   batch   = (const int*)d_in[2];
    const float* gat1_w  = (const float*)d_in[3];
    const float* gat1_as = (const float*)d_in[4];
    const float* gat1_ad = (const float*)d_in[5];
    const float* gat1_b  = (const float*)d_in[6];
    const float* lin1_w  = (const float*)d_in[7];
    const float* lin1_b  = (const float*)d_in[8];
    const float* gat2_w  = (const float*)d_in[9];
    const float* gat2_as = (const float*)d_in[10];
    const float* gat2_ad = (const float*)d_in[11];
    const float* gat2_b  = (const float*)d_in[12];
    const float* lin2_w  = (const float*)d_in[13];
    const float* lin2_b  = (const float*)d_in[14];
    const float* sum_w   = (const float*)d_in[15];
    const float* sum_b   = (const float*)d_in[16];
    const float* sh1_w   = (const float*)d_in[17];
    const float* sh1_b   = (const float*)d_in[18];
    const float* sh2_w   = (const float*)d_in[19];
    const float* sh2_b   = (const float*)d_in[20];
    const float* sh3_w   = (const float*)d_in[21];
    const float* sh3_b   = (const float*)d_in[22];
    const float* reg_w   = (const float*)d_in[23];
    const float* reg_b   = (const float*)d_in[24];

    int N  = in_sizes[2];
    int E  = in_sizes[1] / 2;
    int K1 = in_sizes[0] / N;
    int ET = E + N;

    __half *H, *OUT;
    float *H1, *H2, *AS, *AD, *AS2, *AD2, *SUMP1, *SUMP2, *X1, *X2;
    int *deg, *rowptr, *cur, *adj, *bsum, *MAXP1, *CNT1, *MAXP2, *CNT2;
    cudaGetSymbolAddress((void**)&H, g_H);
    cudaGetSymbolAddress((void**)&OUT, g_OUT);
    cudaGetSymbolAddress((void**)&H1, g_H1);
    cudaGetSymbolAddress((void**)&H2, g_H2);
    cudaGetSymbolAddress((void**)&AS, g_AS);
    cudaGetSymbolAddress((void**)&AD, g_AD);
    cudaGetSymbolAddress((void**)&AS2, g_AS2);
    cudaGetSymbolAddress((void**)&AD2, g_AD2);
    cudaGetSymbolAddress((void**)&deg, g_deg);
    cudaGetSymbolAddress((void**)&rowptr, g_rowptr);
    cudaGetSymbolAddress((void**)&cur, g_cur);
    cudaGetSymbolAddress((void**)&adj, g_adj);
    cudaGetSymbolAddress((void**)&bsum, g_bsum);
    cudaGetSymbolAddress((void**)&SUMP1, g_SUMP1);
    cudaGetSymbolAddress((void**)&MAXP1, g_MAXP1);
    cudaGetSymbolAddress((void**)&CNT1, g_CNT1);
    cudaGetSymbolAddress((void**)&SUMP2, g_SUMP2);
    cudaGetSymbolAddress((void**)&MAXP2, g_MAXP2);
    cudaGetSymbolAddress((void**)&CNT2, g_CNT2);
    cudaGetSymbolAddress((void**)&X1, g_X1);
    cudaGetSymbolAddress((void**)&X2, g_X2);

    int nScanBlocks = (N + 2047) / 2048;
    int nyH = (N + 127) / 128;
    dim3 gH(2, nyH);       // big GEMMs (BN=128, N=256)
    dim3 gH2(3, nyH);      // GEMM2 + fused pool_acc side slice
    dim3 gL(1, nyH);       // lin GEMMs (BN=64)

    // 0-2: prep; 3 = GEMM1 (ncu profiles launch idx 3)
    init_all_kernel<<<(N * 4 + 255) / 256, 256>>>(deg, cur, AS, AD, AS2, AD2,
                                                  SUMP1, MAXP1, CNT1, SUMP2, MAXP2, CNT2, N);
    deg_count_kernel<<<(E + 255) / 256, 256>>>(ei, deg, E);
    scan1_kernel<<<nScanBlocks, 256>>>(deg, rowptr, bsum, N);

    // 3: GEMM1 (A fp32) -> H fp16 + attention dots
    f16_gemm_kernel<128, 2, 4, 2, 0, 0><<<gH, 256>>>(
        x, gat1_w, nullptr, H, gat1_as, gat1_ad, AS, AD,
        nullptr, nullptr, nullptr, nullptr, nullptr, N, 256, K1, 0);

    // 4-5: finish CSR
    scan23_kernel<<<nScanBlocks, 256>>>(rowptr, bsum, N, ET);
    fill_kernel<<<(ET + 255) / 256, 256>>>(ei, rowptr, cur, adj, E, ET);

    // 6: layer-1 aggregate -> OUT fp16
    gat_gather_kernel<<<(N * 32 + 255) / 256, 256>>>(rowptr, adj, H, AS, AD, gat1_b, OUT, N);
    // 7: lin1 + selu (A fp16)
    f16_gemm_kernel<64, 4, 2, 1, 0, 1><<<gL, 256>>>(
        OUT, lin1_w, lin1_b, H1, nullptr, nullptr, nullptr, nullptr,
        nullptr, nullptr, nullptr, nullptr, nullptr, N, 64, 256, 0);

    // 8: GEMM2 (A fp32 H1) -> H fp16 + att dots, fused pool_acc(H1) side slice
    f16_gemm_kernel<128, 2, 4, 2, 2, 0><<<gH2, 256>>>(
        H1, gat2_w, nullptr, H, gat2_as, gat2_ad, AS2, AD2,
        H1, batch, SUMP1, MAXP1, CNT1, N, 256, 64, 0);
    // 9: finish pool1 -> X1
    pool_fin_kernel<<<(GMAX * 64 + 255) / 256, 256>>>(SUMP1, MAXP1, CNT1, X1);

    // 10: layer-2 aggregate -> OUT fp16
    gat_gather_kernel<<<(N * 32 + 255) / 256, 256>>>(rowptr, adj, H, AS2, AD2, gat2_b, OUT, N);
    // 11: lin2 + selu (A fp16)
    f16_gemm_kernel<64, 4, 2, 1, 0, 1><<<gL, 256>>>(
        OUT, lin2_w, lin2_b, H2, nullptr, nullptr, nullptr, nullptr,
        nullptr, nullptr, nullptr, nullptr, nullptr, N, 64, 256, 0);

    // 12-13: pool2 -> X2
    pool_acc_kernel<<<nyH, 256>>>(H2, batch, SUMP2, MAXP2, CNT2, N);
    pool_fin_kernel<<<(GMAX * 64 + 255) / 256, 256>>>(SUMP2, MAXP2, CNT2, X2);

    // 14: head MLP
    mlp_kernel<<<GMAX, 128>>>(X1, X2, sum_w, sum_b, sh1_w, sh1_b, sh2_w, sh2_b,
                              sh3_w, sh3_b, reg_w, reg_b, (float*)d_out);
}

// round 10
// speedup vs baseline: 1.2944x; 1.0170x over previous
#include <cuda_runtime.h>
#include <cuda_fp16.h>
#include <math.h>

#define NMAX 100000
#define EMAX 800000
#define ETMAX (NMAX + EMAX)
#define GMAX 128

// ---------------- device scratch ----------------
__device__ __half g_H[NMAX * 256];     // GAT hidden h, fp16
__device__ __half g_OUT[NMAX * 256];   // GAT aggregation output, fp16
__device__ __half g_H1[NMAX * 64];     // after lin1+selu, fp16
__device__ __half g_H2[NMAX * 64];     // after lin2+selu, fp16
__device__ float g_AS[NMAX * 4];
__device__ float g_AD[NMAX * 4];
__device__ float g_AS2[NMAX * 4];
__device__ float g_AD2[NMAX * 4];
__device__ int   g_deg[NMAX];
__device__ int   g_rowptr[NMAX + 1];
__device__ int   g_cur[NMAX];
__device__ int   g_adj[ETMAX];
__device__ int   g_bsum[256];
__device__ float g_SUMP1[GMAX * 64];
__device__ int   g_MAXP1[GMAX * 64];
__device__ int   g_CNT1[GMAX];
__device__ float g_SUMP2[GMAX * 64];
__device__ int   g_MAXP2[GMAX * 64];
__device__ int   g_CNT2[GMAX];
__device__ float g_X1[GMAX * 128];
__device__ float g_X2[GMAX * 128];

// ---------------- helpers ----------------
__device__ __forceinline__ int fmap(float f) {
    int i = __float_as_int(f);
    return i >= 0 ? i : (i ^ 0x7FFFFFFF);
}
__device__ __forceinline__ float funmap(int i) {
    return __int_as_float(i >= 0 ? i : (i ^ 0x7FFFFFFF));
}
__device__ __forceinline__ float selu_f(float x) {
    const float a = 1.6732632423543772f, s = 1.0507009873554805f;
    return x > 0.f ? s * x : s * a * (expf(x) - 1.f);
}
__device__ __forceinline__ void mma_f16(float& c0, float& c1, float& c2, float& c3,
                                        unsigned a0, unsigned a1, unsigned a2, unsigned a3,
                                        unsigned b0, unsigned b1) {
    asm volatile(
        "mma.sync.aligned.m16n8k16.row.col.f32.f16.f16.f32 "
        "{%0,%1,%2,%3}, {%4,%5,%6,%7}, {%8,%9}, {%0,%1,%2,%3};"
        : "+f"(c0), "+f"(c1), "+f"(c2), "+f"(c3)
        : "r"(a0), "r"(a1), "r"(a2), "r"(a3), "r"(b0), "r"(b1));
}

// =================== one-shot init ===================
__global__ void init_all_kernel(int* __restrict__ deg, int* __restrict__ cur,
                                float* __restrict__ AS, float* __restrict__ AD,
                                float* __restrict__ AS2, float* __restrict__ AD2,
                                float* __restrict__ SUMP1, int* __restrict__ MAXP1,
                                int* __restrict__ CNT1,
                                float* __restrict__ SUMP2, int* __restrict__ MAXP2,
                                int* __restrict__ CNT2, int N) {
    int i = blockIdx.x * blockDim.x + threadIdx.x;
    if (i < N) { deg[i] = 1; cur[i] = 0; }
    if (i < N * 4) { AS[i] = 0.f; AD[i] = 0.f; AS2[i] = 0.f; AD2[i] = 0.f; }
    if (i < GMAX * 64) {
        SUMP1[i] = 0.f; MAXP1[i] = fmap(-INFINITY);
        SUMP2[i] = 0.f; MAXP2[i] = fmap(-INFINITY);
    }
    if (i < GMAX) { CNT1[i] = 0; CNT2[i] = 0; }
}

// =================== CSR build ===================
__global__ void deg_count_kernel(const int* __restrict__ ei, int* __restrict__ deg, int E) {
    int e = blockIdx.x * blockDim.x + threadIdx.x;
    if (e < E) atomicAdd(&deg[ei[E + e]], 1);
}
__global__ void scan1_kernel(const int* __restrict__ deg, int* __restrict__ rowptr,
                             int* __restrict__ bsum, int N) {
    __shared__ int sh[256];
    int tid = threadIdx.x;
    int base = blockIdx.x * 2048 + tid * 8;
    int v[8], pre[8];
    int sum = 0;
    #pragma unroll
    for (int j = 0; j < 8; j++) {
        v[j] = (base + j < N) ? deg[base + j] : 0;
        pre[j] = sum;
        sum += v[j];
    }
    sh[tid] = sum;
    __syncthreads();
    for (int off = 1; off < 256; off <<= 1) {
        int t = (tid >= off) ? sh[tid - off] : 0;
        __syncthreads();
        sh[tid] += t;
        __syncthreads();
    }
    int texcl = sh[tid] - sum;
    #pragma unroll
    for (int j = 0; j < 8; j++)
        if (base + j < N) rowptr[base + j] = texcl + pre[j];
    if (tid == 255) bsum[blockIdx.x] = sh[255];
}
__global__ void scan23_kernel(int* __restrict__ rowptr, const int* __restrict__ bsum,
                              int N, int ET) {
    __shared__ int s_add;
    int tid = threadIdx.x;
    if (tid < 32) {
        int s = 0;
        for (int j = tid; j < blockIdx.x; j += 32) s += bsum[j];
        #pragma unroll
        for (int off = 16; off; off >>= 1) s += __shfl_down_sync(0xFFFFFFFFu, s, off);
        if (tid == 0) s_add = s;
    }
    __syncthreads();
    int add = s_add;
    int base = blockIdx.x * 2048 + tid * 8;
    #pragma unroll
    for (int j = 0; j < 8; j++)
        if (base + j < N) rowptr[base + j] += add;
    if (blockIdx.x == 0 && tid == 0) rowptr[N] = ET;
}
__global__ void fill_kernel(const int* __restrict__ ei, const int* __restrict__ rowptr,
                            int* __restrict__ cur, int* __restrict__ adj, int E, int ET) {
    int idx = blockIdx.x * blockDim.x + threadIdx.x;
    if (idx >= ET) return;
    int src, dst;
    if (idx < E) { src = ei[idx]; dst = ei[E + idx]; }
    else         { src = dst = idx - E; }
    adj[rowptr[dst] + atomicAdd(&cur[dst], 1)] = src;
}

// =================== fp16 m16n8k16 GEMM, fp32 accum, double-buffered ===================
// AHALF: 0 = A fp32 (cvt on store), 1 = A already fp16
// EPI: 0 = plain fp32, 1 = bias+selu fp32, 2 = fp16 store + fused attention dots,
//      3 = bias+selu fp16 store
// SIDE: 0 = none; 2 = last-grid.x blocks do pool_acc (Hx is fp16)
template <int BN, int WARPS_M, int WARPS_N, int EPI, int SIDE, int AHALF>
__global__ void __launch_bounds__(256)
f16_gemm_kernel(const void* __restrict__ Av, const float* __restrict__ B,
                const float* __restrict__ bias, void* __restrict__ Cv,
                const float* __restrict__ a_src, const float* __restrict__ a_dst,
                float* __restrict__ AS, float* __restrict__ AD,
                const void* sp0, const void* sp1, void* sp2, void* sp3, void* sp4,
                int M, int N, int K, int sE) {
    if (SIDE == 2 && blockIdx.x == gridDim.x - 1) {
        const __half* Hx = (const __half*)sp0;
        const int* batch = (const int*)sp1;
        float* SUMP = (float*)sp2;
        int* MAXP = (int*)sp3;
        int* CNT = (int*)sp4;
        int c = threadIdx.x & 63;
        int r = blockIdx.y * 128 + (threadIdx.x >> 6);
        int rend = blockIdx.y * 128 + 128;
        if (rend > M) rend = M;
        float sum = 0.f, mx = -INFINITY;
        int cnt = 0, curg = -1;
        for (; r < rend; r += 4) {
            int g = batch[r];
            float v = __half2float(Hx[(size_t)r * 64 + c]);
            if (g != curg) {
                if (curg >= 0) {
                    atomicAdd(&SUMP[curg * 64 + c], sum);
                    atomicMax(&MAXP[curg * 64 + c], fmap(mx));
                    if (c == 0) atomicAdd(&CNT[curg], cnt);
                }
                curg = g; sum = 0.f; mx = -INFINITY; cnt = 0;
            }
            sum += v;
            mx = fmaxf(mx, v);
            cnt++;
        }
        if (curg >= 0) {
            atomicAdd(&SUMP[curg * 64 + c], sum);
            atomicMax(&MAXP[curg * 64 + c], fmap(mx));
            if (c == 0) atomicAdd(&CNT[curg], cnt);
        }
        return;
    }

    const int WM = 128 / WARPS_M, WN = BN / WARPS_N;
    const int MT = WM / 16, NT = WN / 8;
    const int ASTR = 24;
    __shared__ __half  Asm[2][128][ASTR];
    __shared__ __half2 Bs2[2][8][BN + 8];

    int tid = threadIdx.x;
    int warp = tid >> 5, lane = tid & 31;
    int lr = lane >> 2, lc = lane & 3;
    int warp_m = warp / WARPS_N, warp_n = warp % WARPS_N;
    int wm0 = warp_m * WM, wn0 = warp_n * WN;
    int m0 = blockIdx.y * 128, n0 = blockIdx.x * BN;

    float c[MT][NT][4];
    #pragma unroll
    for (int i = 0; i < MT; i++)
        #pragma unroll
        for (int j = 0; j < NT; j++)
            #pragma unroll
            for (int q = 0; q < 4; q++) c[i][j][q] = 0.f;

    const float* Af = (const float*)Av;
    const __half* Ah = (const __half*)Av;
    float4 areg[2];
    uint4 ahreg;
    float4 bga, bgb;
    const int BTASK = 8 * (BN / 4);
    int bk2 = tid / (BN / 4);
    int bnc = (tid % (BN / 4)) * 4;

    auto ldA = [&](int k0) {
        if (AHALF) {
            int gm = m0 + (tid >> 1), gk = k0 + (tid & 1) * 8;
            uint4 z = {0u, 0u, 0u, 0u};
            ahreg = (gm < M && gk < K) ? *(const uint4*)&Ah[(size_t)gm * K + gk] : z;
        } else {
            #pragma unroll
            for (int q = 0; q < 2; q++) {
                int f = tid + q * 256;
                int r = f >> 2, cc = (f & 3) * 4;
                int gm = m0 + r, gk = k0 + cc;
                float4 v = {0.f, 0.f, 0.f, 0.f};
                if (gm < M && gk < K) v = *(const float4*)&Af[(size_t)gm * K + gk];
                areg[q] = v;
            }
        }
    };
    auto stA = [&](int buf) {
        if (AHALF) {
            int r = tid >> 1, cc = (tid & 1) * 8;
            *(__half2*)&Asm[buf][r][cc + 0] = *(const __half2*)&ahreg.x;
            *(__half2*)&Asm[buf][r][cc + 2] = *(const __half2*)&ahreg.y;
            *(__half2*)&Asm[buf][r][cc + 4] = *(const __half2*)&ahreg.z;
            *(__half2*)&Asm[buf][r][cc + 6] = *(const __half2*)&ahreg.w;
        } else {
            #pragma unroll
            for (int q = 0; q < 2; q++) {
                int f = tid + q * 256;
                int r = f >> 2, cc = (f & 3) * 4;
                *(__half2*)&Asm[buf][r][cc]     = __floats2half2_rn(areg[q].x, areg[q].y);
                *(__half2*)&Asm[buf][r][cc + 2] = __floats2half2_rn(areg[q].z, areg[q].w);
            }
        }
    };
    auto ldB = [&](int k0) {
        if (tid < BTASK) {
            int gk0 = k0 + 2 * bk2, gk1 = gk0 + 1;
            float4 z = {0.f, 0.f, 0.f, 0.f};
            bga = (gk0 < K) ? *(const float4*)&B[(size_t)gk0 * N + n0 + bnc] : z;
            bgb = (gk1 < K) ? *(const float4*)&B[(size_t)gk1 * N + n0 + bnc] : z;
        }
    };
    auto stB = [&](int buf) {
        if (tid < BTASK) {
            Bs2[buf][bk2][bnc + 0] = __floats2half2_rn(bga.x, bgb.x);
            Bs2[buf][bk2][bnc + 1] = __floats2half2_rn(bga.y, bgb.y);
            Bs2[buf][bk2][bnc + 2] = __floats2half2_rn(bga.z, bgb.z);
            Bs2[buf][bk2][bnc + 3] = __floats2half2_rn(bga.w, bgb.w);
        }
    };

    int nk = (K + 15) / 16;
    ldA(0);
    ldB(0);
    for (int t = 0; t < nk; t++) {
        int buf = t & 1;
        stA(buf);
        stB(buf);
        __syncthreads();
        if (t + 1 < nk) { ldA((t + 1) * 16); ldB((t + 1) * 16); }

        unsigned af[MT][4];
        #pragma unroll
        for (int mt = 0; mt < MT; mt++) {
            int row = wm0 + mt * 16 + lr;
            af[mt][0] = *(const unsigned*)&Asm[buf][row][2 * lc];
            af[mt][1] = *(const unsigned*)&Asm[buf][row + 8][2 * lc];
            af[mt][2] = *(const unsigned*)&Asm[buf][row][2 * lc + 8];
            af[mt][3] = *(const unsigned*)&Asm[buf][row + 8][2 * lc + 8];
        }
        unsigned bf[NT][2];
        #pragma unroll
        for (int nt = 0; nt < NT; nt++) {
            int n = wn0 + nt * 8 + lr;
            bf[nt][0] = *(const unsigned*)&Bs2[buf][lc][n];
            bf[nt][1] = *(const unsigned*)&Bs2[buf][lc + 4][n];
        }
        #pragma unroll
        for (int mt = 0; mt < MT; mt++)
            #pragma unroll
            for (int nt = 0; nt < NT; nt++)
                mma_f16(c[mt][nt][0], c[mt][nt][1], c[mt][nt][2], c[mt][nt][3],
                        af[mt][0], af[mt][1], af[mt][2], af[mt][3],
                        bf[nt][0], bf[nt][1]);
    }

    // ---- epilogue ----
    float asv[NT][2], adv[NT][2];
    if (EPI == 2) {
        #pragma unroll
        for (int nt = 0; nt < NT; nt++) {
            int gc = n0 + wn0 + nt * 8 + lc * 2;
            asv[nt][0] = a_src[gc]; asv[nt][1] = a_src[gc + 1];
            adv[nt][0] = a_dst[gc]; adv[nt][1] = a_dst[gc + 1];
        }
    }
    float* Cf = (float*)Cv;
    __half* Ch = (__half*)Cv;
    #pragma unroll
    for (int mt = 0; mt < MT; mt++) {
        int r0 = m0 + wm0 + mt * 16 + lr;
        int r1 = r0 + 8;
        float s0 = 0.f, s1 = 0.f, d0 = 0.f, d1 = 0.f;
        #pragma unroll
        for (int nt = 0; nt < NT; nt++) {
            int gc = n0 + wn0 + nt * 8 + lc * 2;
            float v0 = c[mt][nt][0], v1 = c[mt][nt][1];
            float v2 = c[mt][nt][2], v3 = c[mt][nt][3];
            if (EPI == 1 || EPI == 3) {
                float b0 = bias[gc], b1 = bias[gc + 1];
                v0 = selu_f(v0 + b0); v1 = selu_f(v1 + b1);
                v2 = selu_f(v2 + b0); v3 = selu_f(v3 + b1);
            }
            if (EPI == 2) {
                s0 += v0 * asv[nt][0] + v1 * asv[nt][1];
                s1 += v2 * asv[nt][0] + v3 * asv[nt][1];
                d0 += v0 * adv[nt][0] + v1 * adv[nt][1];
                d1 += v2 * adv[nt][0] + v3 * adv[nt][1];
            }
            if (EPI == 2 || EPI == 3) {
                if (r0 < M) *(__half2*)&Ch[(size_t)r0 * N + gc] = __floats2half2_rn(v0, v1);
                if (r1 < M) *(__half2*)&Ch[(size_t)r1 * N + gc] = __floats2half2_rn(v2, v3);
            } else {
                if (r0 < M) *(float2*)&Cf[(size_t)r0 * N + gc] = make_float2(v0, v1);
                if (r1 < M) *(float2*)&Cf[(size_t)r1 * N + gc] = make_float2(v2, v3);
            }
        }
        if (EPI == 2) {
            s0 += __shfl_xor_sync(0xFFFFFFFFu, s0, 1);
            s0 += __shfl_xor_sync(0xFFFFFFFFu, s0, 2);
            s1 += __shfl_xor_sync(0xFFFFFFFFu, s1, 1);
            s1 += __shfl_xor_sync(0xFFFFFFFFu, s1, 2);
            d0 += __shfl_xor_sync(0xFFFFFFFFu, d0, 1);
            d0 += __shfl_xor_sync(0xFFFFFFFFu, d0, 2);
            d1 += __shfl_xor_sync(0xFFFFFFFFu, d1, 1);
            d1 += __shfl_xor_sync(0xFFFFFFFFu, d1, 2);
            if (lc == 0) {
                int h = (n0 + wn0) >> 6;
                if (r0 < M) { atomicAdd(&AS[r0 * 4 + h], s0); atomicAdd(&AD[r0 * 4 + h], d0); }
                if (r1 < M) { atomicAdd(&AS[r1 * 4 + h], s1); atomicAdd(&AD[r1 * 4 + h], d1); }
            }
        }
    }
}

// =================== GAT gather: warp per dst, fp16 H, fp16 OUT ===================
__device__ __forceinline__ void ons_update(float e, const float* v,
                                           float& m, float& s, float* acc) {
    if (e <= m) {
        float w = expf(e - m);
        s += w;
        #pragma unroll
        for (int q = 0; q < 8; q++) acc[q] += w * v[q];
    } else {
        float sc = expf(m - e);
        s = s * sc + 1.f;
        #pragma unroll
        for (int q = 0; q < 8; q++) acc[q] = acc[q] * sc + v[q];
        m = e;
    }
}
__device__ __forceinline__ void unpack8(uint4 u, float* v) {
    __half2* hh = (__half2*)&u;
    #pragma unroll
    for (int q = 0; q < 4; q++) {
        float2 f = __half22float2(hh[q]);
        v[q * 2] = f.x; v[q * 2 + 1] = f.y;
    }
}

__global__ void gat_gather_kernel(const int* __restrict__ rowptr, const int* __restrict__ adj,
                                  const __half* __restrict__ H, const float* __restrict__ AS,
                                  const float* __restrict__ AD, const float* __restrict__ gb,
                                  __half* __restrict__ OUT, int N) {
    int gw = (blockIdx.x * blockDim.x + threadIdx.x) >> 5;
    int lane = threadIdx.x & 31;
    if (gw >= N) return;
    int dst = gw;
    int h = lane >> 3;
    float adh = AD[dst * 4 + h];
    int beg = rowptr[dst], end = rowptr[dst + 1];
    float acc[8] = {};
    float m = -INFINITY, s = 0.f;
    int i = beg;
    for (; i + 2 <= end; i += 2) {
        int s0 = adj[i], s1 = adj[i + 1];
        float e0 = AS[s0 * 4 + h] + adh;
        float e1 = AS[s1 * 4 + h] + adh;
        uint4 u0 = *((const uint4*)(H + (size_t)s0 * 256) + lane);
        uint4 u1 = *((const uint4*)(H + (size_t)s1 * 256) + lane);
        float v0[8], v1[8];
        unpack8(u0, v0);
        unpack8(u1, v1);
        e0 = e0 > 0.f ? e0 : 0.2f * e0;
        e1 = e1 > 0.f ? e1 : 0.2f * e1;
        ons_update(e0, v0, m, s, acc);
        ons_update(e1, v1, m, s, acc);
    }
    if (i < end) {
        int s0 = adj[i];
        float e0 = AS[s0 * 4 + h] + adh;
        uint4 u0 = *((const uint4*)(H + (size_t)s0 * 256) + lane);
        float v0[8];
        unpack8(u0, v0);
        e0 = e0 > 0.f ? e0 : 0.2f * e0;
        ons_update(e0, v0, m, s, acc);
    }
    float inv = 1.f / (s + 1e-16f);
    const float* gbp = gb + lane * 8;
    uint4 o;
    __half2* oh = (__half2*)&o;
    #pragma unroll
    for (int q = 0; q < 4; q++)
        oh[q] = __floats2half2_rn(acc[2 * q] * inv + gbp[2 * q],
                                  acc[2 * q + 1] * inv + gbp[2 * q + 1]);
    *((uint4*)(OUT + (size_t)dst * 256) + lane) = o;
}

// =================== standalone pool pieces (fp16 input) ===================
__global__ void pool_acc_kernel(const __half* __restrict__ Hx, const int* __restrict__ batch,
                                float* __restrict__ SUMP, int* __restrict__ MAXP,
                                int* __restrict__ CNT, int N) {
    int c = threadIdx.x & 63;
    int r = blockIdx.x * 128 + (threadIdx.x >> 6);
    int rend = blockIdx.x * 128 + 128;
    if (rend > N) rend = N;
    float sum = 0.f, mx = -INFINITY;
    int cnt = 0, curg = -1;
    for (; r < rend; r += 4) {
        int g = batch[r];
        float v = __half2float(Hx[(size_t)r * 64 + c]);
        if (g != curg) {
            if (curg >= 0) {
                atomicAdd(&SUMP[curg * 64 + c], sum);
                atomicMax(&MAXP[curg * 64 + c], fmap(mx));
                if (c == 0) atomicAdd(&CNT[curg], cnt);
            }
            curg = g; sum = 0.f; mx = -INFINITY; cnt = 0;
        }
        sum += v;
        mx = fmaxf(mx, v);
        cnt++;
    }
    if (curg >= 0) {
        atomicAdd(&SUMP[curg * 64 + c], sum);
        atomicMax(&MAXP[curg * 64 + c], fmap(mx));
        if (c == 0) atomicAdd(&CNT[curg], cnt);
    }
}
__global__ void pool_fin_kernel(const float* __restrict__ SUMP, const int* __restrict__ MAXP,
                                const int* __restrict__ CNT, float* __restrict__ X) {
    int i = blockIdx.x * blockDim.x + threadIdx.x;
    if (i >= GMAX * 64) return;
    int g = i >> 6, c = i & 63;
    float cnt = (float)CNT[g];
    if (cnt < 1.f) cnt = 1.f;
    X[g * 128 + c] = SUMP[i] / cnt;
    X[g * 128 + 64 + c] = funmap(MAXP[i]);
}

// =================== final MLP head ===================
__global__ void mlp_kernel(const float* __restrict__ X1, const float* __restrict__ X2,
                           const float* __restrict__ sum_w, const float* __restrict__ sum_b,
                           const float* __restrict__ sh1_w, const float* __restrict__ sh1_b,
                           const float* __restrict__ sh2_w, const float* __restrict__ sh2_b,
                           const float* __restrict__ sh3_w, const float* __restrict__ sh3_b,
                           const float* __restrict__ reg_w, const float* __restrict__ reg_b,
                           float* __restrict__ out) {
    __shared__ float zin[256], z1[128], z2[64], z3[64];
    int g = blockIdx.x, t = threadIdx.x;
    zin[t] = X1[g * 128 + t];
    zin[128 + t] = X2[g * 128 + t];
    __syncthreads();
    {
        float acc = sum_b[t];
        for (int k = 0; k < 256; k++) acc += zin[k] * sum_w[k * 128 + t];
        z1[t] = acc;
    }
    __syncthreads();
    if (t < 64) {
        float acc = sh1_b[t];
        for (int k = 0; k < 128; k++) acc += z1[k] * sh1_w[k * 64 + t];
        z2[t] = selu_f(acc);
    }
    __syncthreads();
    if (t < 64) {
        float acc = sh2_b[t];
        for (int k = 0; k < 64; k++) acc += z2[k] * sh2_w[k * 64 + t];
        z3[t] = selu_f(acc);
    }
    __syncthreads();
    if (t < 64) {
        float acc = sh3_b[t];
        for (int k = 0; k < 64; k++) acc += z3[k] * sh3_w[k * 64 + t];
        z2[t] = selu_f(acc);
    }
    __syncthreads();
    if (t < 32) {
        float acc = reg_b[t];
        for (int k = 0; k < 64; k++) acc += z2[k] * reg_w[k * 32 + t];
        out[g * 32 + t] = acc;
    }
}

// =================== host orchestration ===================
extern "C" void kernel_launch(void* const* d_in, const int* in_sizes, int n_in,
                              void* d_out, int out_size) {
    const float* x       = (const float*)d_in[0];
    const int*   ei      = (const int*)d_in[1];
    const int*   batch   = (const int*)d_in[2];
    const float* gat1_w  = (const float*)d_in[3];
    const float* gat1_as = (const float*)d_in[4];
    const float* gat1_ad = (const float*)d_in[5];
    const float* gat1_b  = (const float*)d_in[6];
    const float* lin1_w  = (const float*)d_in[7];
    const float* lin1_b  = (const float*)d_in[8];
    const float* gat2_w  = (const float*)d_in[9];
    const float* gat2_as = (const float*)d_in[10];
    const float* gat2_ad = (const float*)d_in[11];
    const float* gat2_b  = (const float*)d_in[12];
    const float* lin2_w  = (const float*)d_in[13];
    const float* lin2_b  = (const float*)d_in[14];
    const float* sum_w   = (const float*)d_in[15];
    const float* sum_b   = (const float*)d_in[16];
    const float* sh1_w   = (const float*)d_in[17];
    const float* sh1_b   = (const float*)d_in[18];
    const float* sh2_w   = (const float*)d_in[19];
    const float* sh2_b   = (const float*)d_in[20];
    const float* sh3_w   = (const float*)d_in[21];
    const float* sh3_b   = (const float*)d_in[22];
    const float* reg_w   = (const float*)d_in[23];
    const float* reg_b   = (const float*)d_in[24];

    int N  = in_sizes[2];
    int E  = in_sizes[1] / 2;
    int K1 = in_sizes[0] / N;
    int ET = E + N;

    __half *H, *OUT, *H1, *H2;
    float *AS, *AD, *AS2, *AD2, *SUMP1, *SUMP2, *X1, *X2;
    int *deg, *rowptr, *cur, *adj, *bsum, *MAXP1, *CNT1, *MAXP2, *CNT2;
    cudaGetSymbolAddress((void**)&H, g_H);
    cudaGetSymbolAddress((void**)&OUT, g_OUT);
    cudaGetSymbolAddress((void**)&H1, g_H1);
    cudaGetSymbolAddress((void**)&H2, g_H2);
    cudaGetSymbolAddress((void**)&AS, g_AS);
    cudaGetSymbolAddress((void**)&AD, g_AD);
    cudaGetSymbolAddress((void**)&AS2, g_AS2);
    cudaGetSymbolAddress((void**)&AD2, g_AD2);
    cudaGetSymbolAddress((void**)&deg, g_deg);
    cudaGetSymbolAddress((void**)&rowptr, g_rowptr);
    cudaGetSymbolAddress((void**)&cur, g_cur);
    cudaGetSymbolAddress((void**)&adj, g_adj);
    cudaGetSymbolAddress((void**)&bsum, g_bsum);
    cudaGetSymbolAddress((void**)&SUMP1, g_SUMP1);
    cudaGetSymbolAddress((void**)&MAXP1, g_MAXP1);
    cudaGetSymbolAddress((void**)&CNT1, g_CNT1);
    cudaGetSymbolAddress((void**)&SUMP2, g_SUMP2);
    cudaGetSymbolAddress((void**)&MAXP2, g_MAXP2);
    cudaGetSymbolAddress((void**)&CNT2, g_CNT2);
    cudaGetSymbolAddress((void**)&X1, g_X1);
    cudaGetSymbolAddress((void**)&X2, g_X2);

    int nScanBlocks = (N + 2047) / 2048;
    int nyH = (N + 127) / 128;
    dim3 gH(2, nyH);       // big GEMMs (BN=128, N=256)
    dim3 gH2(3, nyH);      // GEMM2 + fused pool_acc side slice
    dim3 gL(1, nyH);       // lin GEMMs (BN=64)

    // side stream for the CSR branch (created per call; not captured as a node)
    cudaStream_t s1;
    cudaStreamCreateWithFlags(&s1, cudaStreamNonBlocking);
    cudaEvent_t evFork, evCSR;
    cudaEventCreateWithFlags(&evFork, cudaEventDisableTiming);
    cudaEventCreateWithFlags(&evCSR, cudaEventDisableTiming);

    // init on main stream (AS/AD needed by GEMM1; deg/cur by CSR branch)
    init_all_kernel<<<(N * 4 + 255) / 256, 256>>>(deg, cur, AS, AD, AS2, AD2,
                                                  SUMP1, MAXP1, CNT1, SUMP2, MAXP2, CNT2, N);
    cudaEventRecord(evFork, 0);

    // --- branch B (stream s1): CSR build, overlaps GEMM1 ---
    cudaStreamWaitEvent(s1, evFork, 0);
    deg_count_kernel<<<(E + 255) / 256, 256, 0, s1>>>(ei, deg, E);
    scan1_kernel<<<nScanBlocks, 256, 0, s1>>>(deg, rowptr, bsum, N);
    scan23_kernel<<<nScanBlocks, 256, 0, s1>>>(rowptr, bsum, N, ET);
    fill_kernel<<<(ET + 255) / 256, 256, 0, s1>>>(ei, rowptr, cur, adj, E, ET);
    cudaEventRecord(evCSR, s1);

    // --- branch A (main stream): GEMM1 -> H fp16 + attention dots ---
    f16_gemm_kernel<128, 2, 4, 2, 0, 0><<<gH, 256>>>(
        x, gat1_w, nullptr, H, gat1_as, gat1_ad, AS, AD,
        nullptr, nullptr, nullptr, nullptr, nullptr, N, 256, K1, 0);

    // join: gather needs CSR + GEMM1
    cudaStreamWaitEvent(0, evCSR, 0);

    // layer-1 aggregate -> OUT fp16
    gat_gather_kernel<<<(N * 32 + 255) / 256, 256>>>(rowptr, adj, H, AS, AD, gat1_b, OUT, N);
    // lin1 + selu -> H1 fp16
    f16_gemm_kernel<64, 4, 2, 3, 0, 1><<<gL, 256>>>(
        OUT, lin1_w, lin1_b, H1, nullptr, nullptr, nullptr, nullptr,
        nullptr, nullptr, nullptr, nullptr, nullptr, N, 64, 256, 0);

    // GEMM2 (A fp16 H1) -> H fp16 + att dots, fused pool_acc(H1) side slice
    f16_gemm_kernel<128, 2, 4, 2, 2, 1><<<gH2, 256>>>(
        H1, gat2_w, nullptr, H, gat2_as, gat2_ad, AS2, AD2,
        H1, batch, SUMP1, MAXP1, CNT1, N, 256, 64, 0);
    pool_fin_kernel<<<(GMAX * 64 + 255) / 256, 256>>>(SUMP1, MAXP1, CNT1, X1);

    // layer-2 aggregate -> OUT fp16
    gat_gather_kernel<<<(N * 32 + 255) / 256, 256>>>(rowptr, adj, H, AS2, AD2, gat2_b, OUT, N);
    // lin2 + selu -> H2 fp16
    f16_gemm_kernel<64, 4, 2, 3, 0, 1><<<gL, 256>>>(
        OUT, lin2_w, lin2_b, H2, nullptr, nullptr, nullptr, nullptr,
        nullptr, nullptr, nullptr, nullptr, nullptr, N, 64, 256, 0);

    // pool2 -> X2
    pool_acc_kernel<<<nyH, 256>>>(H2, batch, SUMP2, MAXP2, CNT2, N);
    pool_fin_kernel<<<(GMAX * 64 + 255) / 256, 256>>>(SUMP2, MAXP2, CNT2, X2);

    // head MLP
    mlp_kernel<<<GMAX, 128>>>(X1, X2, sum_w, sum_b, sh1_w, sh1_b, sh2_w, sh2_b,
                              sh3_w, sh3_b, reg_w, reg_b, (float*)d_out);
}

// round 11
// speedup vs baseline: 1.3402x; 1.0354x over previous
#include <cuda_runtime.h>
#include <cuda_fp16.h>
#include <math.h>

#define NMAX 100000
#define EMAX 800000
#define ETMAX (NMAX + EMAX)
#define GMAX 128

// ---------------- device scratch ----------------
__device__ __half g_H[NMAX * 256];
__device__ __half g_OUT[NMAX * 256];
__device__ __half g_H1[NMAX * 64];
__device__ __half g_H2[NMAX * 64];
__device__ float g_AS[NMAX * 4];
__device__ float g_AD[NMAX * 4];
__device__ float g_AS2[NMAX * 4];
__device__ float g_AD2[NMAX * 4];
__device__ int   g_deg[NMAX];
__device__ int   g_rowptr[NMAX + 1];
__device__ int   g_cur[NMAX];
__device__ int   g_adj[ETMAX];
__device__ int   g_bsum[256];
__device__ float g_SUMP1[GMAX * 64];
__device__ int   g_MAXP1[GMAX * 64];
__device__ int   g_CNT1[GMAX];
__device__ float g_SUMP2[GMAX * 64];
__device__ int   g_MAXP2[GMAX * 64];
__device__ int   g_CNT2[GMAX];
__device__ float g_X1[GMAX * 128];
__device__ float g_X2[GMAX * 128];

// ---------------- helpers ----------------
__device__ __forceinline__ int fmap(float f) {
    int i = __float_as_int(f);
    return i >= 0 ? i : (i ^ 0x7FFFFFFF);
}
__device__ __forceinline__ float funmap(int i) {
    return __int_as_float(i >= 0 ? i : (i ^ 0x7FFFFFFF));
}
__device__ __forceinline__ float selu_f(float x) {
    const float a = 1.6732632423543772f, s = 1.0507009873554805f;
    return x > 0.f ? s * x : s * a * (expf(x) - 1.f);
}
__device__ __forceinline__ void mma_f16(float& c0, float& c1, float& c2, float& c3,
                                        unsigned a0, unsigned a1, unsigned a2, unsigned a3,
                                        unsigned b0, unsigned b1) {
    asm volatile(
        "mma.sync.aligned.m16n8k16.row.col.f32.f16.f16.f32 "
        "{%0,%1,%2,%3}, {%4,%5,%6,%7}, {%8,%9}, {%0,%1,%2,%3};"
        : "+f"(c0), "+f"(c1), "+f"(c2), "+f"(c3)
        : "r"(a0), "r"(a1), "r"(a2), "r"(a3), "r"(b0), "r"(b1));
}
__device__ __forceinline__ void ldmatrix_x4(unsigned& r0, unsigned& r1,
                                            unsigned& r2, unsigned& r3,
                                            const void* smem_ptr) {
    unsigned addr = (unsigned)__cvta_generic_to_shared(smem_ptr);
    asm volatile("ldmatrix.sync.aligned.m8n8.x4.shared.b16 {%0,%1,%2,%3}, [%4];"
                 : "=r"(r0), "=r"(r1), "=r"(r2), "=r"(r3) : "r"(addr));
}

// =================== one-shot init ===================
__global__ void init_all_kernel(int* __restrict__ deg, int* __restrict__ cur,
                                float* __restrict__ AS, float* __restrict__ AD,
                                float* __restrict__ AS2, float* __restrict__ AD2,
                                float* __restrict__ SUMP1, int* __restrict__ MAXP1,
                                int* __restrict__ CNT1,
                                float* __restrict__ SUMP2, int* __restrict__ MAXP2,
                                int* __restrict__ CNT2, int N) {
    int i = blockIdx.x * blockDim.x + threadIdx.x;
    if (i < N) { deg[i] = 1; cur[i] = 0; }
    if (i < N * 4) { AS[i] = 0.f; AD[i] = 0.f; AS2[i] = 0.f; AD2[i] = 0.f; }
    if (i < GMAX * 64) {
        SUMP1[i] = 0.f; MAXP1[i] = fmap(-INFINITY);
        SUMP2[i] = 0.f; MAXP2[i] = fmap(-INFINITY);
    }
    if (i < GMAX) { CNT1[i] = 0; CNT2[i] = 0; }
}

// =================== CSR build ===================
__global__ void deg_count_kernel(const int* __restrict__ ei, int* __restrict__ deg, int E) {
    int e = blockIdx.x * blockDim.x + threadIdx.x;
    if (e < E) atomicAdd(&deg[ei[E + e]], 1);
}
__global__ void scan1_kernel(const int* __restrict__ deg, int* __restrict__ rowptr,
                             int* __restrict__ bsum, int N) {
    __shared__ int sh[256];
    int tid = threadIdx.x;
    int base = blockIdx.x * 2048 + tid * 8;
    int v[8], pre[8];
    int sum = 0;
    #pragma unroll
    for (int j = 0; j < 8; j++) {
        v[j] = (base + j < N) ? deg[base + j] : 0;
        pre[j] = sum;
        sum += v[j];
    }
    sh[tid] = sum;
    __syncthreads();
    for (int off = 1; off < 256; off <<= 1) {
        int t = (tid >= off) ? sh[tid - off] : 0;
        __syncthreads();
        sh[tid] += t;
        __syncthreads();
    }
    int texcl = sh[tid] - sum;
    #pragma unroll
    for (int j = 0; j < 8; j++)
        if (base + j < N) rowptr[base + j] = texcl + pre[j];
    if (tid == 255) bsum[blockIdx.x] = sh[255];
}
__global__ void scan23_kernel(int* __restrict__ rowptr, const int* __restrict__ bsum,
                              int N, int ET) {
    __shared__ int s_add;
    int tid = threadIdx.x;
    if (tid < 32) {
        int s = 0;
        for (int j = tid; j < blockIdx.x; j += 32) s += bsum[j];
        #pragma unroll
        for (int off = 16; off; off >>= 1) s += __shfl_down_sync(0xFFFFFFFFu, s, off);
        if (tid == 0) s_add = s;
    }
    __syncthreads();
    int add = s_add;
    int base = blockIdx.x * 2048 + tid * 8;
    #pragma unroll
    for (int j = 0; j < 8; j++)
        if (base + j < N) rowptr[base + j] += add;
    if (blockIdx.x == 0 && tid == 0) rowptr[N] = ET;
}
__global__ void fill_kernel(const int* __restrict__ ei, const int* __restrict__ rowptr,
                            int* __restrict__ cur, int* __restrict__ adj, int E, int ET) {
    int idx = blockIdx.x * blockDim.x + threadIdx.x;
    if (idx >= ET) return;
    int src, dst;
    if (idx < E) { src = ei[idx]; dst = ei[E + idx]; }
    else         { src = dst = idx - E; }
    adj[rowptr[dst] + atomicAdd(&cur[dst], 1)] = src;
}

// =================== fp16 m16n8k16 GEMM (ldmatrix A-frags) ===================
// AHALF: 0 = A fp32, 1 = A fp16
// EPI: 0 = plain fp32, 1 = bias+selu fp32, 2 = fp16 + fused att dots, 3 = bias+selu fp16
// SIDE: 0 = none; 2 = last-grid.x blocks do pool_acc (Hx fp16)
template <int BN, int WARPS_M, int WARPS_N, int EPI, int SIDE, int AHALF>
__global__ void __launch_bounds__(256)
f16_gemm_kernel(const void* __restrict__ Av, const float* __restrict__ B,
                const float* __restrict__ bias, void* __restrict__ Cv,
                const float* __restrict__ a_src, const float* __restrict__ a_dst,
                float* __restrict__ AS, float* __restrict__ AD,
                const void* sp0, const void* sp1, void* sp2, void* sp3, void* sp4,
                int M, int N, int K, int sE) {
    if (SIDE == 2 && blockIdx.x == gridDim.x - 1) {
        const __half* Hx = (const __half*)sp0;
        const int* batch = (const int*)sp1;
        float* SUMP = (float*)sp2;
        int* MAXP = (int*)sp3;
        int* CNT = (int*)sp4;
        int c = threadIdx.x & 63;
        int r = blockIdx.y * 128 + (threadIdx.x >> 6);
        int rend = blockIdx.y * 128 + 128;
        if (rend > M) rend = M;
        float sum = 0.f, mx = -INFINITY;
        int cnt = 0, curg = -1;
        for (; r < rend; r += 4) {
            int g = batch[r];
            float v = __half2float(Hx[(size_t)r * 64 + c]);
            if (g != curg) {
                if (curg >= 0) {
                    atomicAdd(&SUMP[curg * 64 + c], sum);
                    atomicMax(&MAXP[curg * 64 + c], fmap(mx));
                    if (c == 0) atomicAdd(&CNT[curg], cnt);
                }
                curg = g; sum = 0.f; mx = -INFINITY; cnt = 0;
            }
            sum += v;
            mx = fmaxf(mx, v);
            cnt++;
        }
        if (curg >= 0) {
            atomicAdd(&SUMP[curg * 64 + c], sum);
            atomicMax(&MAXP[curg * 64 + c], fmap(mx));
            if (c == 0) atomicAdd(&CNT[curg], cnt);
        }
        return;
    }

    const int WM = 128 / WARPS_M, WN = BN / WARPS_N;
    const int MT = WM / 16, NT = WN / 8;
    const int ASTR = 24;
    __shared__ __half  Asm[2][128][ASTR];
    __shared__ __half2 Bs2[2][8][BN + 8];

    int tid = threadIdx.x;
    int warp = tid >> 5, lane = tid & 31;
    int lr = lane >> 2, lc = lane & 3;
    int warp_m = warp / WARPS_N, warp_n = warp % WARPS_N;
    int wm0 = warp_m * WM, wn0 = warp_n * WN;
    int m0 = blockIdx.y * 128, n0 = blockIdx.x * BN;

    // ldmatrix address: lane l -> row (l&15), k-col (l<16 ? 0 : 8)
    int lm_row = lane & 15;
    int lm_col = (lane < 16) ? 0 : 8;

    float c[MT][NT][4];
    #pragma unroll
    for (int i = 0; i < MT; i++)
        #pragma unroll
        for (int j = 0; j < NT; j++)
            #pragma unroll
            for (int q = 0; q < 4; q++) c[i][j][q] = 0.f;

    const float* Af = (const float*)Av;
    const __half* Ah = (const __half*)Av;
    float4 areg[2];
    uint4 ahreg;
    float4 bga, bgb;
    const int BTASK = 8 * (BN / 4);
    int bk2 = tid / (BN / 4);
    int bnc = (tid % (BN / 4)) * 4;

    auto ldA = [&](int k0) {
        if (AHALF) {
            int gm = m0 + (tid >> 1), gk = k0 + (tid & 1) * 8;
            uint4 z = {0u, 0u, 0u, 0u};
            ahreg = (gm < M && gk < K) ? *(const uint4*)&Ah[(size_t)gm * K + gk] : z;
        } else {
            #pragma unroll
            for (int q = 0; q < 2; q++) {
                int f = tid + q * 256;
                int r = f >> 2, cc = (f & 3) * 4;
                int gm = m0 + r, gk = k0 + cc;
                float4 v = {0.f, 0.f, 0.f, 0.f};
                if (gm < M && gk < K) v = *(const float4*)&Af[(size_t)gm * K + gk];
                areg[q] = v;
            }
        }
    };
    auto stA = [&](int buf) {
        if (AHALF) {
            int r = tid >> 1, cc = (tid & 1) * 8;
            *(__half2*)&Asm[buf][r][cc + 0] = *(const __half2*)&ahreg.x;
            *(__half2*)&Asm[buf][r][cc + 2] = *(const __half2*)&ahreg.y;
            *(__half2*)&Asm[buf][r][cc + 4] = *(const __half2*)&ahreg.z;
            *(__half2*)&Asm[buf][r][cc + 6] = *(const __half2*)&ahreg.w;
        } else {
            #pragma unroll
            for (int q = 0; q < 2; q++) {
                int f = tid + q * 256;
                int r = f >> 2, cc = (f & 3) * 4;
                *(__half2*)&Asm[buf][r][cc]     = __floats2half2_rn(areg[q].x, areg[q].y);
                *(__half2*)&Asm[buf][r][cc + 2] = __floats2half2_rn(areg[q].z, areg[q].w);
            }
        }
    };
    auto ldB = [&](int k0) {
        if (tid < BTASK) {
            int gk0 = k0 + 2 * bk2, gk1 = gk0 + 1;
            float4 z = {0.f, 0.f, 0.f, 0.f};
            bga = (gk0 < K) ? *(const float4*)&B[(size_t)gk0 * N + n0 + bnc] : z;
            bgb = (gk1 < K) ? *(const float4*)&B[(size_t)gk1 * N + n0 + bnc] : z;
        }
    };
    auto stB = [&](int buf) {
        if (tid < BTASK) {
            Bs2[buf][bk2][bnc + 0] = __floats2half2_rn(bga.x, bgb.x);
            Bs2[buf][bk2][bnc + 1] = __floats2half2_rn(bga.y, bgb.y);
            Bs2[buf][bk2][bnc + 2] = __floats2half2_rn(bga.z, bgb.z);
            Bs2[buf][bk2][bnc + 3] = __floats2half2_rn(bga.w, bgb.w);
        }
    };

    int nk = (K + 15) / 16;
    ldA(0);
    ldB(0);
    for (int t = 0; t < nk; t++) {
        int buf = t & 1;
        stA(buf);
        stB(buf);
        __syncthreads();
        if (t + 1 < nk) { ldA((t + 1) * 16); ldB((t + 1) * 16); }

        unsigned af[MT][4];
        #pragma unroll
        for (int mt = 0; mt < MT; mt++)
            ldmatrix_x4(af[mt][0], af[mt][1], af[mt][2], af[mt][3],
                        &Asm[buf][wm0 + mt * 16 + lm_row][lm_col]);
        unsigned bf[NT][2];
        #pragma unroll
        for (int nt = 0; nt < NT; nt++) {
            int n = wn0 + nt * 8 + lr;
            bf[nt][0] = *(const unsigned*)&Bs2[buf][lc][n];
            bf[nt][1] = *(const unsigned*)&Bs2[buf][lc + 4][n];
        }
        #pragma unroll
        for (int mt = 0; mt < MT; mt++)
            #pragma unroll
            for (int nt = 0; nt < NT; nt++)
                mma_f16(c[mt][nt][0], c[mt][nt][1], c[mt][nt][2], c[mt][nt][3],
                        af[mt][0], af[mt][1], af[mt][2], af[mt][3],
                        bf[nt][0], bf[nt][1]);
    }

    // ---- epilogue ----
    float asv[NT][2], adv[NT][2];
    if (EPI == 2) {
        #pragma unroll
        for (int nt = 0; nt < NT; nt++) {
            int gc = n0 + wn0 + nt * 8 + lc * 2;
            asv[nt][0] = a_src[gc]; asv[nt][1] = a_src[gc + 1];
            adv[nt][0] = a_dst[gc]; adv[nt][1] = a_dst[gc + 1];
        }
    }
    float* Cf = (float*)Cv;
    __half* Ch = (__half*)Cv;
    #pragma unroll
    for (int mt = 0; mt < MT; mt++) {
        int r0 = m0 + wm0 + mt * 16 + lr;
        int r1 = r0 + 8;
        float s0 = 0.f, s1 = 0.f, d0 = 0.f, d1 = 0.f;
        #pragma unroll
        for (int nt = 0; nt < NT; nt++) {
            int gc = n0 + wn0 + nt * 8 + lc * 2;
            float v0 = c[mt][nt][0], v1 = c[mt][nt][1];
            float v2 = c[mt][nt][2], v3 = c[mt][nt][3];
            if (EPI == 1 || EPI == 3) {
                float b0 = bias[gc], b1 = bias[gc + 1];
                v0 = selu_f(v0 + b0); v1 = selu_f(v1 + b1);
                v2 = selu_f(v2 + b0); v3 = selu_f(v3 + b1);
            }
            if (EPI == 2) {
                s0 += v0 * asv[nt][0] + v1 * asv[nt][1];
                s1 += v2 * asv[nt][0] + v3 * asv[nt][1];
                d0 += v0 * adv[nt][0] + v1 * adv[nt][1];
                d1 += v2 * adv[nt][0] + v3 * adv[nt][1];
            }
            if (EPI == 2 || EPI == 3) {
                if (r0 < M) *(__half2*)&Ch[(size_t)r0 * N + gc] = __floats2half2_rn(v0, v1);
                if (r1 < M) *(__half2*)&Ch[(size_t)r1 * N + gc] = __floats2half2_rn(v2, v3);
            } else {
                if (r0 < M) *(float2*)&Cf[(size_t)r0 * N + gc] = make_float2(v0, v1);
                if (r1 < M) *(float2*)&Cf[(size_t)r1 * N + gc] = make_float2(v2, v3);
            }
        }
        if (EPI == 2) {
            s0 += __shfl_xor_sync(0xFFFFFFFFu, s0, 1);
            s0 += __shfl_xor_sync(0xFFFFFFFFu, s0, 2);
            s1 += __shfl_xor_sync(0xFFFFFFFFu, s1, 1);
            s1 += __shfl_xor_sync(0xFFFFFFFFu, s1, 2);
            d0 += __shfl_xor_sync(0xFFFFFFFFu, d0, 1);
            d0 += __shfl_xor_sync(0xFFFFFFFFu, d0, 2);
            d1 += __shfl_xor_sync(0xFFFFFFFFu, d1, 1);
            d1 += __shfl_xor_sync(0xFFFFFFFFu, d1, 2);
            if (lc == 0) {
                int h = (n0 + wn0) >> 6;
                if (r0 < M) { atomicAdd(&AS[r0 * 4 + h], s0); atomicAdd(&AD[r0 * 4 + h], d0); }
                if (r1 < M) { atomicAdd(&AS[r1 * 4 + h], s1); atomicAdd(&AD[r1 * 4 + h], d1); }
            }
        }
    }
}

// =================== GAT gather: warp per dst, 4-edge unroll ===================
__device__ __forceinline__ void ons_update(float e, const float* v,
                                           float& m, float& s, float* acc) {
    if (e <= m) {
        float w = expf(e - m);
        s += w;
        #pragma unroll
        for (int q = 0; q < 8; q++) acc[q] += w * v[q];
    } else {
        float sc = expf(m - e);
        s = s * sc + 1.f;
        #pragma unroll
        for (int q = 0; q < 8; q++) acc[q] = acc[q] * sc + v[q];
        m = e;
    }
}
__device__ __forceinline__ void unpack8(uint4 u, float* v) {
    __half2* hh = (__half2*)&u;
    #pragma unroll
    for (int q = 0; q < 4; q++) {
        float2 f = __half22float2(hh[q]);
        v[q * 2] = f.x; v[q * 2 + 1] = f.y;
    }
}

__global__ void gat_gather_kernel(const int* __restrict__ rowptr, const int* __restrict__ adj,
                                  const __half* __restrict__ H, const float* __restrict__ AS,
                                  const float* __restrict__ AD, const float* __restrict__ gb,
                                  __half* __restrict__ OUT, int N) {
    int gw = (blockIdx.x * blockDim.x + threadIdx.x) >> 5;
    int lane = threadIdx.x & 31;
    if (gw >= N) return;
    int dst = gw;
    int h = lane >> 3;
    float adh = AD[dst * 4 + h];
    int beg = rowptr[dst], end = rowptr[dst + 1];
    float acc[8] = {};
    float m = -INFINITY, s = 0.f;
    int i = beg;
    for (; i + 4 <= end; i += 4) {
        int s0 = adj[i], s1 = adj[i + 1], s2 = adj[i + 2], s3 = adj[i + 3];
        float e0 = AS[s0 * 4 + h], e1 = AS[s1 * 4 + h];
        float e2 = AS[s2 * 4 + h], e3 = AS[s3 * 4 + h];
        uint4 u0 = *((const uint4*)(H + (size_t)s0 * 256) + lane);
        uint4 u1 = *((const uint4*)(H + (size_t)s1 * 256) + lane);
        uint4 u2 = *((const uint4*)(H + (size_t)s2 * 256) + lane);
        uint4 u3 = *((const uint4*)(H + (size_t)s3 * 256) + lane);
        e0 += adh; e1 += adh; e2 += adh; e3 += adh;
        e0 = e0 > 0.f ? e0 : 0.2f * e0;
        e1 = e1 > 0.f ? e1 : 0.2f * e1;
        e2 = e2 > 0.f ? e2 : 0.2f * e2;
        e3 = e3 > 0.f ? e3 : 0.2f * e3;
        float v[8];
        unpack8(u0, v); ons_update(e0, v, m, s, acc);
        unpack8(u1, v); ons_update(e1, v, m, s, acc);
        unpack8(u2, v); ons_update(e2, v, m, s, acc);
        unpack8(u3, v); ons_update(e3, v, m, s, acc);
    }
    for (; i < end; i++) {
        int s0 = adj[i];
        float e0 = AS[s0 * 4 + h] + adh;
        uint4 u0 = *((const uint4*)(H + (size_t)s0 * 256) + lane);
        float v[8];
        unpack8(u0, v);
        e0 = e0 > 0.f ? e0 : 0.2f * e0;
        ons_update(e0, v, m, s, acc);
    }
    float inv = 1.f / (s + 1e-16f);
    const float* gbp = gb + lane * 8;
    uint4 o;
    __half2* oh = (__half2*)&o;
    #pragma unroll
    for (int q = 0; q < 4; q++)
        oh[q] = __floats2half2_rn(acc[2 * q] * inv + gbp[2 * q],
                                  acc[2 * q + 1] * inv + gbp[2 * q + 1]);
    *((uint4*)(OUT + (size_t)dst * 256) + lane) = o;
}

// =================== standalone pool pieces (fp16 input) ===================
__global__ void pool_acc_kernel(const __half* __restrict__ Hx, const int* __restrict__ batch,
                                float* __restrict__ SUMP, int* __restrict__ MAXP,
                                int* __restrict__ CNT, int N) {
    int c = threadIdx.x & 63;
    int r = blockIdx.x * 128 + (threadIdx.x >> 6);
    int rend = blockIdx.x * 128 + 128;
    if (rend > N) rend = N;
    float sum = 0.f, mx = -INFINITY;
    int cnt = 0, curg = -1;
    for (; r < rend; r += 4) {
        int g = batch[r];
        float v = __half2float(Hx[(size_t)r * 64 + c]);
        if (g != curg) {
            if (curg >= 0) {
                atomicAdd(&SUMP[curg * 64 + c], sum);
                atomicMax(&MAXP[curg * 64 + c], fmap(mx));
                if (c == 0) atomicAdd(&CNT[curg], cnt);
            }
            curg = g; sum = 0.f; mx = -INFINITY; cnt = 0;
        }
        sum += v;
        mx = fmaxf(mx, v);
        cnt++;
    }
    if (curg >= 0) {
        atomicAdd(&SUMP[curg * 64 + c], sum);
        atomicMax(&MAXP[curg * 64 + c], fmap(mx));
        if (c == 0) atomicAdd(&CNT[curg], cnt);
    }
}
__global__ void pool_fin_kernel(const float* __restrict__ SUMP, const int* __restrict__ MAXP,
                                const int* __restrict__ CNT, float* __restrict__ X) {
    int i = blockIdx.x * blockDim.x + threadIdx.x;
    if (i >= GMAX * 64) return;
    int g = i >> 6, c = i & 63;
    float cnt = (float)CNT[g];
    if (cnt < 1.f) cnt = 1.f;
    X[g * 128 + c] = SUMP[i] / cnt;
    X[g * 128 + 64 + c] = funmap(MAXP[i]);
}

// =================== final MLP head ===================
__global__ void mlp_kernel(const float* __restrict__ X1, const float* __restrict__ X2,
                           const float* __restrict__ sum_w, const float* __restrict__ sum_b,
                           const float* __restrict__ sh1_w, const float* __restrict__ sh1_b,
                           const float* __restrict__ sh2_w, const float* __restrict__ sh2_b,
                           const float* __restrict__ sh3_w, const float* __restrict__ sh3_b,
                           const float* __restrict__ reg_w, const float* __restrict__ reg_b,
                           float* __restrict__ out) {
    __shared__ float zin[256], z1[128], z2[64], z3[64];
    int g = blockIdx.x, t = threadIdx.x;
    zin[t] = X1[g * 128 + t];
    zin[128 + t] = X2[g * 128 + t];
    __syncthreads();
    {
        float acc = sum_b[t];
        for (int k = 0; k < 256; k++) acc += zin[k] * sum_w[k * 128 + t];
        z1[t] = acc;
    }
    __syncthreads();
    if (t < 64) {
        float acc = sh1_b[t];
        for (int k = 0; k < 128; k++) acc += z1[k] * sh1_w[k * 64 + t];
        z2[t] = selu_f(acc);
    }
    __syncthreads();
    if (t < 64) {
        float acc = sh2_b[t];
        for (int k = 0; k < 64; k++) acc += z2[k] * sh2_w[k * 64 + t];
        z3[t] = selu_f(acc);
    }
    __syncthreads();
    if (t < 64) {
        float acc = sh3_b[t];
        for (int k = 0; k < 64; k++) acc += z3[k] * sh3_w[k * 64 + t];
        z2[t] = selu_f(acc);
    }
    __syncthreads();
    if (t < 32) {
        float acc = reg_b[t];
        for (int k = 0; k < 64; k++) acc += z2[k] * reg_w[k * 32 + t];
        out[g * 32 + t] = acc;
    }
}

// =================== host orchestration ===================
extern "C" void kernel_launch(void* const* d_in, const int* in_sizes, int n_in,
                              void* d_out, int out_size) {
    const float* x       = (const float*)d_in[0];
    const int*   ei      = (const int*)d_in[1];
    const int*   batch   = (const int*)d_in[2];
    const float* gat1_w  = (const float*)d_in[3];
    const float* gat1_as = (const float*)d_in[4];
    const float* gat1_ad = (const float*)d_in[5];
    const float* gat1_b  = (const float*)d_in[6];
    const float* lin1_w  = (const float*)d_in[7];
    const float* lin1_b  = (const float*)d_in[8];
    const float* gat2_w  = (const float*)d_in[9];
    const float* gat2_as = (const float*)d_in[10];
    const float* gat2_ad = (const float*)d_in[11];
    const float* gat2_b  = (const float*)d_in[12];
    const float* lin2_w  = (const float*)d_in[13];
    const float* lin2_b  = (const float*)d_in[14];
    const float* sum_w   = (const float*)d_in[15];
    const float* sum_b   = (const float*)d_in[16];
    const float* sh1_w   = (const float*)d_in[17];
    const float* sh1_b   = (const float*)d_in[18];
    const float* sh2_w   = (const float*)d_in[19];
    const float* sh2_b   = (const float*)d_in[20];
    const float* sh3_w   = (const float*)d_in[21];
    const float* sh3_b   = (const float*)d_in[22];
    const float* reg_w   = (const float*)d_in[23];
    const float* reg_b   = (const float*)d_in[24];

    int N  = in_sizes[2];
    int E  = in_sizes[1] / 2;
    int K1 = in_sizes[0] / N;
    int ET = E + N;

    __half *H, *OUT, *H1, *H2;
    float *AS, *AD, *AS2, *AD2, *SUMP1, *SUMP2, *X1, *X2;
    int *deg, *rowptr, *cur, *adj, *bsum, *MAXP1, *CNT1, *MAXP2, *CNT2;
    cudaGetSymbolAddress((void**)&H, g_H);
    cudaGetSymbolAddress((void**)&OUT, g_OUT);
    cudaGetSymbolAddress((void**)&H1, g_H1);
    cudaGetSymbolAddress((void**)&H2, g_H2);
    cudaGetSymbolAddress((void**)&AS, g_AS);
    cudaGetSymbolAddress((void**)&AD, g_AD);
    cudaGetSymbolAddress((void**)&AS2, g_AS2);
    cudaGetSymbolAddress((void**)&AD2, g_AD2);
    cudaGetSymbolAddress((void**)&deg, g_deg);
    cudaGetSymbolAddress((void**)&rowptr, g_rowptr);
    cudaGetSymbolAddress((void**)&cur, g_cur);
    cudaGetSymbolAddress((void**)&adj, g_adj);
    cudaGetSymbolAddress((void**)&bsum, g_bsum);
    cudaGetSymbolAddress((void**)&SUMP1, g_SUMP1);
    cudaGetSymbolAddress((void**)&MAXP1, g_MAXP1);
    cudaGetSymbolAddress((void**)&CNT1, g_CNT1);
    cudaGetSymbolAddress((void**)&SUMP2, g_SUMP2);
    cudaGetSymbolAddress((void**)&MAXP2, g_MAXP2);
    cudaGetSymbolAddress((void**)&CNT2, g_CNT2);
    cudaGetSymbolAddress((void**)&X1, g_X1);
    cudaGetSymbolAddress((void**)&X2, g_X2);

    int nScanBlocks = (N + 2047) / 2048;
    int nyH = (N + 127) / 128;
    dim3 gH(2, nyH);
    dim3 gH2(3, nyH);
    dim3 gL(1, nyH);

    cudaStream_t s1;
    cudaStreamCreateWithFlags(&s1, cudaStreamNonBlocking);
    cudaEvent_t evFork, evCSR;
    cudaEventCreateWithFlags(&evFork, cudaEventDisableTiming);
    cudaEventCreateWithFlags(&evCSR, cudaEventDisableTiming);

    init_all_kernel<<<(N * 4 + 255) / 256, 256>>>(deg, cur, AS, AD, AS2, AD2,
                                                  SUMP1, MAXP1, CNT1, SUMP2, MAXP2, CNT2, N);
    cudaEventRecord(evFork, 0);

    // --- CSR branch (s1), overlaps GEMM1 ---
    cudaStreamWaitEvent(s1, evFork, 0);
    deg_count_kernel<<<(E + 255) / 256, 256, 0, s1>>>(ei, deg, E);
    scan1_kernel<<<nScanBlocks, 256, 0, s1>>>(deg, rowptr, bsum, N);
    scan23_kernel<<<nScanBlocks, 256, 0, s1>>>(rowptr, bsum, N, ET);
    fill_kernel<<<(ET + 255) / 256, 256, 0, s1>>>(ei, rowptr, cur, adj, E, ET);
    cudaEventRecord(evCSR, s1);

    // --- GEMM1 -> H fp16 + attention dots ---
    f16_gemm_kernel<128, 2, 4, 2, 0, 0><<<gH, 256>>>(
        x, gat1_w, nullptr, H, gat1_as, gat1_ad, AS, AD,
        nullptr, nullptr, nullptr, nullptr, nullptr, N, 256, K1, 0);

    cudaStreamWaitEvent(0, evCSR, 0);

    gat_gather_kernel<<<(N * 32 + 255) / 256, 256>>>(rowptr, adj, H, AS, AD, gat1_b, OUT, N);
    f16_gemm_kernel<64, 4, 2, 3, 0, 1><<<gL, 256>>>(
        OUT, lin1_w, lin1_b, H1, nullptr, nullptr, nullptr, nullptr,
        nullptr, nullptr, nullptr, nullptr, nullptr, N, 64, 256, 0);

    f16_gemm_kernel<128, 2, 4, 2, 2, 1><<<gH2, 256>>>(
        H1, gat2_w, nullptr, H, gat2_as, gat2_ad, AS2, AD2,
        H1, batch, SUMP1, MAXP1, CNT1, N, 256, 64, 0);
    pool_fin_kernel<<<(GMAX * 64 + 255) / 256, 256>>>(SUMP1, MAXP1, CNT1, X1);

    gat_gather_kernel<<<(N * 32 + 255) / 256, 256>>>(rowptr, adj, H, AS2, AD2, gat2_b, OUT, N);
    f16_gemm_kernel<64, 4, 2, 3, 0, 1><<<gL, 256>>>(
        OUT, lin2_w, lin2_b, H2, nullptr, nullptr, nullptr, nullptr,
        nullptr, nullptr, nullptr, nullptr, nullptr, N, 64, 256, 0);

    pool_acc_kernel<<<nyH, 256>>>(H2, batch, SUMP2, MAXP2, CNT2, N);
    pool_fin_kernel<<<(GMAX * 64 + 255) / 256, 256>>>(SUMP2, MAXP2, CNT2, X2);

    mlp_kernel<<<GMAX, 128>>>(X1, X2, sum_w, sum_b, sh1_w, sh1_b, sh2_w, sh2_b,
                              sh3_w, sh3_b, reg_w, reg_b, (float*)d_out);
}